// round 1
// baseline (speedup 1.0000x reference)
#include <cuda_runtime.h>
#include <math.h>
#include <stdint.h>

// ---------------- problem constants ----------------
#define BATCH 8
#define SEQ   1024
#define DIM   768
#define HEADS 8
#define HDIM  96          // DIM / HEADS
#define KNEIGH 5
#define NLAYERS 3
#define ROWS (BATCH*SEQ)  // 8192
#define LN_EPS 1e-5f

// ---------------- device scratch (static, allocation-free) ----------------
__device__ float g_h[ROWS * DIM];
__device__ float g_xw[ROWS * DIM];
__device__ float g_qkv[ROWS * 3 * DIM];
__device__ float g_scores[(long long)BATCH * HEADS * SEQ * SEQ]; // 256 MB
__device__ float g_ocat[ROWS * DIM];
__device__ float g_cat[ROWS * 2 * DIM];   // [gcn | attn] stride 1536
__device__ float g_gate[ROWS * DIM];
__device__ unsigned char g_adj[(long long)BATCH * SEQ * SEQ];    // 8 MB
__device__ float g_dinv[ROWS];
__device__ int   g_topk[ROWS * KNEIGH];

// ---------------- simple elementwise ----------------
__global__ void copy_kernel(const float* __restrict__ src, float* __restrict__ dst, long n) {
    long i = (long)blockIdx.x * blockDim.x + threadIdx.x;
    long stride = (long)gridDim.x * blockDim.x;
    for (; i < n; i += stride) dst[i] = src[i];
}

__global__ void zero_bytes_kernel(unsigned char* p, long n) {
    long i = (long)blockIdx.x * blockDim.x + threadIdx.x;
    long stride = (long)gridDim.x * blockDim.x;
    int* pi = (int*)p;
    long nw = n >> 2;
    for (; i < nw; i += stride) pi[i] = 0;
}

// ---------------- sim + top-k (k=5) ----------------
// One block per (b,s) row. Warp-per-key dot products, then 5 sequential argmax
// selections with jax tie-break (equal value -> lower index).
__global__ void topk_kernel(const float* __restrict__ x, int* __restrict__ idx_out) {
    int b = blockIdx.x >> 10;
    int s = blockIdx.x & 1023;
    __shared__ float q[DIM];
    __shared__ float sim[SEQ];
    __shared__ float bv[256];
    __shared__ int   bi[256];
    int tid = threadIdx.x;
    const float* xb = x + (long)b * SEQ * DIM;
    for (int i = tid; i < DIM; i += 256) q[i] = xb[(long)s * DIM + i];
    __syncthreads();
    int warp = tid >> 5, lane = tid & 31;
    for (int t = warp; t < SEQ; t += 8) {
        const float* xk = xb + (long)t * DIM;
        float acc = 0.f;
        #pragma unroll 4
        for (int i = lane; i < DIM; i += 32) acc += q[i] * xk[i];
        #pragma unroll
        for (int o = 16; o > 0; o >>= 1) acc += __shfl_down_sync(0xffffffffu, acc, o);
        if (lane == 0) sim[t] = acc;
    }
    __syncthreads();
    for (int sel = 0; sel < KNEIGH; sel++) {
        float v = -INFINITY; int mi = 0x7fffffff;
        for (int t = tid; t < SEQ; t += 256) {
            float sv = sim[t];
            if (sv > v || (sv == v && t < mi)) { v = sv; mi = t; }
        }
        bv[tid] = v; bi[tid] = mi;
        __syncthreads();
        for (int o = 128; o > 0; o >>= 1) {
            if (tid < o) {
                if (bv[tid + o] > bv[tid] || (bv[tid + o] == bv[tid] && bi[tid + o] < bi[tid])) {
                    bv[tid] = bv[tid + o]; bi[tid] = bi[tid + o];
                }
            }
            __syncthreads();
        }
        if (tid == 0) { idx_out[(long)blockIdx.x * KNEIGH + sel] = bi[0]; sim[bi[0]] = -INFINITY; }
        __syncthreads();
    }
}

// ---------------- adjacency scatter + degree ----------------
__global__ void scatter_adj_kernel(const int* __restrict__ idx, unsigned char* __restrict__ A) {
    int r = blockIdx.x * blockDim.x + threadIdx.x;
    if (r >= ROWS) return;
    int b = r >> 10, s = r & 1023;
    unsigned char* Ab = A + (long long)b * SEQ * SEQ;
    Ab[(long)s * SEQ + s] = 1;
    #pragma unroll
    for (int j = 0; j < KNEIGH; j++) {
        int t = idx[(long)r * KNEIGH + j];
        Ab[(long)s * SEQ + t] = 1;
        Ab[(long)t * SEQ + s] = 1;
    }
}

__global__ void degree_kernel(const unsigned char* __restrict__ A, float* __restrict__ dinv) {
    int r = blockIdx.x * blockDim.x + threadIdx.x;
    if (r >= ROWS) return;
    const uint32_t* row = (const uint32_t*)(A + (long long)r * SEQ);
    int d = 0;
    for (int i = 0; i < SEQ / 4; i++) {
        uint32_t w = row[i];
        d += (w & 0xff) + ((w >> 8) & 0xff) + ((w >> 16) & 0xff) + ((w >> 24) & 0xff);
    }
    dinv[r] = rsqrtf((float)d);
}

// ---------------- sparse GCN aggregate: cat[:,0:768] = dinv_s * sum dinv_t * XW[t] + b ----------------
__global__ void gcn_agg_kernel(const unsigned char* __restrict__ A, const float* __restrict__ dinv,
                               const float* __restrict__ xw, const float* __restrict__ gcn_b,
                               float* __restrict__ cat) {
    int r = blockIdx.x;           // 8192
    int b = r >> 10;
    const unsigned char* Arow = A + (long long)r * SEQ;
    __shared__ int   nbr[SEQ];
    __shared__ float wgt[SEQ];
    __shared__ int cnt;
    int tid = threadIdx.x;
    if (tid == 0) cnt = 0;
    __syncthreads();
    for (int t = tid; t < SEQ; t += 256) {
        if (Arow[t]) {
            int p = atomicAdd(&cnt, 1);
            nbr[p] = t;
            wgt[p] = dinv[(b << 10) + t];
        }
    }
    __syncthreads();
    int n = cnt;
    float acc0 = 0.f, acc1 = 0.f, acc2 = 0.f;
    for (int i = 0; i < n; i++) {
        const float* row = xw + ((long)(b << 10) + nbr[i]) * DIM;
        float w = wgt[i];
        acc0 += w * row[tid];
        acc1 += w * row[tid + 256];
        acc2 += w * row[tid + 512];
    }
    float ws = dinv[r];
    long base = (long)r * (2 * DIM);
    cat[base + tid]       = ws * acc0 + gcn_b[tid];
    cat[base + tid + 256] = ws * acc1 + gcn_b[tid + 256];
    cat[base + tid + 512] = ws * acc2 + gcn_b[tid + 512];
}

// ---------------- generic tiled fp32 GEMM (128x128x8, 8x8/thread, batched strides) ----------------
// C[z] = alpha * A[z] (x) op(B[z]) + bias ; z decomposed as (b = z/batchH, h = z%batchH)
template<bool TRANS_B>
__global__ __launch_bounds__(256, 2)
void gemm_kernel(const float* __restrict__ A, long lda,
                 const float* __restrict__ B, long ldb,
                 float* __restrict__ C, long ldc,
                 int M, int N, int K,
                 const float* __restrict__ bias, float alpha,
                 int batchH,
                 long aOffB, long aOffH, long bOffB, long bOffH, long cOffB, long cOffH) {
    int z = blockIdx.z;
    int bb = z / batchH, hh = z % batchH;
    A += bb * aOffB + hh * aOffH;
    B += bb * bOffB + hh * bOffH;
    C += bb * cOffB + hh * cOffH;

    const int BM = 128, BN = 128, BK = 8;
    __shared__ float As[BK][BM];
    __shared__ float Bs[BK][BN];
    int tid = threadIdx.x;            // 256
    int tx = tid & 15, ty = tid >> 4; // 16x16 threads
    int m0 = blockIdx.y * BM, n0 = blockIdx.x * BN;

    float acc[8][8];
    #pragma unroll
    for (int i = 0; i < 8; i++)
        #pragma unroll
        for (int j = 0; j < 8; j++) acc[i][j] = 0.f;

    for (int k0 = 0; k0 < K; k0 += BK) {
        // load A tile: As[kk][m]
        {
            int m  = tid >> 1;
            int kb = (tid & 1) * 4;
            int gm = m0 + m;
            #pragma unroll
            for (int i = 0; i < 4; i++) {
                int kk = kb + i;
                int gk = k0 + kk;
                As[kk][m] = (gm < M && gk < K) ? A[(long)gm * lda + gk] : 0.f;
            }
        }
        // load B tile: Bs[kk][n]
        if (!TRANS_B) {
            int kk = tid >> 5;
            int nb = tid & 31;
            int gk = k0 + kk;
            #pragma unroll
            for (int i = 0; i < 4; i++) {
                int n = nb + 32 * i;
                int gn = n0 + n;
                Bs[kk][n] = (gk < K && gn < N) ? B[(long)gk * ldb + gn] : 0.f;
            }
        } else {
            int n  = tid >> 1;
            int kb = (tid & 1) * 4;
            int gn = n0 + n;
            #pragma unroll
            for (int i = 0; i < 4; i++) {
                int kk = kb + i;
                int gk = k0 + kk;
                Bs[kk][n] = (gn < N && gk < K) ? B[(long)gn * ldb + gk] : 0.f;
            }
        }
        __syncthreads();
        #pragma unroll
        for (int kk = 0; kk < BK; kk++) {
            float a[8], bvals[8];
            #pragma unroll
            for (int i = 0; i < 8; i++) a[i] = As[kk][ty * 8 + i];
            #pragma unroll
            for (int j = 0; j < 8; j++) bvals[j] = Bs[kk][tx * 8 + j];
            #pragma unroll
            for (int i = 0; i < 8; i++)
                #pragma unroll
                for (int j = 0; j < 8; j++) acc[i][j] += a[i] * bvals[j];
        }
        __syncthreads();
    }
    #pragma unroll
    for (int i = 0; i < 8; i++) {
        int gm = m0 + ty * 8 + i;
        if (gm >= M) continue;
        #pragma unroll
        for (int j = 0; j < 8; j++) {
            int gn = n0 + tx * 8 + j;
            if (gn >= N) continue;
            float v = acc[i][j] * alpha;
            if (bias) v += bias[gn];
            C[(long)gm * ldc + gn] = v;
        }
    }
}

// ---------------- row softmax over 1024 ----------------
__global__ void softmax_kernel(float* __restrict__ scores) {
    long r = blockIdx.x;
    float* row = scores + r * SEQ;
    int tid = threadIdx.x;
    __shared__ float red[256];
    float v[4];
    float mx = -INFINITY;
    #pragma unroll
    for (int i = 0; i < 4; i++) { v[i] = row[tid + 256 * i]; mx = fmaxf(mx, v[i]); }
    red[tid] = mx; __syncthreads();
    #pragma unroll
    for (int o = 128; o > 0; o >>= 1) { if (tid < o) red[tid] = fmaxf(red[tid], red[tid + o]); __syncthreads(); }
    mx = red[0]; __syncthreads();
    float sum = 0.f;
    #pragma unroll
    for (int i = 0; i < 4; i++) { v[i] = expf(v[i] - mx); sum += v[i]; }
    red[tid] = sum; __syncthreads();
    #pragma unroll
    for (int o = 128; o > 0; o >>= 1) { if (tid < o) red[tid] += red[tid + o]; __syncthreads(); }
    float inv = 1.f / red[0];
    #pragma unroll
    for (int i = 0; i < 4; i++) row[tid + 256 * i] = v[i] * inv;
}

// ---------------- gate + residual + layernorm (in-place update of h) ----------------
__global__ void fuse_ln_kernel(const float* __restrict__ gatelin, const float* __restrict__ cat,
                               float* __restrict__ h,
                               const float* __restrict__ ln_scale, const float* __restrict__ ln_bias) {
    long r = blockIdx.x;
    int tid = threadIdx.x;
    __shared__ float red[256];
    float f[3];
    #pragma unroll
    for (int i = 0; i < 3; i++) {
        int j = tid + 256 * i;
        float g  = gatelin[r * DIM + j];
        float gc = cat[r * (2 * DIM) + j];
        float at = cat[r * (2 * DIM) + DIM + j];
        float sg = 1.f / (1.f + expf(-g));
        f[i] = sg * gc + (1.f - sg) * at + h[r * DIM + j];
    }
    float s1 = f[0] + f[1] + f[2];
    red[tid] = s1; __syncthreads();
    #pragma unroll
    for (int o = 128; o > 0; o >>= 1) { if (tid < o) red[tid] += red[tid + o]; __syncthreads(); }
    float mu = red[0] * (1.f / DIM);
    __syncthreads();
    float s2 = 0.f;
    #pragma unroll
    for (int i = 0; i < 3; i++) { float d = f[i] - mu; s2 += d * d; }
    red[tid] = s2; __syncthreads();
    #pragma unroll
    for (int o = 128; o > 0; o >>= 1) { if (tid < o) red[tid] += red[tid + o]; __syncthreads(); }
    float var = red[0] * (1.f / DIM);
    float inv = rsqrtf(var + LN_EPS);
    #pragma unroll
    for (int i = 0; i < 3; i++) {
        int j = tid + 256 * i;
        h[r * DIM + j] = (f[i] - mu) * inv * ln_scale[j] + ln_bias[j];
    }
}

// ---------------- host launch helpers ----------------
static void launch_gemm(bool transB, const float* A, long lda, const float* B, long ldb,
                        float* C, long ldc, int M, int N, int K,
                        const float* bias, float alpha,
                        int Z = 1, int batchH = 1,
                        long aOffB = 0, long aOffH = 0, long bOffB = 0, long bOffH = 0,
                        long cOffB = 0, long cOffH = 0) {
    dim3 grid((N + 127) / 128, (M + 127) / 128, Z);
    if (transB)
        gemm_kernel<true><<<grid, 256>>>(A, lda, B, ldb, C, ldc, M, N, K, bias, alpha,
                                         batchH, aOffB, aOffH, bOffB, bOffH, cOffB, cOffH);
    else
        gemm_kernel<false><<<grid, 256>>>(A, lda, B, ldb, C, ldc, M, N, K, bias, alpha,
                                          batchH, aOffB, aOffH, bOffB, bOffH, cOffB, cOffH);
}

extern "C" void kernel_launch(void* const* d_in, const int* in_sizes, int n_in,
                              void* d_out, int out_size) {
    const float* x          = (const float*)d_in[0];
    const float* gcn_w      = (const float*)d_in[1];
    const float* gcn_b      = (const float*)d_in[2];
    const float* attn_in_w  = (const float*)d_in[3];
    const float* attn_in_b  = (const float*)d_in[4];
    const float* attn_out_w = (const float*)d_in[5];
    const float* attn_out_b = (const float*)d_in[6];
    const float* gate_w     = (const float*)d_in[7];
    const float* gate_b     = (const float*)d_in[8];
    const float* ln_scale   = (const float*)d_in[9];
    const float* ln_bias    = (const float*)d_in[10];
    const float* proj_w     = (const float*)d_in[11];
    const float* proj_b     = (const float*)d_in[12];
    float* out = (float*)d_out;

    float *p_h, *p_xw, *p_qkv, *p_scores, *p_ocat, *p_cat, *p_gate, *p_dinv;
    unsigned char* p_adj;
    int* p_topk;
    cudaGetSymbolAddress((void**)&p_h, g_h);
    cudaGetSymbolAddress((void**)&p_xw, g_xw);
    cudaGetSymbolAddress((void**)&p_qkv, g_qkv);
    cudaGetSymbolAddress((void**)&p_scores, g_scores);
    cudaGetSymbolAddress((void**)&p_ocat, g_ocat);
    cudaGetSymbolAddress((void**)&p_cat, g_cat);
    cudaGetSymbolAddress((void**)&p_gate, g_gate);
    cudaGetSymbolAddress((void**)&p_dinv, g_dinv);
    cudaGetSymbolAddress((void**)&p_adj, g_adj);
    cudaGetSymbolAddress((void**)&p_topk, g_topk);

    const float attn_scale = (float)(1.0 / sqrt((double)HDIM));

    // h = x
    copy_kernel<<<1024, 256>>>(x, p_h, (long)ROWS * DIM);

    // dynamic kNN graph from x
    topk_kernel<<<ROWS, 256>>>(x, p_topk);
    zero_bytes_kernel<<<1024, 256>>>(p_adj, (long long)BATCH * SEQ * SEQ);
    scatter_adj_kernel<<<(ROWS + 255) / 256, 256>>>(p_topk, p_adj);
    degree_kernel<<<(ROWS + 255) / 256, 256>>>(p_adj, p_dinv);

    for (int l = 0; l < NLAYERS; l++) {
        const float* gw   = gcn_w + (long)l * DIM * DIM;
        const float* gb   = gcn_b + (long)l * DIM;
        const float* aiw  = attn_in_w + (long)l * DIM * 3 * DIM;
        const float* aib  = attn_in_b + (long)l * 3 * DIM;
        const float* aow  = attn_out_w + (long)l * DIM * DIM;
        const float* aob  = attn_out_b + (long)l * DIM;
        const float* gtw  = gate_w + (long)l * 2 * DIM * DIM;
        const float* gtb  = gate_b + (long)l * DIM;
        const float* lns  = ln_scale + (long)l * DIM;
        const float* lnb  = ln_bias + (long)l * DIM;

        // XW = h @ gcn_w[l]
        launch_gemm(false, p_h, DIM, gw, DIM, p_xw, DIM, ROWS, DIM, DIM, nullptr, 1.f);
        // gcn_out -> cat[:, 0:768]
        gcn_agg_kernel<<<ROWS, 256>>>(p_adj, p_dinv, p_xw, gb, p_cat);
        // qkv = h @ attn_in_w[l] + b
        launch_gemm(false, p_h, DIM, aiw, 3 * DIM, p_qkv, 3 * DIM, ROWS, 3 * DIM, DIM, aib, 1.f);
        // scores[b,h] = Q Kt * scale  (batched over 64 (b,h))
        launch_gemm(true,
                    p_qkv, 3 * DIM, p_qkv + DIM, 3 * DIM, p_scores, SEQ,
                    SEQ, SEQ, HDIM, nullptr, attn_scale,
                    BATCH * HEADS, HEADS,
                    (long)SEQ * 3 * DIM, HDIM,
                    (long)SEQ * 3 * DIM, HDIM,
                    (long)HEADS * SEQ * SEQ, (long)SEQ * SEQ);
        // softmax
        softmax_kernel<<<BATCH * HEADS * SEQ, 256>>>(p_scores);
        // O = P @ V  (batched) -> per-head slices of p_ocat
        launch_gemm(false,
                    p_scores, SEQ, p_qkv + 2 * DIM, 3 * DIM, p_ocat, DIM,
                    SEQ, HDIM, SEQ, nullptr, 1.f,
                    BATCH * HEADS, HEADS,
                    (long)HEADS * SEQ * SEQ, (long)SEQ * SEQ,
                    (long)SEQ * 3 * DIM, HDIM,
                    (long)SEQ * DIM, HDIM);
        // attn_out = O @ attn_out_w[l] + b -> cat[:, 768:1536]
        launch_gemm(false, p_ocat, DIM, aow, DIM, p_cat + DIM, 2 * DIM, ROWS, DIM, DIM, aob, 1.f);
        // gate_lin = cat @ gate_w[l] + b
        launch_gemm(false, p_cat, 2 * DIM, gtw, DIM, p_gate, DIM, ROWS, DIM, 2 * DIM, gtb, 1.f);
        // h = LN(gate*gcn + (1-gate)*attn + h)
        fuse_ln_kernel<<<ROWS, 256>>>(p_gate, p_cat, p_h, lns, lnb);
    }

    // out = h @ proj_w + proj_b
    launch_gemm(false, p_h, DIM, proj_w, DIM, out, DIM, ROWS, DIM, DIM, proj_b, 1.f);
}

// round 3
// speedup vs baseline: 2.1822x; 2.1822x over previous
#include <cuda_runtime.h>
#include <math.h>
#include <stdint.h>

// ---------------- problem constants ----------------
#define BATCH 8
#define SEQ   1024
#define DIM   768
#define HEADS 8
#define HDIM  96
#define KNEIGH 5
#define NLAYERS 3
#define ROWS (BATCH*SEQ)  // 8192
#define LN_EPS 1e-5f

// ---------------- device scratch (static, allocation-free) ----------------
__device__ float g_h[ROWS * DIM];
__device__ float g_xw[ROWS * DIM];
__device__ float g_qkv[ROWS * 3 * DIM];
__device__ float g_scores[(long long)BATCH * HEADS * SEQ * SEQ]; // 256 MB
__device__ float g_ocat[ROWS * DIM];
__device__ float g_cat[ROWS * 2 * DIM];   // [gcn | attn] stride 1536
__device__ float g_gate[ROWS * DIM];
__device__ unsigned char g_adj[(long long)BATCH * SEQ * SEQ];    // 8 MB
__device__ float g_dinv[ROWS];
__device__ int   g_topk[ROWS * KNEIGH];
__device__ float g_wt[12976128];          // transposed weights (52 MB)
__device__ float g_vt[ROWS * DIM];        // V transposed per (b,h): [64, 96, 1024]

// transposed weight offsets
#define WT_GCN(l)  ((long)(l) * 589824)
#define WT_AIW(l)  (1769472L + (long)(l) * 1769472L)
#define WT_AOW(l)  (7077888L + (long)(l) * 589824L)
#define WT_GW(l)   (8847360L + (long)(l) * 1179648L)
#define WT_PROJ    (12386304L)

__device__ __forceinline__ uint32_t to_tf32(float f) {
    uint32_t r; asm("cvt.rna.tf32.f32 %0, %1;" : "=r"(r) : "f"(f)); return r;
}

#define MMA1688(d, a, b) \
    asm volatile("mma.sync.aligned.m16n8k8.row.col.f32.tf32.tf32.f32 " \
        "{%0,%1,%2,%3}, {%4,%5,%6,%7}, {%8,%9}, {%0,%1,%2,%3};" \
        : "+f"((d)[0]), "+f"((d)[1]), "+f"((d)[2]), "+f"((d)[3]) \
        : "r"((a).x), "r"((a).y), "r"((a).z), "r"((a).w), \
          "r"((b).x), "r"((b).y))

// ---------------- mma.sync tf32 GEMM ----------------
// C = alpha * A[M,K] @ Bt[N,K]^T + bias.  Block tile 128x64, warp tile 32x32,
// BK = 32, double-buffered fragment-packed SMEM, 256 threads.
__global__ __launch_bounds__(256, 2)
void mma_gemm(const float* __restrict__ A, long lda,
              const float* __restrict__ Bt, long ldb,
              float* __restrict__ C, long ldc,
              int M, int N, int K,
              const float* __restrict__ bias, float alpha,
              int batchH,
              long aOffB, long aOffH, long bOffB, long bOffH,
              long cOffB, long cOffH) {
    __shared__ uint32_t sA[2][4096];   // 8 m-tiles x 4 k-tiles x 32 lanes x 4 regs
    __shared__ uint32_t sB[2][2048];   // 8 n-tiles x 4 k-tiles x 32 lanes x 2 regs

    int z = blockIdx.z;
    int bb = z / batchH, hh = z % batchH;
    A  += bb * aOffB + hh * aOffH;
    Bt += bb * bOffB + hh * bOffH;
    C  += bb * cOffB + hh * cOffH;
    int m0 = blockIdx.y * 128, n0 = blockIdx.x * 64;
    int tid = threadIdx.x, lane = tid & 31, wid = tid >> 5;
    int wm = wid & 3, wn = wid >> 2;

    const float* Ab = A + (long)m0 * lda;

    // loader index precompute
    int aR[4], aQ[4], aS[4];
    #pragma unroll
    for (int i = 0; i < 4; i++) {
        int idx = tid + 256 * i;
        int r = idx >> 3, q = idx & 7;
        aR[i] = r; aQ[i] = q;
        int im = r >> 4, mm = r & 15, ik = q >> 1;
        aS[i] = ((im * 4 + ik) * 32 + (mm & 7) * 4) * 4 + (q & 1) * 2 + ((mm >> 3) & 1);
    }
    int bR[2], bQ[2], bS[2];
    #pragma unroll
    for (int i = 0; i < 2; i++) {
        int idx = tid + 256 * i;
        int r = idx >> 3, q = idx & 7;
        bR[i] = r; bQ[i] = q;
        int in = r >> 3, nn = r & 7, ik = q >> 1;
        bS[i] = ((in * 4 + ik) * 32 + nn * 4) * 2 + (q & 1);
    }

    float acc[2][4][4];
    #pragma unroll
    for (int i = 0; i < 2; i++)
        #pragma unroll
        for (int j = 0; j < 4; j++)
            #pragma unroll
            for (int c = 0; c < 4; c++) acc[i][j][c] = 0.f;

    int nch = K >> 5;
    float4 va[4], vb[2];

    // prologue: load chunk 0, store to buf 0
    #pragma unroll
    for (int i = 0; i < 4; i++)
        va[i] = *(const float4*)(Ab + (long)aR[i] * lda + aQ[i] * 4);
    #pragma unroll
    for (int i = 0; i < 2; i++) {
        int gn = n0 + bR[i];
        vb[i] = (gn < N) ? *(const float4*)(Bt + (long)gn * ldb + bQ[i] * 4)
                         : make_float4(0.f, 0.f, 0.f, 0.f);
    }
    #pragma unroll
    for (int i = 0; i < 4; i++) {
        uint32_t* s = &sA[0][aS[i]];
        s[0] = to_tf32(va[i].x); s[4]  = to_tf32(va[i].y);
        s[8] = to_tf32(va[i].z); s[12] = to_tf32(va[i].w);
    }
    #pragma unroll
    for (int i = 0; i < 2; i++) {
        uint32_t* s = &sB[0][bS[i]];
        s[0] = to_tf32(vb[i].x); s[2] = to_tf32(vb[i].y);
        s[4] = to_tf32(vb[i].z); s[6] = to_tf32(vb[i].w);
    }
    __syncthreads();

    for (int it = 0; it < nch; it++) {
        int buf = it & 1;
        bool more = (it + 1 < nch);
        if (more) {
            long koff = (long)(it + 1) * 32;
            #pragma unroll
            for (int i = 0; i < 4; i++)
                va[i] = *(const float4*)(Ab + (long)aR[i] * lda + koff + aQ[i] * 4);
            #pragma unroll
            for (int i = 0; i < 2; i++) {
                int gn = n0 + bR[i];
                vb[i] = (gn < N) ? *(const float4*)(Bt + (long)gn * ldb + koff + bQ[i] * 4)
                                 : make_float4(0.f, 0.f, 0.f, 0.f);
            }
        }
        // compute on buf
        #pragma unroll
        for (int ik = 0; ik < 4; ik++) {
            uint4 af[2];
            uint2 bf[4];
            #pragma unroll
            for (int i2 = 0; i2 < 2; i2++)
                af[i2] = *(const uint4*)&sA[buf][(((wm * 2 + i2) * 4 + ik) * 32 + lane) * 4];
            #pragma unroll
            for (int j2 = 0; j2 < 4; j2++)
                bf[j2] = *(const uint2*)&sB[buf][(((wn * 4 + j2) * 4 + ik) * 32 + lane) * 2];
            #pragma unroll
            for (int i2 = 0; i2 < 2; i2++)
                #pragma unroll
                for (int j2 = 0; j2 < 4; j2++)
                    MMA1688(acc[i2][j2], af[i2], bf[j2]);
        }
        __syncthreads();
        if (more) {
            int nb = buf ^ 1;
            #pragma unroll
            for (int i = 0; i < 4; i++) {
                uint32_t* s = &sA[nb][aS[i]];
                s[0] = to_tf32(va[i].x); s[4]  = to_tf32(va[i].y);
                s[8] = to_tf32(va[i].z); s[12] = to_tf32(va[i].w);
            }
            #pragma unroll
            for (int i = 0; i < 2; i++) {
                uint32_t* s = &sB[nb][bS[i]];
                s[0] = to_tf32(vb[i].x); s[2] = to_tf32(vb[i].y);
                s[4] = to_tf32(vb[i].z); s[6] = to_tf32(vb[i].w);
            }
            __syncthreads();
        }
    }

    // epilogue
    int g = lane >> 2, t = lane & 3;
    #pragma unroll
    for (int i2 = 0; i2 < 2; i2++) {
        int gm = m0 + (wm * 2 + i2) * 16 + g;
        #pragma unroll
        for (int j2 = 0; j2 < 4; j2++) {
            int gn = n0 + (wn * 4 + j2) * 8 + t * 2;
            if (gn < N) {
                float b0 = bias ? __ldg(bias + gn) : 0.f;
                float b1 = bias ? __ldg(bias + gn + 1) : 0.f;
                float2 v0, v1;
                v0.x = acc[i2][j2][0] * alpha + b0;
                v0.y = acc[i2][j2][1] * alpha + b1;
                v1.x = acc[i2][j2][2] * alpha + b0;
                v1.y = acc[i2][j2][3] * alpha + b1;
                *(float2*)&C[(long)gm * ldc + gn] = v0;
                *(float2*)&C[(long)(gm + 8) * ldc + gn] = v1;
            }
        }
    }
}

// ---------------- transposes ----------------
__global__ void transpose_kernel(const float* __restrict__ src, float* __restrict__ dst,
                                 int R, int Cc) {
    __shared__ float t[32][33];
    int c0 = blockIdx.x * 32, r0 = blockIdx.y * 32;
    int tx = threadIdx.x, ty = threadIdx.y;
    for (int i = ty; i < 32; i += 8) {
        int r = r0 + i, c = c0 + tx;
        if (r < R && c < Cc) t[i][tx] = src[(long)r * Cc + c];
    }
    __syncthreads();
    for (int i = ty; i < 32; i += 8) {
        int c = c0 + i, r = r0 + tx;
        if (c < Cc && r < R) dst[(long)c * R + r] = t[tx][i];
    }
}

// vt[(b*8+h)*96 + d][t] = qkv[(b*1024+t)*2304 + 1536 + h*96 + d]
__global__ void transpose_v_kernel(const float* __restrict__ qkv, float* __restrict__ vt) {
    int z = blockIdx.z; int b = z >> 3, h = z & 7;
    __shared__ float tb[32][33];
    int d0 = blockIdx.x * 32, t0 = blockIdx.y * 32;
    int tx = threadIdx.x, ty = threadIdx.y;
    const float* src = qkv + (long)b * 1024 * 2304 + 1536 + h * 96;
    for (int i = ty; i < 32; i += 8)
        tb[i][tx] = src[(long)(t0 + i) * 2304 + d0 + tx];
    __syncthreads();
    float* dst = vt + ((long)z * 96 + d0) * 1024 + t0;
    for (int j = ty; j < 32; j += 8)
        dst[(long)j * 1024 + tx] = tb[tx][j];
}

// ---------------- misc elementwise ----------------
__global__ void copy_kernel(const float* __restrict__ src, float* __restrict__ dst, long n) {
    long i = (long)blockIdx.x * blockDim.x + threadIdx.x;
    long stride = (long)gridDim.x * blockDim.x;
    for (; i < n; i += stride) dst[i] = src[i];
}
__global__ void zero_bytes_kernel(unsigned char* p, long n) {
    long i = (long)blockIdx.x * blockDim.x + threadIdx.x;
    long stride = (long)gridDim.x * blockDim.x;
    int* pi = (int*)p;
    long nw = n >> 2;
    for (; i < nw; i += stride) pi[i] = 0;
}

// ---------------- topk select (sim precomputed in fp32) ----------------
__global__ void topk_select_kernel(const float* __restrict__ sim, int* __restrict__ idx_out) {
    long r = blockIdx.x;
    const float* row = sim + r * SEQ;
    __shared__ float s[SEQ];
    __shared__ float bv[256];
    __shared__ int   bi[256];
    int tid = threadIdx.x;
    for (int i = tid; i < SEQ; i += 256) s[i] = row[i];
    __syncthreads();
    for (int sel = 0; sel < KNEIGH; sel++) {
        float v = -INFINITY; int mi = 0x7fffffff;
        for (int t = tid; t < SEQ; t += 256) {
            float sv = s[t];
            if (sv > v || (sv == v && t < mi)) { v = sv; mi = t; }
        }
        bv[tid] = v; bi[tid] = mi;
        __syncthreads();
        for (int o = 128; o > 0; o >>= 1) {
            if (tid < o) {
                if (bv[tid + o] > bv[tid] || (bv[tid + o] == bv[tid] && bi[tid + o] < bi[tid])) {
                    bv[tid] = bv[tid + o]; bi[tid] = bi[tid + o];
                }
            }
            __syncthreads();
        }
        if (tid == 0) { idx_out[r * KNEIGH + sel] = bi[0]; s[bi[0]] = -INFINITY; }
        __syncthreads();
    }
}

// ---------------- adjacency + degree ----------------
__global__ void scatter_adj_kernel(const int* __restrict__ idx, unsigned char* __restrict__ A) {
    int r = blockIdx.x * blockDim.x + threadIdx.x;
    if (r >= ROWS) return;
    int b = r >> 10, s = r & 1023;
    unsigned char* Ab = A + (long long)b * SEQ * SEQ;
    Ab[(long)s * SEQ + s] = 1;
    #pragma unroll
    for (int j = 0; j < KNEIGH; j++) {
        int t = idx[(long)r * KNEIGH + j];
        Ab[(long)s * SEQ + t] = 1;
        Ab[(long)t * SEQ + s] = 1;
    }
}
__global__ void degree_kernel(const unsigned char* __restrict__ A, float* __restrict__ dinv) {
    int r = blockIdx.x * blockDim.x + threadIdx.x;
    if (r >= ROWS) return;
    const uint32_t* row = (const uint32_t*)(A + (long long)r * SEQ);
    int d = 0;
    for (int i = 0; i < SEQ / 4; i++) {
        uint32_t w = row[i];
        d += (w & 0xff) + ((w >> 8) & 0xff) + ((w >> 16) & 0xff) + ((w >> 24) & 0xff);
    }
    dinv[r] = rsqrtf((float)d);
}

// ---------------- sparse GCN aggregate ----------------
__global__ void gcn_agg_kernel(const unsigned char* __restrict__ A, const float* __restrict__ dinv,
                               const float* __restrict__ xw, const float* __restrict__ gcn_b,
                               float* __restrict__ cat) {
    int r = blockIdx.x;
    int b = r >> 10;
    const unsigned char* Arow = A + (long long)r * SEQ;
    __shared__ int   nbr[SEQ];
    __shared__ float wgt[SEQ];
    __shared__ int cnt;
    int tid = threadIdx.x;
    if (tid == 0) cnt = 0;
    __syncthreads();
    for (int t = tid; t < SEQ; t += 256) {
        if (Arow[t]) {
            int p = atomicAdd(&cnt, 1);
            nbr[p] = t;
            wgt[p] = dinv[(b << 10) + t];
        }
    }
    __syncthreads();
    int n = cnt;
    float acc0 = 0.f, acc1 = 0.f, acc2 = 0.f;
    for (int i = 0; i < n; i++) {
        const float* row = xw + ((long)(b << 10) + nbr[i]) * DIM;
        float w = wgt[i];
        acc0 += w * row[tid];
        acc1 += w * row[tid + 256];
        acc2 += w * row[tid + 512];
    }
    float ws = dinv[r];
    long base = (long)r * (2 * DIM);
    cat[base + tid]       = ws * acc0 + gcn_b[tid];
    cat[base + tid + 256] = ws * acc1 + gcn_b[tid + 256];
    cat[base + tid + 512] = ws * acc2 + gcn_b[tid + 512];
}

// ---------------- SIMT fp32 GEMM (kept for exact sim = x x^T) ----------------
template<bool TRANS_B>
__global__ __launch_bounds__(256, 2)
void gemm_kernel(const float* __restrict__ A, long lda,
                 const float* __restrict__ B, long ldb,
                 float* __restrict__ C, long ldc,
                 int M, int N, int K,
                 const float* __restrict__ bias, float alpha,
                 int batchH,
                 long aOffB, long aOffH, long bOffB, long bOffH, long cOffB, long cOffH) {
    int z = blockIdx.z;
    int bb = z / batchH, hh = z % batchH;
    A += bb * aOffB + hh * aOffH;
    B += bb * bOffB + hh * bOffH;
    C += bb * cOffB + hh * cOffH;
    const int BM = 128, BN = 128, BK = 8;
    __shared__ float As[BK][BM];
    __shared__ float Bs[BK][BN];
    int tid = threadIdx.x;
    int tx = tid & 15, ty = tid >> 4;
    int m0 = blockIdx.y * BM, n0 = blockIdx.x * BN;
    float acc[8][8];
    #pragma unroll
    for (int i = 0; i < 8; i++)
        #pragma unroll
        for (int j = 0; j < 8; j++) acc[i][j] = 0.f;
    for (int k0 = 0; k0 < K; k0 += BK) {
        {
            int m  = tid >> 1;
            int kb = (tid & 1) * 4;
            int gm = m0 + m;
            #pragma unroll
            for (int i = 0; i < 4; i++) {
                int kk = kb + i, gk = k0 + kk;
                As[kk][m] = (gm < M && gk < K) ? A[(long)gm * lda + gk] : 0.f;
            }
        }
        if (!TRANS_B) {
            int kk = tid >> 5, nb = tid & 31, gk = k0 + kk;
            #pragma unroll
            for (int i = 0; i < 4; i++) {
                int n = nb + 32 * i, gn = n0 + n;
                Bs[kk][n] = (gk < K && gn < N) ? B[(long)gk * ldb + gn] : 0.f;
            }
        } else {
            int n = tid >> 1, kb = (tid & 1) * 4, gn = n0 + n;
            #pragma unroll
            for (int i = 0; i < 4; i++) {
                int kk = kb + i, gk = k0 + kk;
                Bs[kk][n] = (gn < N && gk < K) ? B[(long)gn * ldb + gk] : 0.f;
            }
        }
        __syncthreads();
        #pragma unroll
        for (int kk = 0; kk < BK; kk++) {
            float a[8], bvals[8];
            #pragma unroll
            for (int i = 0; i < 8; i++) a[i] = As[kk][ty * 8 + i];
            #pragma unroll
            for (int j = 0; j < 8; j++) bvals[j] = Bs[kk][tx * 8 + j];
            #pragma unroll
            for (int i = 0; i < 8; i++)
                #pragma unroll
                for (int j = 0; j < 8; j++) acc[i][j] += a[i] * bvals[j];
        }
        __syncthreads();
    }
    #pragma unroll
    for (int i = 0; i < 8; i++) {
        int gm = m0 + ty * 8 + i;
        if (gm >= M) continue;
        #pragma unroll
        for (int j = 0; j < 8; j++) {
            int gn = n0 + tx * 8 + j;
            if (gn >= N) continue;
            float v = acc[i][j] * alpha;
            if (bias) v += bias[gn];
            C[(long)gm * ldc + gn] = v;
        }
    }
}

// ---------------- softmax ----------------
__global__ void softmax_kernel(float* __restrict__ scores) {
    long r = blockIdx.x;
    float* row = scores + r * SEQ;
    int tid = threadIdx.x;
    __shared__ float red[256];
    float v[4];
    float mx = -INFINITY;
    #pragma unroll
    for (int i = 0; i < 4; i++) { v[i] = row[tid + 256 * i]; mx = fmaxf(mx, v[i]); }
    red[tid] = mx; __syncthreads();
    #pragma unroll
    for (int o = 128; o > 0; o >>= 1) { if (tid < o) red[tid] = fmaxf(red[tid], red[tid + o]); __syncthreads(); }
    mx = red[0]; __syncthreads();
    float sum = 0.f;
    #pragma unroll
    for (int i = 0; i < 4; i++) { v[i] = expf(v[i] - mx); sum += v[i]; }
    red[tid] = sum; __syncthreads();
    #pragma unroll
    for (int o = 128; o > 0; o >>= 1) { if (tid < o) red[tid] += red[tid + o]; __syncthreads(); }
    float inv = 1.f / red[0];
    #pragma unroll
    for (int i = 0; i < 4; i++) row[tid + 256 * i] = v[i] * inv;
}

// ---------------- gate + residual + layernorm ----------------
__global__ void fuse_ln_kernel(const float* __restrict__ gatelin, const float* __restrict__ cat,
                               float* __restrict__ h,
                               const float* __restrict__ ln_scale, const float* __restrict__ ln_bias) {
    long r = blockIdx.x;
    int tid = threadIdx.x;
    __shared__ float red[256];
    float f[3];
    #pragma unroll
    for (int i = 0; i < 3; i++) {
        int j = tid + 256 * i;
        float g  = gatelin[r * DIM + j];
        float gc = cat[r * (2 * DIM) + j];
        float at = cat[r * (2 * DIM) + DIM + j];
        float sg = 1.f / (1.f + expf(-g));
        f[i] = sg * gc + (1.f - sg) * at + h[r * DIM + j];
    }
    float s1 = f[0] + f[1] + f[2];
    red[tid] = s1; __syncthreads();
    #pragma unroll
    for (int o = 128; o > 0; o >>= 1) { if (tid < o) red[tid] += red[tid + o]; __syncthreads(); }
    float mu = red[0] * (1.f / DIM);
    __syncthreads();
    float s2 = 0.f;
    #pragma unroll
    for (int i = 0; i < 3; i++) { float d = f[i] - mu; s2 += d * d; }
    red[tid] = s2; __syncthreads();
    #pragma unroll
    for (int o = 128; o > 0; o >>= 1) { if (tid < o) red[tid] += red[tid + o]; __syncthreads(); }
    float var = red[0] * (1.f / DIM);
    float inv = rsqrtf(var + LN_EPS);
    #pragma unroll
    for (int i = 0; i < 3; i++) {
        int j = tid + 256 * i;
        h[r * DIM + j] = (f[i] - mu) * inv * ln_scale[j] + ln_bias[j];
    }
}

// ---------------- host helper ----------------
static void launch_mma(const float* A, long lda, const float* Bt, long ldb,
                       float* C, long ldc, int M, int N, int K,
                       const float* bias, float alpha,
                       int Z = 1, int batchH = 1,
                       long aOffB = 0, long aOffH = 0, long bOffB = 0, long bOffH = 0,
                       long cOffB = 0, long cOffH = 0) {
    dim3 grid((N + 63) / 64, M / 128, Z);
    mma_gemm<<<grid, 256>>>(A, lda, Bt, ldb, C, ldc, M, N, K, bias, alpha,
                            batchH, aOffB, aOffH, bOffB, bOffH, cOffB, cOffH);
}

extern "C" void kernel_launch(void* const* d_in, const int* in_sizes, int n_in,
                              void* d_out, int out_size) {
    const float* x          = (const float*)d_in[0];
    const float* gcn_w      = (const float*)d_in[1];
    const float* gcn_b      = (const float*)d_in[2];
    const float* attn_in_w  = (const float*)d_in[3];
    const float* attn_in_b  = (const float*)d_in[4];
    const float* attn_out_w = (const float*)d_in[5];
    const float* attn_out_b = (const float*)d_in[6];
    const float* gate_w     = (const float*)d_in[7];
    const float* gate_b     = (const float*)d_in[8];
    const float* ln_scale   = (const float*)d_in[9];
    const float* ln_bias    = (const float*)d_in[10];
    const float* proj_w     = (const float*)d_in[11];
    const float* proj_b     = (const float*)d_in[12];
    float* out = (float*)d_out;

    float *p_h, *p_xw, *p_qkv, *p_scores, *p_ocat, *p_cat, *p_gate, *p_dinv, *p_wt, *p_vt;
    unsigned char* p_adj;
    int* p_topk;
    cudaGetSymbolAddress((void**)&p_h, g_h);
    cudaGetSymbolAddress((void**)&p_xw, g_xw);
    cudaGetSymbolAddress((void**)&p_qkv, g_qkv);
    cudaGetSymbolAddress((void**)&p_scores, g_scores);
    cudaGetSymbolAddress((void**)&p_ocat, g_ocat);
    cudaGetSymbolAddress((void**)&p_cat, g_cat);
    cudaGetSymbolAddress((void**)&p_gate, g_gate);
    cudaGetSymbolAddress((void**)&p_dinv, g_dinv);
    cudaGetSymbolAddress((void**)&p_adj, g_adj);
    cudaGetSymbolAddress((void**)&p_topk, g_topk);
    cudaGetSymbolAddress((void**)&p_wt, g_wt);
    cudaGetSymbolAddress((void**)&p_vt, g_vt);

    const float attn_scale = (float)(1.0 / sqrt((double)HDIM));
    dim3 tb(32, 8);

    // h = x
    copy_kernel<<<1024, 256>>>(x, p_h, (long)ROWS * DIM);

    // transpose all weights once: src [K,N] -> dst [N,K]
    for (int l = 0; l < NLAYERS; l++) {
        transpose_kernel<<<dim3(768 / 32, 768 / 32), tb>>>(gcn_w + (long)l * DIM * DIM, p_wt + WT_GCN(l), DIM, DIM);
        transpose_kernel<<<dim3(2304 / 32, 768 / 32), tb>>>(attn_in_w + (long)l * DIM * 3 * DIM, p_wt + WT_AIW(l), DIM, 3 * DIM);
        transpose_kernel<<<dim3(768 / 32, 768 / 32), tb>>>(attn_out_w + (long)l * DIM * DIM, p_wt + WT_AOW(l), DIM, DIM);
        transpose_kernel<<<dim3(768 / 32, 1536 / 32), tb>>>(gate_w + (long)l * 2 * DIM * DIM, p_wt + WT_GW(l), 2 * DIM, DIM);
    }
    transpose_kernel<<<dim3(768 / 32, 768 / 32), tb>>>(proj_w, p_wt + WT_PROJ, DIM, DIM);

    // sim = x x^T (exact fp32 SIMT), then top-5 select
    {
        dim3 grid(SEQ / 128, SEQ / 128, BATCH);
        gemm_kernel<true><<<grid, 256>>>(x, DIM, x, DIM, p_scores, SEQ,
                                         SEQ, SEQ, DIM, nullptr, 1.f,
                                         1, (long)SEQ * DIM, 0, (long)SEQ * DIM, 0,
                                         (long)SEQ * SEQ, 0);
    }
    topk_select_kernel<<<ROWS, 256>>>(p_scores, p_topk);
    zero_bytes_kernel<<<1024, 256>>>(p_adj, (long long)BATCH * SEQ * SEQ);
    scatter_adj_kernel<<<(ROWS + 255) / 256, 256>>>(p_topk, p_adj);
    degree_kernel<<<(ROWS + 255) / 256, 256>>>(p_adj, p_dinv);

    for (int l = 0; l < NLAYERS; l++) {
        const float* gb  = gcn_b + (long)l * DIM;
        const float* aib = attn_in_b + (long)l * 3 * DIM;
        const float* aob = attn_out_b + (long)l * DIM;
        const float* gtb = gate_b + (long)l * DIM;
        const float* lns = ln_scale + (long)l * DIM;
        const float* lnb = ln_bias + (long)l * DIM;

        // XW = h @ gcn_w[l]
        launch_mma(p_h, DIM, p_wt + WT_GCN(l), DIM, p_xw, DIM, ROWS, DIM, DIM, nullptr, 1.f);
        // gcn_out -> cat[:, 0:768]
        gcn_agg_kernel<<<ROWS, 256>>>(p_adj, p_dinv, p_xw, gb, p_cat);
        // qkv = h @ attn_in_w[l] + b
        launch_mma(p_h, DIM, p_wt + WT_AIW(l), DIM, p_qkv, 3 * DIM, ROWS, 3 * DIM, DIM, aib, 1.f);
        // V transpose: [64, 96, 1024]
        transpose_v_kernel<<<dim3(3, 32, 64), tb>>>(p_qkv, p_vt);
        // scores = Q K^T * scale   (A=Q slice, Bt=K slice, both [1024,96] ld 2304)
        launch_mma(p_qkv, 3 * DIM, p_qkv + DIM, 3 * DIM, p_scores, SEQ,
                   SEQ, SEQ, HDIM, nullptr, attn_scale,
                   BATCH * HEADS, HEADS,
                   (long)SEQ * 3 * DIM, HDIM,
                   (long)SEQ * 3 * DIM, HDIM,
                   (long)HEADS * SEQ * SEQ, (long)SEQ * SEQ);
        // softmax
        softmax_kernel<<<BATCH * HEADS * SEQ, 256>>>(p_scores);
        // O = P @ V : A = scores, Bt = vt [96,1024]
        launch_mma(p_scores, SEQ, p_vt, SEQ, p_ocat, DIM,
                   SEQ, HDIM, SEQ, nullptr, 1.f,
                   BATCH * HEADS, HEADS,
                   (long)HEADS * SEQ * SEQ, (long)SEQ * SEQ,
                   (long)HEADS * HDIM * SEQ, (long)HDIM * SEQ,
                   (long)SEQ * DIM, HDIM);
        // attn_out = O @ attn_out_w[l] + b -> cat[:, 768:1536]
        launch_mma(p_ocat, DIM, p_wt + WT_AOW(l), DIM, p_cat + DIM, 2 * DIM, ROWS, DIM, DIM, aob, 1.f);
        // gate_lin = cat @ gate_w[l] + b
        launch_mma(p_cat, 2 * DIM, p_wt + WT_GW(l), 2 * DIM, p_gate, DIM, ROWS, DIM, 2 * DIM, gtb, 1.f);
        // h = LN(gate*gcn + (1-gate)*attn + h)
        fuse_ln_kernel<<<ROWS, 256>>>(p_gate, p_cat, p_h, lns, lnb);
    }

    // out = h @ proj_w + proj_b
    launch_mma(p_h, DIM, p_wt + WT_PROJ, DIM, out, DIM, ROWS, DIM, DIM, proj_b, 1.f);
}

// round 4
// speedup vs baseline: 2.5291x; 1.1590x over previous
#include <cuda_runtime.h>
#include <math.h>
#include <stdint.h>

// ---------------- problem constants ----------------
#define BATCH 8
#define SEQ   1024
#define DIM   768
#define HEADS 8
#define HDIM  96
#define KNEIGH 5
#define NLAYERS 3
#define ROWS (BATCH*SEQ)  // 8192
#define LN_EPS 1e-5f

// ---------------- device scratch (static, allocation-free) ----------------
__device__ float g_h[ROWS * DIM];
__device__ float g_xw[ROWS * DIM];
__device__ float g_qkv[ROWS * 3 * DIM];
__device__ float g_scores[(long long)BATCH * HEADS * SEQ * SEQ]; // 256 MB
__device__ float g_ocat[ROWS * DIM];
__device__ float g_cat[ROWS * 2 * DIM];   // [gcn | attn] stride 1536
__device__ float g_gate[ROWS * DIM];
__device__ unsigned char g_adj[(long long)BATCH * SEQ * SEQ];    // 8 MB
__device__ float g_dinv[ROWS];
__device__ int   g_topk[ROWS * KNEIGH];
__device__ float g_wt[12976128];          // transposed weights (52 MB)
__device__ float g_vt[ROWS * DIM];        // V transposed per (b,h): [64, 96, 1024]

// transposed weight offsets
#define WT_GCN(l)  ((long)(l) * 589824)
#define WT_AIW(l)  (1769472L + (long)(l) * 1769472L)
#define WT_AOW(l)  (7077888L + (long)(l) * 589824L)
#define WT_GW(l)   (8847360L + (long)(l) * 1179648L)
#define WT_PROJ    (12386304L)

__device__ __forceinline__ uint32_t to_tf32(float f) {
    uint32_t r; asm("cvt.rna.tf32.f32 %0, %1;" : "=r"(r) : "f"(f)); return r;
}

// FMA-only exp (no MUFU): range-reduce to r in [-ln2/2, ln2/2], degree-7 Horner,
// exponent via bit splice. |rel err| < 1e-6 for x > -87.
__device__ __forceinline__ float fexp(float x) {
    x = fmaxf(x, -87.0f);
    float y = x * 1.4426950408889634f;
    int i = __float2int_rn(y);
    float r = (y - (float)i) * 0.6931471805599453f;
    float p = 1.9841270e-4f;
    p = fmaf(p, r, 1.3888889e-3f);
    p = fmaf(p, r, 8.3333333e-3f);
    p = fmaf(p, r, 4.1666667e-2f);
    p = fmaf(p, r, 1.6666667e-1f);
    p = fmaf(p, r, 0.5f);
    p = fmaf(p, r, 1.0f);
    p = fmaf(p, r, 1.0f);
    return p * __int_as_float((i + 127) << 23);
}

#define MMA1688(d, a, b) \
    asm volatile("mma.sync.aligned.m16n8k8.row.col.f32.tf32.tf32.f32 " \
        "{%0,%1,%2,%3}, {%4,%5,%6,%7}, {%8,%9}, {%0,%1,%2,%3};" \
        : "+f"((d)[0]), "+f"((d)[1]), "+f"((d)[2]), "+f"((d)[3]) \
        : "r"((a).x), "r"((a).y), "r"((a).z), "r"((a).w), \
          "r"((b).x), "r"((b).y))

// ---------------- mma.sync tf32 GEMM ----------------
// C = alpha * A[M,K] @ Bt[N,K]^T + bias.  Block tile 128x128, warp tile 64x32,
// BK = 32, double-buffered fragment-packed dynamic SMEM (64 KB), 256 threads.
__global__ __launch_bounds__(256, 1)
void mma_gemm(const float* __restrict__ A, long lda,
              const float* __restrict__ Bt, long ldb,
              float* __restrict__ C, long ldc,
              int M, int N, int K,
              const float* __restrict__ bias, float alpha,
              int batchH,
              long aOffB, long aOffH, long bOffB, long bOffH,
              long cOffB, long cOffH) {
    extern __shared__ uint32_t dsm[];
    // sA buffers: dsm + buf*4096 ; sB buffers: dsm + 8192 + buf*4096

    int z = blockIdx.z;
    int bb = z / batchH, hh = z % batchH;
    A  += bb * aOffB + hh * aOffH;
    Bt += bb * bOffB + hh * bOffH;
    C  += bb * cOffB + hh * cOffH;
    int m0 = blockIdx.y * 128, n0 = blockIdx.x * 128;
    int tid = threadIdx.x, lane = tid & 31, wid = tid >> 5;
    int wm = wid & 1, wn = wid >> 1;   // warp grid 2(m) x 4(n), warp tile 64x32

    const float* Ab = A + (long)m0 * lda;

    // loader index precompute (fragment-packed layout, verified in R3)
    int aR[4], aQ[4], aS[4];
    #pragma unroll
    for (int i = 0; i < 4; i++) {
        int idx = tid + 256 * i;
        int r = idx >> 3, q = idx & 7;
        aR[i] = r; aQ[i] = q;
        int im = r >> 4, mm = r & 15, ik = q >> 1;
        aS[i] = ((im * 4 + ik) * 32 + (mm & 7) * 4) * 4 + (q & 1) * 2 + ((mm >> 3) & 1);
    }
    int bR[4], bQ[4], bS[4];
    #pragma unroll
    for (int i = 0; i < 4; i++) {
        int idx = tid + 256 * i;
        int r = idx >> 3, q = idx & 7;
        bR[i] = r; bQ[i] = q;
        int in = r >> 3, nn = r & 7, ik = q >> 1;
        bS[i] = ((in * 4 + ik) * 32 + nn * 4) * 2 + (q & 1);
    }

    float acc[4][4][4];
    #pragma unroll
    for (int i = 0; i < 4; i++)
        #pragma unroll
        for (int j = 0; j < 4; j++)
            #pragma unroll
            for (int c = 0; c < 4; c++) acc[i][j][c] = 0.f;

    int nch = K >> 5;
    float4 va[4], vb[4];

    // prologue: load chunk 0, store to buf 0
    #pragma unroll
    for (int i = 0; i < 4; i++)
        va[i] = *(const float4*)(Ab + (long)aR[i] * lda + aQ[i] * 4);
    #pragma unroll
    for (int i = 0; i < 4; i++) {
        int gn = n0 + bR[i];
        vb[i] = (gn < N) ? *(const float4*)(Bt + (long)gn * ldb + bQ[i] * 4)
                         : make_float4(0.f, 0.f, 0.f, 0.f);
    }
    {
        uint32_t* sA0 = dsm;
        uint32_t* sB0 = dsm + 8192;
        #pragma unroll
        for (int i = 0; i < 4; i++) {
            uint32_t* s = &sA0[aS[i]];
            s[0] = to_tf32(va[i].x); s[4]  = to_tf32(va[i].y);
            s[8] = to_tf32(va[i].z); s[12] = to_tf32(va[i].w);
        }
        #pragma unroll
        for (int i = 0; i < 4; i++) {
            uint32_t* s = &sB0[bS[i]];
            s[0] = to_tf32(vb[i].x); s[2] = to_tf32(vb[i].y);
            s[4] = to_tf32(vb[i].z); s[6] = to_tf32(vb[i].w);
        }
    }
    __syncthreads();

    for (int it = 0; it < nch; it++) {
        int buf = it & 1;
        bool more = (it + 1 < nch);
        if (more) {
            long koff = (long)(it + 1) * 32;
            #pragma unroll
            for (int i = 0; i < 4; i++)
                va[i] = *(const float4*)(Ab + (long)aR[i] * lda + koff + aQ[i] * 4);
            #pragma unroll
            for (int i = 0; i < 4; i++) {
                int gn = n0 + bR[i];
                vb[i] = (gn < N) ? *(const float4*)(Bt + (long)gn * ldb + koff + bQ[i] * 4)
                                 : make_float4(0.f, 0.f, 0.f, 0.f);
            }
        }
        // compute on buf
        const uint32_t* sAb = dsm + buf * 4096;
        const uint32_t* sBb = dsm + 8192 + buf * 4096;
        #pragma unroll
        for (int ik = 0; ik < 4; ik++) {
            uint4 af[4];
            uint2 bf[4];
            #pragma unroll
            for (int i2 = 0; i2 < 4; i2++)
                af[i2] = *(const uint4*)&sAb[(((wm * 4 + i2) * 4 + ik) * 32 + lane) * 4];
            #pragma unroll
            for (int j2 = 0; j2 < 4; j2++)
                bf[j2] = *(const uint2*)&sBb[(((wn * 4 + j2) * 4 + ik) * 32 + lane) * 2];
            #pragma unroll
            for (int i2 = 0; i2 < 4; i2++)
                #pragma unroll
                for (int j2 = 0; j2 < 4; j2++)
                    MMA1688(acc[i2][j2], af[i2], bf[j2]);
        }
        __syncthreads();
        if (more) {
            uint32_t* sAn = dsm + (buf ^ 1) * 4096;
            uint32_t* sBn = dsm + 8192 + (buf ^ 1) * 4096;
            #pragma unroll
            for (int i = 0; i < 4; i++) {
                uint32_t* s = &sAn[aS[i]];
                s[0] = to_tf32(va[i].x); s[4]  = to_tf32(va[i].y);
                s[8] = to_tf32(va[i].z); s[12] = to_tf32(va[i].w);
            }
            #pragma unroll
            for (int i = 0; i < 4; i++) {
                uint32_t* s = &sBn[bS[i]];
                s[0] = to_tf32(vb[i].x); s[2] = to_tf32(vb[i].y);
                s[4] = to_tf32(vb[i].z); s[6] = to_tf32(vb[i].w);
            }
            __syncthreads();
        }
    }

    // epilogue
    int g = lane >> 2, t = lane & 3;
    #pragma unroll
    for (int i2 = 0; i2 < 4; i2++) {
        int gm = m0 + (wm * 4 + i2) * 16 + g;
        #pragma unroll
        for (int j2 = 0; j2 < 4; j2++) {
            int gn = n0 + (wn * 4 + j2) * 8 + t * 2;
            if (gn < N) {
                float b0 = bias ? __ldg(bias + gn) : 0.f;
                float b1 = bias ? __ldg(bias + gn + 1) : 0.f;
                float2 v0, v1;
                v0.x = acc[i2][j2][0] * alpha + b0;
                v0.y = acc[i2][j2][1] * alpha + b1;
                v1.x = acc[i2][j2][2] * alpha + b0;
                v1.y = acc[i2][j2][3] * alpha + b1;
                *(float2*)&C[(long)gm * ldc + gn] = v0;
                *(float2*)&C[(long)(gm + 8) * ldc + gn] = v1;
            }
        }
    }
}

// ---------------- transposes ----------------
__global__ void transpose_kernel(const float* __restrict__ src, float* __restrict__ dst,
                                 int R, int Cc) {
    __shared__ float t[32][33];
    int c0 = blockIdx.x * 32, r0 = blockIdx.y * 32;
    int tx = threadIdx.x, ty = threadIdx.y;
    for (int i = ty; i < 32; i += 8) {
        int r = r0 + i, c = c0 + tx;
        if (r < R && c < Cc) t[i][tx] = src[(long)r * Cc + c];
    }
    __syncthreads();
    for (int i = ty; i < 32; i += 8) {
        int c = c0 + i, r = r0 + tx;
        if (c < Cc && r < R) dst[(long)c * R + r] = t[tx][i];
    }
}

// vt[(b*8+h)*96 + d][t] = qkv[(b*1024+t)*2304 + 1536 + h*96 + d]
__global__ void transpose_v_kernel(const float* __restrict__ qkv, float* __restrict__ vt) {
    int z = blockIdx.z; int b = z >> 3, h = z & 7;
    __shared__ float tb[32][33];
    int d0 = blockIdx.x * 32, t0 = blockIdx.y * 32;
    int tx = threadIdx.x, ty = threadIdx.y;
    const float* src = qkv + (long)b * 1024 * 2304 + 1536 + h * 96;
    for (int i = ty; i < 32; i += 8)
        tb[i][tx] = src[(long)(t0 + i) * 2304 + d0 + tx];
    __syncthreads();
    float* dst = vt + ((long)z * 96 + d0) * 1024 + t0;
    for (int j = ty; j < 32; j += 8)
        dst[(long)j * 1024 + tx] = tb[tx][j];
}

// ---------------- misc elementwise ----------------
__global__ void copy_kernel(const float* __restrict__ src, float* __restrict__ dst, long n) {
    long i = (long)blockIdx.x * blockDim.x + threadIdx.x;
    long stride = (long)gridDim.x * blockDim.x;
    for (; i < n; i += stride) dst[i] = src[i];
}
__global__ void zero_bytes_kernel(unsigned char* p, long n) {
    long i = (long)blockIdx.x * blockDim.x + threadIdx.x;
    long stride = (long)gridDim.x * blockDim.x;
    int* pi = (int*)p;
    long nw = n >> 2;
    for (; i < nw; i += stride) pi[i] = 0;
}

// ---------------- topk select (sim precomputed in fp32) ----------------
__global__ void topk_select_kernel(const float* __restrict__ sim, int* __restrict__ idx_out) {
    long r = blockIdx.x;
    const float* row = sim + r * SEQ;
    __shared__ float s[SEQ];
    __shared__ float bv[256];
    __shared__ int   bi[256];
    int tid = threadIdx.x;
    for (int i = tid; i < SEQ; i += 256) s[i] = row[i];
    __syncthreads();
    for (int sel = 0; sel < KNEIGH; sel++) {
        float v = -INFINITY; int mi = 0x7fffffff;
        for (int t = tid; t < SEQ; t += 256) {
            float sv = s[t];
            if (sv > v || (sv == v && t < mi)) { v = sv; mi = t; }
        }
        bv[tid] = v; bi[tid] = mi;
        __syncthreads();
        for (int o = 128; o > 0; o >>= 1) {
            if (tid < o) {
                if (bv[tid + o] > bv[tid] || (bv[tid + o] == bv[tid] && bi[tid + o] < bi[tid])) {
                    bv[tid] = bv[tid + o]; bi[tid] = bi[tid + o];
                }
            }
            __syncthreads();
        }
        if (tid == 0) { idx_out[r * KNEIGH + sel] = bi[0]; s[bi[0]] = -INFINITY; }
        __syncthreads();
    }
}

// ---------------- adjacency + degree ----------------
__global__ void scatter_adj_kernel(const int* __restrict__ idx, unsigned char* __restrict__ A) {
    int r = blockIdx.x * blockDim.x + threadIdx.x;
    if (r >= ROWS) return;
    int b = r >> 10, s = r & 1023;
    unsigned char* Ab = A + (long long)b * SEQ * SEQ;
    Ab[(long)s * SEQ + s] = 1;
    #pragma unroll
    for (int j = 0; j < KNEIGH; j++) {
        int t = idx[(long)r * KNEIGH + j];
        Ab[(long)s * SEQ + t] = 1;
        Ab[(long)t * SEQ + s] = 1;
    }
}
__global__ void degree_kernel(const unsigned char* __restrict__ A, float* __restrict__ dinv) {
    int r = blockIdx.x * blockDim.x + threadIdx.x;
    if (r >= ROWS) return;
    const uint32_t* row = (const uint32_t*)(A + (long long)r * SEQ);
    int d = 0;
    for (int i = 0; i < SEQ / 4; i++) {
        uint32_t w = row[i];
        d += (w & 0xff) + ((w >> 8) & 0xff) + ((w >> 16) & 0xff) + ((w >> 24) & 0xff);
    }
    dinv[r] = rsqrtf((float)d);
}

// ---------------- sparse GCN aggregate ----------------
__global__ void gcn_agg_kernel(const unsigned char* __restrict__ A, const float* __restrict__ dinv,
                               const float* __restrict__ xw, const float* __restrict__ gcn_b,
                               float* __restrict__ cat) {
    int r = blockIdx.x;
    int b = r >> 10;
    const unsigned char* Arow = A + (long long)r * SEQ;
    __shared__ int   nbr[SEQ];
    __shared__ float wgt[SEQ];
    __shared__ int cnt;
    int tid = threadIdx.x;
    if (tid == 0) cnt = 0;
    __syncthreads();
    for (int t = tid; t < SEQ; t += 256) {
        if (Arow[t]) {
            int p = atomicAdd(&cnt, 1);
            nbr[p] = t;
            wgt[p] = dinv[(b << 10) + t];
        }
    }
    __syncthreads();
    int n = cnt;
    float acc0 = 0.f, acc1 = 0.f, acc2 = 0.f;
    for (int i = 0; i < n; i++) {
        const float* row = xw + ((long)(b << 10) + nbr[i]) * DIM;
        float w = wgt[i];
        acc0 += w * row[tid];
        acc1 += w * row[tid + 256];
        acc2 += w * row[tid + 512];
    }
    float ws = dinv[r];
    long base = (long)r * (2 * DIM);
    cat[base + tid]       = ws * acc0 + gcn_b[tid];
    cat[base + tid + 256] = ws * acc1 + gcn_b[tid + 256];
    cat[base + tid + 512] = ws * acc2 + gcn_b[tid + 512];
}

// ---------------- SIMT fp32 GEMM (kept for exact sim = x x^T) ----------------
template<bool TRANS_B>
__global__ __launch_bounds__(256, 2)
void gemm_kernel(const float* __restrict__ A, long lda,
                 const float* __restrict__ B, long ldb,
                 float* __restrict__ C, long ldc,
                 int M, int N, int K,
                 const float* __restrict__ bias, float alpha,
                 int batchH,
                 long aOffB, long aOffH, long bOffB, long bOffH, long cOffB, long cOffH) {
    int z = blockIdx.z;
    int bb = z / batchH, hh = z % batchH;
    A += bb * aOffB + hh * aOffH;
    B += bb * bOffB + hh * bOffH;
    C += bb * cOffB + hh * cOffH;
    const int BM = 128, BN = 128, BK = 8;
    __shared__ float As[BK][BM];
    __shared__ float Bs[BK][BN];
    int tid = threadIdx.x;
    int tx = tid & 15, ty = tid >> 4;
    int m0 = blockIdx.y * BM, n0 = blockIdx.x * BN;
    float acc[8][8];
    #pragma unroll
    for (int i = 0; i < 8; i++)
        #pragma unroll
        for (int j = 0; j < 8; j++) acc[i][j] = 0.f;
    for (int k0 = 0; k0 < K; k0 += BK) {
        {
            int m  = tid >> 1;
            int kb = (tid & 1) * 4;
            int gm = m0 + m;
            #pragma unroll
            for (int i = 0; i < 4; i++) {
                int kk = kb + i, gk = k0 + kk;
                As[kk][m] = (gm < M && gk < K) ? A[(long)gm * lda + gk] : 0.f;
            }
        }
        if (!TRANS_B) {
            int kk = tid >> 5, nb = tid & 31, gk = k0 + kk;
            #pragma unroll
            for (int i = 0; i < 4; i++) {
                int n = nb + 32 * i, gn = n0 + n;
                Bs[kk][n] = (gk < K && gn < N) ? B[(long)gk * ldb + gn] : 0.f;
            }
        } else {
            int n = tid >> 1, kb = (tid & 1) * 4, gn = n0 + n;
            #pragma unroll
            for (int i = 0; i < 4; i++) {
                int kk = kb + i, gk = k0 + kk;
                Bs[kk][n] = (gn < N && gk < K) ? B[(long)gn * ldb + gk] : 0.f;
            }
        }
        __syncthreads();
        #pragma unroll
        for (int kk = 0; kk < BK; kk++) {
            float a[8], bvals[8];
            #pragma unroll
            for (int i = 0; i < 8; i++) a[i] = As[kk][ty * 8 + i];
            #pragma unroll
            for (int j = 0; j < 8; j++) bvals[j] = Bs[kk][tx * 8 + j];
            #pragma unroll
            for (int i = 0; i < 8; i++)
                #pragma unroll
                for (int j = 0; j < 8; j++) acc[i][j] += a[i] * bvals[j];
        }
        __syncthreads();
    }
    #pragma unroll
    for (int i = 0; i < 8; i++) {
        int gm = m0 + ty * 8 + i;
        if (gm >= M) continue;
        #pragma unroll
        for (int j = 0; j < 8; j++) {
            int gn = n0 + tx * 8 + j;
            if (gn >= N) continue;
            float v = acc[i][j] * alpha;
            if (bias) v += bias[gn];
            C[(long)gm * ldc + gn] = v;
        }
    }
}

// ---------------- softmax (FMA exp) ----------------
__global__ void softmax_kernel(float* __restrict__ scores) {
    long r = blockIdx.x;
    float* row = scores + r * SEQ;
    int tid = threadIdx.x;
    __shared__ float red[256];
    float v[4];
    float mx = -INFINITY;
    #pragma unroll
    for (int i = 0; i < 4; i++) { v[i] = row[tid + 256 * i]; mx = fmaxf(mx, v[i]); }
    red[tid] = mx; __syncthreads();
    #pragma unroll
    for (int o = 128; o > 0; o >>= 1) { if (tid < o) red[tid] = fmaxf(red[tid], red[tid + o]); __syncthreads(); }
    mx = red[0]; __syncthreads();
    float sum = 0.f;
    #pragma unroll
    for (int i = 0; i < 4; i++) { v[i] = fexp(v[i] - mx); sum += v[i]; }
    red[tid] = sum; __syncthreads();
    #pragma unroll
    for (int o = 128; o > 0; o >>= 1) { if (tid < o) red[tid] += red[tid + o]; __syncthreads(); }
    float inv = 1.f / red[0];
    #pragma unroll
    for (int i = 0; i < 4; i++) row[tid + 256 * i] = v[i] * inv;
}

// ---------------- gate + residual + layernorm ----------------
__global__ void fuse_ln_kernel(const float* __restrict__ gatelin, const float* __restrict__ cat,
                               float* __restrict__ h,
                               const float* __restrict__ ln_scale, const float* __restrict__ ln_bias) {
    long r = blockIdx.x;
    int tid = threadIdx.x;
    __shared__ float red[256];
    float f[3];
    #pragma unroll
    for (int i = 0; i < 3; i++) {
        int j = tid + 256 * i;
        float g  = gatelin[r * DIM + j];
        float gc = cat[r * (2 * DIM) + j];
        float at = cat[r * (2 * DIM) + DIM + j];
        float sg = 1.f / (1.f + fexp(-g));
        f[i] = sg * gc + (1.f - sg) * at + h[r * DIM + j];
    }
    float s1 = f[0] + f[1] + f[2];
    red[tid] = s1; __syncthreads();
    #pragma unroll
    for (int o = 128; o > 0; o >>= 1) { if (tid < o) red[tid] += red[tid + o]; __syncthreads(); }
    float mu = red[0] * (1.f / DIM);
    __syncthreads();
    float s2 = 0.f;
    #pragma unroll
    for (int i = 0; i < 3; i++) { float d = f[i] - mu; s2 += d * d; }
    red[tid] = s2; __syncthreads();
    #pragma unroll
    for (int o = 128; o > 0; o >>= 1) { if (tid < o) red[tid] += red[tid + o]; __syncthreads(); }
    float var = red[0] * (1.f / DIM);
    float inv = rsqrtf(var + LN_EPS);
    #pragma unroll
    for (int i = 0; i < 3; i++) {
        int j = tid + 256 * i;
        h[r * DIM + j] = (f[i] - mu) * inv * ln_scale[j] + ln_bias[j];
    }
}

// ---------------- host helper ----------------
#define MMA_SMEM 65536

static void launch_mma(const float* A, long lda, const float* Bt, long ldb,
                       float* C, long ldc, int M, int N, int K,
                       const float* bias, float alpha,
                       int Z = 1, int batchH = 1,
                       long aOffB = 0, long aOffH = 0, long bOffB = 0, long bOffH = 0,
                       long cOffB = 0, long cOffH = 0) {
    dim3 grid((N + 127) / 128, M / 128, Z);
    mma_gemm<<<grid, 256, MMA_SMEM>>>(A, lda, Bt, ldb, C, ldc, M, N, K, bias, alpha,
                                      batchH, aOffB, aOffH, bOffB, bOffH, cOffB, cOffH);
}

extern "C" void kernel_launch(void* const* d_in, const int* in_sizes, int n_in,
                              void* d_out, int out_size) {
    const float* x          = (const float*)d_in[0];
    const float* gcn_w      = (const float*)d_in[1];
    const float* gcn_b      = (const float*)d_in[2];
    const float* attn_in_w  = (const float*)d_in[3];
    const float* attn_in_b  = (const float*)d_in[4];
    const float* attn_out_w = (const float*)d_in[5];
    const float* attn_out_b = (const float*)d_in[6];
    const float* gate_w     = (const float*)d_in[7];
    const float* gate_b     = (const float*)d_in[8];
    const float* ln_scale   = (const float*)d_in[9];
    const float* ln_bias    = (const float*)d_in[10];
    const float* proj_w     = (const float*)d_in[11];
    const float* proj_b     = (const float*)d_in[12];
    float* out = (float*)d_out;

    static bool attr_done = false;
    if (!attr_done) {
        cudaFuncSetAttribute(mma_gemm, cudaFuncAttributeMaxDynamicSharedMemorySize, MMA_SMEM);
        attr_done = true;
    }

    float *p_h, *p_xw, *p_qkv, *p_scores, *p_ocat, *p_cat, *p_gate, *p_dinv, *p_wt, *p_vt;
    unsigned char* p_adj;
    int* p_topk;
    cudaGetSymbolAddress((void**)&p_h, g_h);
    cudaGetSymbolAddress((void**)&p_xw, g_xw);
    cudaGetSymbolAddress((void**)&p_qkv, g_qkv);
    cudaGetSymbolAddress((void**)&p_scores, g_scores);
    cudaGetSymbolAddress((void**)&p_ocat, g_ocat);
    cudaGetSymbolAddress((void**)&p_cat, g_cat);
    cudaGetSymbolAddress((void**)&p_gate, g_gate);
    cudaGetSymbolAddress((void**)&p_dinv, g_dinv);
    cudaGetSymbolAddress((void**)&p_adj, g_adj);
    cudaGetSymbolAddress((void**)&p_topk, g_topk);
    cudaGetSymbolAddress((void**)&p_wt, g_wt);
    cudaGetSymbolAddress((void**)&p_vt, g_vt);

    const float attn_scale = (float)(1.0 / sqrt((double)HDIM));
    dim3 tb(32, 8);

    // h = x
    copy_kernel<<<1024, 256>>>(x, p_h, (long)ROWS * DIM);

    // transpose all weights once: src [K,N] -> dst [N,K]
    for (int l = 0; l < NLAYERS; l++) {
        transpose_kernel<<<dim3(768 / 32, 768 / 32), tb>>>(gcn_w + (long)l * DIM * DIM, p_wt + WT_GCN(l), DIM, DIM);
        transpose_kernel<<<dim3(2304 / 32, 768 / 32), tb>>>(attn_in_w + (long)l * DIM * 3 * DIM, p_wt + WT_AIW(l), DIM, 3 * DIM);
        transpose_kernel<<<dim3(768 / 32, 768 / 32), tb>>>(attn_out_w + (long)l * DIM * DIM, p_wt + WT_AOW(l), DIM, DIM);
        transpose_kernel<<<dim3(768 / 32, 1536 / 32), tb>>>(gate_w + (long)l * 2 * DIM * DIM, p_wt + WT_GW(l), 2 * DIM, DIM);
    }
    transpose_kernel<<<dim3(768 / 32, 768 / 32), tb>>>(proj_w, p_wt + WT_PROJ, DIM, DIM);

    // sim = x x^T (exact fp32 SIMT), then top-5 select
    {
        dim3 grid(SEQ / 128, SEQ / 128, BATCH);
        gemm_kernel<true><<<grid, 256>>>(x, DIM, x, DIM, p_scores, SEQ,
                                         SEQ, SEQ, DIM, nullptr, 1.f,
                                         1, (long)SEQ * DIM, 0, (long)SEQ * DIM, 0,
                                         (long)SEQ * SEQ, 0);
    }
    topk_select_kernel<<<ROWS, 256>>>(p_scores, p_topk);
    zero_bytes_kernel<<<1024, 256>>>(p_adj, (long long)BATCH * SEQ * SEQ);
    scatter_adj_kernel<<<(ROWS + 255) / 256, 256>>>(p_topk, p_adj);
    degree_kernel<<<(ROWS + 255) / 256, 256>>>(p_adj, p_dinv);

    for (int l = 0; l < NLAYERS; l++) {
        const float* gb  = gcn_b + (long)l * DIM;
        const float* aib = attn_in_b + (long)l * 3 * DIM;
        const float* aob = attn_out_b + (long)l * DIM;
        const float* gtb = gate_b + (long)l * DIM;
        const float* lns = ln_scale + (long)l * DIM;
        const float* lnb = ln_bias + (long)l * DIM;

        // XW = h @ gcn_w[l]
        launch_mma(p_h, DIM, p_wt + WT_GCN(l), DIM, p_xw, DIM, ROWS, DIM, DIM, nullptr, 1.f);
        // gcn_out -> cat[:, 0:768]
        gcn_agg_kernel<<<ROWS, 256>>>(p_adj, p_dinv, p_xw, gb, p_cat);
        // qkv = h @ attn_in_w[l] + b
        launch_mma(p_h, DIM, p_wt + WT_AIW(l), DIM, p_qkv, 3 * DIM, ROWS, 3 * DIM, DIM, aib, 1.f);
        // V transpose: [64, 96, 1024]
        transpose_v_kernel<<<dim3(3, 32, 64), tb>>>(p_qkv, p_vt);
        // scores = Q K^T * scale
        launch_mma(p_qkv, 3 * DIM, p_qkv + DIM, 3 * DIM, p_scores, SEQ,
                   SEQ, SEQ, HDIM, nullptr, attn_scale,
                   BATCH * HEADS, HEADS,
                   (long)SEQ * 3 * DIM, HDIM,
                   (long)SEQ * 3 * DIM, HDIM,
                   (long)HEADS * SEQ * SEQ, (long)SEQ * SEQ);
        // softmax
        softmax_kernel<<<BATCH * HEADS * SEQ, 256>>>(p_scores);
        // O = P @ V : A = scores, Bt = vt [96,1024]
        launch_mma(p_scores, SEQ, p_vt, SEQ, p_ocat, DIM,
                   SEQ, HDIM, SEQ, nullptr, 1.f,
                   BATCH * HEADS, HEADS,
                   (long)HEADS * SEQ * SEQ, (long)SEQ * SEQ,
                   (long)HEADS * HDIM * SEQ, (long)HDIM * SEQ,
                   (long)SEQ * DIM, HDIM);
        // attn_out = O @ attn_out_w[l] + b -> cat[:, 768:1536]
        launch_mma(p_ocat, DIM, p_wt + WT_AOW(l), DIM, p_cat + DIM, 2 * DIM, ROWS, DIM, DIM, aob, 1.f);
        // gate_lin = cat @ gate_w[l] + b
        launch_mma(p_cat, 2 * DIM, p_wt + WT_GW(l), 2 * DIM, p_gate, DIM, ROWS, DIM, 2 * DIM, gtb, 1.f);
        // h = LN(gate*gcn + (1-gate)*attn + h)
        fuse_ln_kernel<<<ROWS, 256>>>(p_gate, p_cat, p_h, lns, lnb);
    }

    // out = h @ proj_w + proj_b
    launch_mma(p_h, DIM, p_wt + WT_PROJ, DIM, out, DIM, ROWS, DIM, DIM, proj_b, 1.f);
}

// round 5
// speedup vs baseline: 3.3902x; 1.3405x over previous
#include <cuda_runtime.h>
#include <math.h>
#include <stdint.h>

// ---------------- problem constants ----------------
#define BATCH 8
#define SEQ   1024
#define DIM   768
#define HEADS 8
#define HDIM  96
#define KNEIGH 5
#define NLAYERS 3
#define ROWS (BATCH*SEQ)  // 8192
#define LN_EPS 1e-5f

// ---------------- device scratch (static, allocation-free) ----------------
__device__ float g_h[ROWS * DIM];
__device__ float g_xw[ROWS * DIM];
__device__ float g_qkv[ROWS * 3 * DIM];
__device__ float g_scores[(long long)BATCH * HEADS * SEQ * SEQ]; // 256 MB
__device__ float g_ocat[ROWS * DIM];
__device__ float g_cat[ROWS * 2 * DIM];   // [gcn | attn] stride 1536
__device__ float g_gate[ROWS * DIM];
__device__ unsigned char g_adj[(long long)BATCH * SEQ * SEQ];    // 8 MB
__device__ float g_dinv[ROWS];
__device__ int   g_topk[ROWS * KNEIGH];
__device__ float g_wt[12976128];          // transposed weights (52 MB)
__device__ float g_vt[ROWS * DIM];        // V transposed per (b,h): [64, 96, 1024]

// transposed weight offsets
#define WT_GCN(l)  ((long)(l) * 589824)
#define WT_AIW(l)  (1769472L + (long)(l) * 1769472L)
#define WT_AOW(l)  (7077888L + (long)(l) * 589824L)
#define WT_GW(l)   (8847360L + (long)(l) * 1179648L)
#define WT_PROJ    (12386304L)

// pack two floats to half2 (lo = a, hi = b)
__device__ __forceinline__ uint32_t pack_h2(float a, float b) {
    uint32_t r;
    asm("cvt.rn.f16x2.f32 %0, %2, %1;" : "=r"(r) : "f"(a), "f"(b));
    return r;
}

// FMA-only exp (no MUFU)
__device__ __forceinline__ float fexp(float x) {
    x = fmaxf(x, -87.0f);
    float y = x * 1.4426950408889634f;
    int i = __float2int_rn(y);
    float r = (y - (float)i) * 0.6931471805599453f;
    float p = 1.9841270e-4f;
    p = fmaf(p, r, 1.3888889e-3f);
    p = fmaf(p, r, 8.3333333e-3f);
    p = fmaf(p, r, 4.1666667e-2f);
    p = fmaf(p, r, 1.6666667e-1f);
    p = fmaf(p, r, 0.5f);
    p = fmaf(p, r, 1.0f);
    p = fmaf(p, r, 1.0f);
    return p * __int_as_float((i + 127) << 23);
}

#define MMAF16(d, a, b) \
    asm volatile("mma.sync.aligned.m16n8k16.row.col.f32.f16.f16.f32 " \
        "{%0,%1,%2,%3}, {%4,%5,%6,%7}, {%8,%9}, {%0,%1,%2,%3};" \
        : "+f"((d)[0]), "+f"((d)[1]), "+f"((d)[2]), "+f"((d)[3]) \
        : "r"((a).x), "r"((a).y), "r"((a).z), "r"((a).w), \
          "r"((b).x), "r"((b).y))

// ---------------- mma.sync fp16 GEMM ----------------
// C = alpha * A[M,K] @ Bt[N,K]^T + bias. Block tile 128x128, warp tile 64x32,
// BK = 32 (2 k16-frags), double-buffered fragment-packed SMEM (32 KB), 256 thr.
// m16n8k16 fragment mapping (PTX ISA):
//   A regs a0..a3 = {row<8,row>=8} x {k<8,k>=8}; elem(row,k): lane=(row&7)*4+((k>>1)&3),
//   half2 lo = even k.  B regs b0/b1 = k<8 / k>=8; elem(n,k): lane=(n&7)*4+((k>>1)&3).
__global__ __launch_bounds__(256, 1)
void mma_gemm(const float* __restrict__ A, long lda,
              const float* __restrict__ Bt, long ldb,
              float* __restrict__ C, long ldc,
              int M, int N, int K,
              const float* __restrict__ bias, float alpha,
              int batchH,
              long aOffB, long aOffH, long bOffB, long bOffH,
              long cOffB, long cOffH) {
    extern __shared__ uint32_t dsm[];
    // sA buffers: dsm + buf*2048 ; sB buffers: dsm + 4096 + buf*2048

    int z = blockIdx.z;
    int bb = z / batchH, hh = z % batchH;
    A  += bb * aOffB + hh * aOffH;
    Bt += bb * bOffB + hh * bOffH;
    C  += bb * cOffB + hh * cOffH;
    int m0 = blockIdx.y * 128, n0 = blockIdx.x * 128;
    int tid = threadIdx.x, lane = tid & 31, wid = tid >> 5;
    int wm = wid & 1, wn = wid >> 1;   // warp grid 2(m) x 4(n), warp tile 64x32

    const float* Ab = A + (long)m0 * lda;

    // loader index precompute (fp16 fragment-packed layout)
    int aR[4], aQ[4], aBase[4], aOff[4];
    #pragma unroll
    for (int i = 0; i < 4; i++) {
        int idx = tid + 256 * i;
        int r = idx >> 3, q = idx & 7;
        aR[i] = r; aQ[i] = q;
        int im = r >> 4, g = r & 7, row8 = (r >> 3) & 1;
        int ikf = q >> 2, k8 = (q >> 1) & 1;
        aBase[i] = ((im * 2 + ikf) * 32 + g * 4) * 4 + k8 * 2 + row8;
        aOff[i] = 8 * (q & 1);
    }
    int bR[4], bQ[4], bBase[4], bOff[4];
    #pragma unroll
    for (int i = 0; i < 4; i++) {
        int idx = tid + 256 * i;
        int r = idx >> 3, q = idx & 7;
        bR[i] = r; bQ[i] = q;
        int in = r >> 3, nn = r & 7;
        int ikf = q >> 2, k8 = (q >> 1) & 1;
        bBase[i] = ((in * 2 + ikf) * 32 + nn * 4) * 2 + k8;
        bOff[i] = 4 * (q & 1);
    }

    float acc[4][4][4];
    #pragma unroll
    for (int i = 0; i < 4; i++)
        #pragma unroll
        for (int j = 0; j < 4; j++)
            #pragma unroll
            for (int c = 0; c < 4; c++) acc[i][j][c] = 0.f;

    int nch = K >> 5;
    float4 va[4], vb[4];

    // prologue: load chunk 0, store to buf 0
    #pragma unroll
    for (int i = 0; i < 4; i++)
        va[i] = *(const float4*)(Ab + (long)aR[i] * lda + aQ[i] * 4);
    #pragma unroll
    for (int i = 0; i < 4; i++) {
        int gn = n0 + bR[i];
        vb[i] = (gn < N) ? *(const float4*)(Bt + (long)gn * ldb + bQ[i] * 4)
                         : make_float4(0.f, 0.f, 0.f, 0.f);
    }
    {
        uint32_t* sA0 = dsm;
        uint32_t* sB0 = dsm + 4096;
        #pragma unroll
        for (int i = 0; i < 4; i++) {
            uint32_t* s = &sA0[aBase[i] + aOff[i]];
            s[0] = pack_h2(va[i].x, va[i].y);
            s[4] = pack_h2(va[i].z, va[i].w);
        }
        #pragma unroll
        for (int i = 0; i < 4; i++) {
            uint32_t* s = &sB0[bBase[i] + bOff[i]];
            s[0] = pack_h2(vb[i].x, vb[i].y);
            s[2] = pack_h2(vb[i].z, vb[i].w);
        }
    }
    __syncthreads();

    for (int it = 0; it < nch; it++) {
        int buf = it & 1;
        bool more = (it + 1 < nch);
        if (more) {
            long koff = (long)(it + 1) * 32;
            #pragma unroll
            for (int i = 0; i < 4; i++)
                va[i] = *(const float4*)(Ab + (long)aR[i] * lda + koff + aQ[i] * 4);
            #pragma unroll
            for (int i = 0; i < 4; i++) {
                int gn = n0 + bR[i];
                vb[i] = (gn < N) ? *(const float4*)(Bt + (long)gn * ldb + koff + bQ[i] * 4)
                                 : make_float4(0.f, 0.f, 0.f, 0.f);
            }
        }
        // compute on buf
        const uint32_t* sAb = dsm + buf * 2048;
        const uint32_t* sBb = dsm + 4096 + buf * 2048;
        #pragma unroll
        for (int ikf = 0; ikf < 2; ikf++) {
            uint4 af[4];
            uint2 bf[4];
            #pragma unroll
            for (int i2 = 0; i2 < 4; i2++)
                af[i2] = *(const uint4*)&sAb[(((wm * 4 + i2) * 2 + ikf) * 32 + lane) * 4];
            #pragma unroll
            for (int j2 = 0; j2 < 4; j2++)
                bf[j2] = *(const uint2*)&sBb[(((wn * 4 + j2) * 2 + ikf) * 32 + lane) * 2];
            #pragma unroll
            for (int i2 = 0; i2 < 4; i2++)
                #pragma unroll
                for (int j2 = 0; j2 < 4; j2++)
                    MMAF16(acc[i2][j2], af[i2], bf[j2]);
        }
        __syncthreads();
        if (more) {
            uint32_t* sAn = dsm + (buf ^ 1) * 2048;
            uint32_t* sBn = dsm + 4096 + (buf ^ 1) * 2048;
            #pragma unroll
            for (int i = 0; i < 4; i++) {
                uint32_t* s = &sAn[aBase[i] + aOff[i]];
                s[0] = pack_h2(va[i].x, va[i].y);
                s[4] = pack_h2(va[i].z, va[i].w);
            }
            #pragma unroll
            for (int i = 0; i < 4; i++) {
                uint32_t* s = &sBn[bBase[i] + bOff[i]];
                s[0] = pack_h2(vb[i].x, vb[i].y);
                s[2] = pack_h2(vb[i].z, vb[i].w);
            }
            __syncthreads();
        }
    }

    // epilogue
    int g = lane >> 2, t = lane & 3;
    #pragma unroll
    for (int i2 = 0; i2 < 4; i2++) {
        int gm = m0 + (wm * 4 + i2) * 16 + g;
        #pragma unroll
        for (int j2 = 0; j2 < 4; j2++) {
            int gn = n0 + (wn * 4 + j2) * 8 + t * 2;
            if (gn < N) {
                float b0 = bias ? __ldg(bias + gn) : 0.f;
                float b1 = bias ? __ldg(bias + gn + 1) : 0.f;
                float2 v0, v1;
                v0.x = acc[i2][j2][0] * alpha + b0;
                v0.y = acc[i2][j2][1] * alpha + b1;
                v1.x = acc[i2][j2][2] * alpha + b0;
                v1.y = acc[i2][j2][3] * alpha + b1;
                *(float2*)&C[(long)gm * ldc + gn] = v0;
                *(float2*)&C[(long)(gm + 8) * ldc + gn] = v1;
            }
        }
    }
}

// ---------------- transposes ----------------
__global__ void transpose_kernel(const float* __restrict__ src, float* __restrict__ dst,
                                 int R, int Cc) {
    __shared__ float t[32][33];
    int c0 = blockIdx.x * 32, r0 = blockIdx.y * 32;
    int tx = threadIdx.x, ty = threadIdx.y;
    for (int i = ty; i < 32; i += 8) {
        int r = r0 + i, c = c0 + tx;
        if (r < R && c < Cc) t[i][tx] = src[(long)r * Cc + c];
    }
    __syncthreads();
    for (int i = ty; i < 32; i += 8) {
        int c = c0 + i, r = r0 + tx;
        if (c < Cc && r < R) dst[(long)c * R + r] = t[tx][i];
    }
}

// vt[(b*8+h)*96 + d][t] = qkv[(b*1024+t)*2304 + 1536 + h*96 + d]
__global__ void transpose_v_kernel(const float* __restrict__ qkv, float* __restrict__ vt) {
    int z = blockIdx.z; int b = z >> 3, h = z & 7;
    __shared__ float tb[32][33];
    int d0 = blockIdx.x * 32, t0 = blockIdx.y * 32;
    int tx = threadIdx.x, ty = threadIdx.y;
    const float* src = qkv + (long)b * 1024 * 2304 + 1536 + h * 96;
    for (int i = ty; i < 32; i += 8)
        tb[i][tx] = src[(long)(t0 + i) * 2304 + d0 + tx];
    __syncthreads();
    float* dst = vt + ((long)z * 96 + d0) * 1024 + t0;
    for (int j = ty; j < 32; j += 8)
        dst[(long)j * 1024 + tx] = tb[tx][j];
}

// ---------------- misc elementwise ----------------
__global__ void copy_kernel(const float* __restrict__ src, float* __restrict__ dst, long n) {
    long i = (long)blockIdx.x * blockDim.x + threadIdx.x;
    long stride = (long)gridDim.x * blockDim.x;
    for (; i < n; i += stride) dst[i] = src[i];
}
__global__ void zero_bytes_kernel(unsigned char* p, long n) {
    long i = (long)blockIdx.x * blockDim.x + threadIdx.x;
    long stride = (long)gridDim.x * blockDim.x;
    int* pi = (int*)p;
    long nw = n >> 2;
    for (; i < nw; i += stride) pi[i] = 0;
}

// ---------------- topk select (sim precomputed in fp32) ----------------
__global__ void topk_select_kernel(const float* __restrict__ sim, int* __restrict__ idx_out) {
    long r = blockIdx.x;
    const float* row = sim + r * SEQ;
    __shared__ float s[SEQ];
    __shared__ float bv[256];
    __shared__ int   bi[256];
    int tid = threadIdx.x;
    for (int i = tid; i < SEQ; i += 256) s[i] = row[i];
    __syncthreads();
    for (int sel = 0; sel < KNEIGH; sel++) {
        float v = -INFINITY; int mi = 0x7fffffff;
        for (int t = tid; t < SEQ; t += 256) {
            float sv = s[t];
            if (sv > v || (sv == v && t < mi)) { v = sv; mi = t; }
        }
        bv[tid] = v; bi[tid] = mi;
        __syncthreads();
        for (int o = 128; o > 0; o >>= 1) {
            if (tid < o) {
                if (bv[tid + o] > bv[tid] || (bv[tid + o] == bv[tid] && bi[tid + o] < bi[tid])) {
                    bv[tid] = bv[tid + o]; bi[tid] = bi[tid + o];
                }
            }
            __syncthreads();
        }
        if (tid == 0) { idx_out[r * KNEIGH + sel] = bi[0]; s[bi[0]] = -INFINITY; }
        __syncthreads();
    }
}

// ---------------- adjacency + degree ----------------
__global__ void scatter_adj_kernel(const int* __restrict__ idx, unsigned char* __restrict__ A) {
    int r = blockIdx.x * blockDim.x + threadIdx.x;
    if (r >= ROWS) return;
    int b = r >> 10, s = r & 1023;
    unsigned char* Ab = A + (long long)b * SEQ * SEQ;
    Ab[(long)s * SEQ + s] = 1;
    #pragma unroll
    for (int j = 0; j < KNEIGH; j++) {
        int t = idx[(long)r * KNEIGH + j];
        Ab[(long)s * SEQ + t] = 1;
        Ab[(long)t * SEQ + s] = 1;
    }
}
__global__ void degree_kernel(const unsigned char* __restrict__ A, float* __restrict__ dinv) {
    int r = blockIdx.x * blockDim.x + threadIdx.x;
    if (r >= ROWS) return;
    const uint32_t* row = (const uint32_t*)(A + (long long)r * SEQ);
    int d = 0;
    for (int i = 0; i < SEQ / 4; i++) {
        uint32_t w = row[i];
        d += (w & 0xff) + ((w >> 8) & 0xff) + ((w >> 16) & 0xff) + ((w >> 24) & 0xff);
    }
    dinv[r] = rsqrtf((float)d);
}

// ---------------- sparse GCN aggregate ----------------
__global__ void gcn_agg_kernel(const unsigned char* __restrict__ A, const float* __restrict__ dinv,
                               const float* __restrict__ xw, const float* __restrict__ gcn_b,
                               float* __restrict__ cat) {
    int r = blockIdx.x;
    int b = r >> 10;
    const unsigned char* Arow = A + (long long)r * SEQ;
    __shared__ int   nbr[SEQ];
    __shared__ float wgt[SEQ];
    __shared__ int cnt;
    int tid = threadIdx.x;
    if (tid == 0) cnt = 0;
    __syncthreads();
    for (int t = tid; t < SEQ; t += 256) {
        if (Arow[t]) {
            int p = atomicAdd(&cnt, 1);
            nbr[p] = t;
            wgt[p] = dinv[(b << 10) + t];
        }
    }
    __syncthreads();
    int n = cnt;
    float acc0 = 0.f, acc1 = 0.f, acc2 = 0.f;
    for (int i = 0; i < n; i++) {
        const float* row = xw + ((long)(b << 10) + nbr[i]) * DIM;
        float w = wgt[i];
        acc0 += w * row[tid];
        acc1 += w * row[tid + 256];
        acc2 += w * row[tid + 512];
    }
    float ws = dinv[r];
    long base = (long)r * (2 * DIM);
    cat[base + tid]       = ws * acc0 + gcn_b[tid];
    cat[base + tid + 256] = ws * acc1 + gcn_b[tid + 256];
    cat[base + tid + 512] = ws * acc2 + gcn_b[tid + 512];
}

// ---------------- SIMT fp32 GEMM (kept for exact sim = x x^T) ----------------
template<bool TRANS_B>
__global__ __launch_bounds__(256, 2)
void gemm_kernel(const float* __restrict__ A, long lda,
                 const float* __restrict__ B, long ldb,
                 float* __restrict__ C, long ldc,
                 int M, int N, int K,
                 const float* __restrict__ bias, float alpha,
                 int batchH,
                 long aOffB, long aOffH, long bOffB, long bOffH, long cOffB, long cOffH) {
    int z = blockIdx.z;
    int bb = z / batchH, hh = z % batchH;
    A += bb * aOffB + hh * aOffH;
    B += bb * bOffB + hh * bOffH;
    C += bb * cOffB + hh * cOffH;
    const int BM = 128, BN = 128, BK = 8;
    __shared__ float As[BK][BM];
    __shared__ float Bs[BK][BN];
    int tid = threadIdx.x;
    int tx = tid & 15, ty = tid >> 4;
    int m0 = blockIdx.y * BM, n0 = blockIdx.x * BN;
    float acc[8][8];
    #pragma unroll
    for (int i = 0; i < 8; i++)
        #pragma unroll
        for (int j = 0; j < 8; j++) acc[i][j] = 0.f;
    for (int k0 = 0; k0 < K; k0 += BK) {
        {
            int m  = tid >> 1;
            int kb = (tid & 1) * 4;
            int gm = m0 + m;
            #pragma unroll
            for (int i = 0; i < 4; i++) {
                int kk = kb + i, gk = k0 + kk;
                As[kk][m] = (gm < M && gk < K) ? A[(long)gm * lda + gk] : 0.f;
            }
        }
        if (!TRANS_B) {
            int kk = tid >> 5, nb = tid & 31, gk = k0 + kk;
            #pragma unroll
            for (int i = 0; i < 4; i++) {
                int n = nb + 32 * i, gn = n0 + n;
                Bs[kk][n] = (gk < K && gn < N) ? B[(long)gk * ldb + gn] : 0.f;
            }
        } else {
            int n = tid >> 1, kb = (tid & 1) * 4, gn = n0 + n;
            #pragma unroll
            for (int i = 0; i < 4; i++) {
                int kk = kb + i, gk = k0 + kk;
                Bs[kk][n] = (gn < N && gk < K) ? B[(long)gn * ldb + gk] : 0.f;
            }
        }
        __syncthreads();
        #pragma unroll
        for (int kk = 0; kk < BK; kk++) {
            float a[8], bvals[8];
            #pragma unroll
            for (int i = 0; i < 8; i++) a[i] = As[kk][ty * 8 + i];
            #pragma unroll
            for (int j = 0; j < 8; j++) bvals[j] = Bs[kk][tx * 8 + j];
            #pragma unroll
            for (int i = 0; i < 8; i++)
                #pragma unroll
                for (int j = 0; j < 8; j++) acc[i][j] += a[i] * bvals[j];
        }
        __syncthreads();
    }
    #pragma unroll
    for (int i = 0; i < 8; i++) {
        int gm = m0 + ty * 8 + i;
        if (gm >= M) continue;
        #pragma unroll
        for (int j = 0; j < 8; j++) {
            int gn = n0 + tx * 8 + j;
            if (gn >= N) continue;
            float v = acc[i][j] * alpha;
            if (bias) v += bias[gn];
            C[(long)gm * ldc + gn] = v;
        }
    }
}

// ---------------- softmax (FMA exp) ----------------
__global__ void softmax_kernel(float* __restrict__ scores) {
    long r = blockIdx.x;
    float* row = scores + r * SEQ;
    int tid = threadIdx.x;
    __shared__ float red[256];
    float v[4];
    float mx = -INFINITY;
    #pragma unroll
    for (int i = 0; i < 4; i++) { v[i] = row[tid + 256 * i]; mx = fmaxf(mx, v[i]); }
    red[tid] = mx; __syncthreads();
    #pragma unroll
    for (int o = 128; o > 0; o >>= 1) { if (tid < o) red[tid] = fmaxf(red[tid], red[tid + o]); __syncthreads(); }
    mx = red[0]; __syncthreads();
    float sum = 0.f;
    #pragma unroll
    for (int i = 0; i < 4; i++) { v[i] = fexp(v[i] - mx); sum += v[i]; }
    red[tid] = sum; __syncthreads();
    #pragma unroll
    for (int o = 128; o > 0; o >>= 1) { if (tid < o) red[tid] += red[tid + o]; __syncthreads(); }
    float inv = 1.f / red[0];
    #pragma unroll
    for (int i = 0; i < 4; i++) row[tid + 256 * i] = v[i] * inv;
}

// ---------------- gate + residual + layernorm ----------------
__global__ void fuse_ln_kernel(const float* __restrict__ gatelin, const float* __restrict__ cat,
                               float* __restrict__ h,
                               const float* __restrict__ ln_scale, const float* __restrict__ ln_bias) {
    long r = blockIdx.x;
    int tid = threadIdx.x;
    __shared__ float red[256];
    float f[3];
    #pragma unroll
    for (int i = 0; i < 3; i++) {
        int j = tid + 256 * i;
        float g  = gatelin[r * DIM + j];
        float gc = cat[r * (2 * DIM) + j];
        float at = cat[r * (2 * DIM) + DIM + j];
        float sg = 1.f / (1.f + fexp(-g));
        f[i] = sg * gc + (1.f - sg) * at + h[r * DIM + j];
    }
    float s1 = f[0] + f[1] + f[2];
    red[tid] = s1; __syncthreads();
    #pragma unroll
    for (int o = 128; o > 0; o >>= 1) { if (tid < o) red[tid] += red[tid + o]; __syncthreads(); }
    float mu = red[0] * (1.f / DIM);
    __syncthreads();
    float s2 = 0.f;
    #pragma unroll
    for (int i = 0; i < 3; i++) { float d = f[i] - mu; s2 += d * d; }
    red[tid] = s2; __syncthreads();
    #pragma unroll
    for (int o = 128; o > 0; o >>= 1) { if (tid < o) red[tid] += red[tid + o]; __syncthreads(); }
    float var = red[0] * (1.f / DIM);
    float inv = rsqrtf(var + LN_EPS);
    #pragma unroll
    for (int i = 0; i < 3; i++) {
        int j = tid + 256 * i;
        h[r * DIM + j] = (f[i] - mu) * inv * ln_scale[j] + ln_bias[j];
    }
}

// ---------------- host helper ----------------
#define MMA_SMEM 32768

static void launch_mma(const float* A, long lda, const float* Bt, long ldb,
                       float* C, long ldc, int M, int N, int K,
                       const float* bias, float alpha,
                       int Z = 1, int batchH = 1,
                       long aOffB = 0, long aOffH = 0, long bOffB = 0, long bOffH = 0,
                       long cOffB = 0, long cOffH = 0) {
    dim3 grid((N + 127) / 128, M / 128, Z);
    mma_gemm<<<grid, 256, MMA_SMEM>>>(A, lda, Bt, ldb, C, ldc, M, N, K, bias, alpha,
                                      batchH, aOffB, aOffH, bOffB, bOffH, cOffB, cOffH);
}

extern "C" void kernel_launch(void* const* d_in, const int* in_sizes, int n_in,
                              void* d_out, int out_size) {
    const float* x          = (const float*)d_in[0];
    const float* gcn_w      = (const float*)d_in[1];
    const float* gcn_b      = (const float*)d_in[2];
    const float* attn_in_w  = (const float*)d_in[3];
    const float* attn_in_b  = (const float*)d_in[4];
    const float* attn_out_w = (const float*)d_in[5];
    const float* attn_out_b = (const float*)d_in[6];
    const float* gate_w     = (const float*)d_in[7];
    const float* gate_b     = (const float*)d_in[8];
    const float* ln_scale   = (const float*)d_in[9];
    const float* ln_bias    = (const float*)d_in[10];
    const float* proj_w     = (const float*)d_in[11];
    const float* proj_b     = (const float*)d_in[12];
    float* out = (float*)d_out;

    static bool attr_done = false;
    if (!attr_done) {
        cudaFuncSetAttribute(mma_gemm, cudaFuncAttributeMaxDynamicSharedMemorySize, MMA_SMEM);
        attr_done = true;
    }

    float *p_h, *p_xw, *p_qkv, *p_scores, *p_ocat, *p_cat, *p_gate, *p_dinv, *p_wt, *p_vt;
    unsigned char* p_adj;
    int* p_topk;
    cudaGetSymbolAddress((void**)&p_h, g_h);
    cudaGetSymbolAddress((void**)&p_xw, g_xw);
    cudaGetSymbolAddress((void**)&p_qkv, g_qkv);
    cudaGetSymbolAddress((void**)&p_scores, g_scores);
    cudaGetSymbolAddress((void**)&p_ocat, g_ocat);
    cudaGetSymbolAddress((void**)&p_cat, g_cat);
    cudaGetSymbolAddress((void**)&p_gate, g_gate);
    cudaGetSymbolAddress((void**)&p_dinv, g_dinv);
    cudaGetSymbolAddress((void**)&p_adj, g_adj);
    cudaGetSymbolAddress((void**)&p_topk, g_topk);
    cudaGetSymbolAddress((void**)&p_wt, g_wt);
    cudaGetSymbolAddress((void**)&p_vt, g_vt);

    const float attn_scale = (float)(1.0 / sqrt((double)HDIM));
    dim3 tb(32, 8);

    // h = x
    copy_kernel<<<1024, 256>>>(x, p_h, (long)ROWS * DIM);

    // transpose all weights once: src [K,N] -> dst [N,K]
    for (int l = 0; l < NLAYERS; l++) {
        transpose_kernel<<<dim3(768 / 32, 768 / 32), tb>>>(gcn_w + (long)l * DIM * DIM, p_wt + WT_GCN(l), DIM, DIM);
        transpose_kernel<<<dim3(2304 / 32, 768 / 32), tb>>>(attn_in_w + (long)l * DIM * 3 * DIM, p_wt + WT_AIW(l), DIM, 3 * DIM);
        transpose_kernel<<<dim3(768 / 32, 768 / 32), tb>>>(attn_out_w + (long)l * DIM * DIM, p_wt + WT_AOW(l), DIM, DIM);
        transpose_kernel<<<dim3(768 / 32, 1536 / 32), tb>>>(gate_w + (long)l * 2 * DIM * DIM, p_wt + WT_GW(l), 2 * DIM, DIM);
    }
    transpose_kernel<<<dim3(768 / 32, 768 / 32), tb>>>(proj_w, p_wt + WT_PROJ, DIM, DIM);

    // sim = x x^T (exact fp32 SIMT), then top-5 select
    {
        dim3 grid(SEQ / 128, SEQ / 128, BATCH);
        gemm_kernel<true><<<grid, 256>>>(x, DIM, x, DIM, p_scores, SEQ,
                                         SEQ, SEQ, DIM, nullptr, 1.f,
                                         1, (long)SEQ * DIM, 0, (long)SEQ * DIM, 0,
                                         (long)SEQ * SEQ, 0);
    }
    topk_select_kernel<<<ROWS, 256>>>(p_scores, p_topk);
    zero_bytes_kernel<<<1024, 256>>>(p_adj, (long long)BATCH * SEQ * SEQ);
    scatter_adj_kernel<<<(ROWS + 255) / 256, 256>>>(p_topk, p_adj);
    degree_kernel<<<(ROWS + 255) / 256, 256>>>(p_adj, p_dinv);

    for (int l = 0; l < NLAYERS; l++) {
        const float* gb  = gcn_b + (long)l * DIM;
        const float* aib = attn_in_b + (long)l * 3 * DIM;
        const float* aob = attn_out_b + (long)l * DIM;
        const float* gtb = gate_b + (long)l * DIM;
        const float* lns = ln_scale + (long)l * DIM;
        const float* lnb = ln_bias + (long)l * DIM;

        // XW = h @ gcn_w[l]
        launch_mma(p_h, DIM, p_wt + WT_GCN(l), DIM, p_xw, DIM, ROWS, DIM, DIM, nullptr, 1.f);
        // gcn_out -> cat[:, 0:768]
        gcn_agg_kernel<<<ROWS, 256>>>(p_adj, p_dinv, p_xw, gb, p_cat);
        // qkv = h @ attn_in_w[l] + b
        launch_mma(p_h, DIM, p_wt + WT_AIW(l), DIM, p_qkv, 3 * DIM, ROWS, 3 * DIM, DIM, aib, 1.f);
        // V transpose: [64, 96, 1024]
        transpose_v_kernel<<<dim3(3, 32, 64), tb>>>(p_qkv, p_vt);
        // scores = Q K^T * scale
        launch_mma(p_qkv, 3 * DIM, p_qkv + DIM, 3 * DIM, p_scores, SEQ,
                   SEQ, SEQ, HDIM, nullptr, attn_scale,
                   BATCH * HEADS, HEADS,
                   (long)SEQ * 3 * DIM, HDIM,
                   (long)SEQ * 3 * DIM, HDIM,
                   (long)HEADS * SEQ * SEQ, (long)SEQ * SEQ);
        // softmax
        softmax_kernel<<<BATCH * HEADS * SEQ, 256>>>(p_scores);
        // O = P @ V : A = scores, Bt = vt [96,1024]
        launch_mma(p_scores, SEQ, p_vt, SEQ, p_ocat, DIM,
                   SEQ, HDIM, SEQ, nullptr, 1.f,
                   BATCH * HEADS, HEADS,
                   (long)HEADS * SEQ * SEQ, (long)SEQ * SEQ,
                   (long)HEADS * HDIM * SEQ, (long)HDIM * SEQ,
                   (long)SEQ * DIM, HDIM);
        // attn_out = O @ attn_out_w[l] + b -> cat[:, 768:1536]
        launch_mma(p_ocat, DIM, p_wt + WT_AOW(l), DIM, p_cat + DIM, 2 * DIM, ROWS, DIM, DIM, aob, 1.f);
        // gate_lin = cat @ gate_w[l] + b
        launch_mma(p_cat, 2 * DIM, p_wt + WT_GW(l), 2 * DIM, p_gate, DIM, ROWS, DIM, 2 * DIM, gtb, 1.f);
        // h = LN(gate*gcn + (1-gate)*attn + h)
        fuse_ln_kernel<<<ROWS, 256>>>(p_gate, p_cat, p_h, lns, lnb);
    }

    // out = h @ proj_w + proj_b
    launch_mma(p_h, DIM, p_wt + WT_PROJ, DIM, out, DIM, ROWS, DIM, DIM, proj_b, 1.f);
}

// round 6
// speedup vs baseline: 4.2631x; 1.2575x over previous
#include <cuda_runtime.h>
#include <math.h>
#include <stdint.h>

// ---------------- problem constants ----------------
#define BATCH 8
#define SEQ   1024
#define DIM   768
#define HEADS 8
#define HDIM  96
#define KNEIGH 5
#define NLAYERS 3
#define ROWS (BATCH*SEQ)  // 8192
#define LN_EPS 1e-5f

// ---------------- device scratch (static, allocation-free) ----------------
__device__ float g_h[ROWS * DIM];
__device__ float g_xw[ROWS * DIM];
__device__ float g_qkv[ROWS * 3 * DIM];
__device__ float g_scores[(long long)BATCH * SEQ * SEQ]; // sim workspace (32 MB)
__device__ float g_ocat[ROWS * DIM];
__device__ float g_cat[ROWS * 2 * DIM];   // [gcn | attn] stride 1536
__device__ float g_gate[ROWS * DIM];
__device__ unsigned char g_adj[(long long)BATCH * SEQ * SEQ];    // 8 MB
__device__ float g_dinv[ROWS];
__device__ int   g_topk[ROWS * KNEIGH];
__device__ float g_wt[12976128];          // transposed weights (52 MB)
__device__ float g_vt[ROWS * DIM];        // V transposed per (b,h): [64, 96, 1024]

// transposed weight offsets
#define WT_GCN(l)  ((long)(l) * 589824)
#define WT_AIW(l)  (1769472L + (long)(l) * 1769472L)
#define WT_AOW(l)  (7077888L + (long)(l) * 589824L)
#define WT_GW(l)   (8847360L + (long)(l) * 1179648L)
#define WT_PROJ    (12386304L)

// pack two floats to half2 (lo = a, hi = b)
__device__ __forceinline__ uint32_t pack_h2(float a, float b) {
    uint32_t r;
    asm("cvt.rn.f16x2.f32 %0, %2, %1;" : "=r"(r) : "f"(a), "f"(b));
    return r;
}

// FMA-only exp (no MUFU)
__device__ __forceinline__ float fexp(float x) {
    x = fmaxf(x, -87.0f);
    float y = x * 1.4426950408889634f;
    int i = __float2int_rn(y);
    float r = (y - (float)i) * 0.6931471805599453f;
    float p = 1.9841270e-4f;
    p = fmaf(p, r, 1.3888889e-3f);
    p = fmaf(p, r, 8.3333333e-3f);
    p = fmaf(p, r, 4.1666667e-2f);
    p = fmaf(p, r, 1.6666667e-1f);
    p = fmaf(p, r, 0.5f);
    p = fmaf(p, r, 1.0f);
    p = fmaf(p, r, 1.0f);
    return p * __int_as_float((i + 127) << 23);
}

#define MMAF16(d, a, b) \
    asm volatile("mma.sync.aligned.m16n8k16.row.col.f32.f16.f16.f32 " \
        "{%0,%1,%2,%3}, {%4,%5,%6,%7}, {%8,%9}, {%0,%1,%2,%3};" \
        : "+f"((d)[0]), "+f"((d)[1]), "+f"((d)[2]), "+f"((d)[3]) \
        : "r"((a).x), "r"((a).y), "r"((a).z), "r"((a).w), \
          "r"((b).x), "r"((b).y))

// ---------------- flash attention: O = softmax(Q K^T * scale) V ----------------
// Grid: (1, 8 m-tiles, 64 (b,h)). 256 thr = 8 warps; warp w owns q-rows w*16..+16.
// Q A-frags in regs; K/V tiles fragment-packed in SMEM; online softmax in regs.
__global__ __launch_bounds__(256, 1)
void flash_kernel(const float* __restrict__ qkv, const float* __restrict__ vt,
                  float* __restrict__ ocat, float scale) {
    __shared__ uint32_t sK[6144];   // 24 KB: K tile B-frags (16 jn x 6 kg), aliased for Q staging
    __shared__ uint32_t sV[6144];   // 24 KB: V tile B-frags (12 jn x 8 kg)
    int z = blockIdx.z, b = z >> 3, h = z & 7;
    int m0 = blockIdx.y * 128;
    int tid = threadIdx.x, lane = tid & 31, wid = tid >> 5;
    int t = lane & 3, g = lane >> 2;

    const float* Qg = qkv + ((long)b * 1024 + m0) * 2304 + h * 96;
    const float* Kg = qkv + (long)b * 1024 * 2304 + 768 + h * 96;
    const float* Vg = vt + (long)z * 96 * 1024;

    // ---- stage Q (128x96) into sK in A-frag layout; pull to regs
    #pragma unroll
    for (int i = 0; i < 12; i++) {
        int idx = tid + 256 * i;
        int r = idx / 24, q = idx % 24;
        int k0 = q * 4;
        int im = r >> 4, gg = r & 7, row8 = (r >> 3) & 1;
        int kg = k0 >> 4, k8 = (k0 >> 3) & 1, t0 = (k0 >> 1) & 3;
        int base = ((im * 6 + kg) * 32 + gg * 4 + t0) * 4 + row8 + 2 * k8;
        float4 v = *(const float4*)(Qg + (long)r * 2304 + k0);
        sK[base]     = pack_h2(v.x, v.y);
        sK[base + 4] = pack_h2(v.z, v.w);
    }
    __syncthreads();
    uint4 qf[6];
    #pragma unroll
    for (int kg = 0; kg < 6; kg++)
        qf[kg] = *(const uint4*)&sK[((wid * 6 + kg) * 32 + lane) * 4];
    __syncthreads();

    float mr0 = -1e30f, mr1 = -1e30f, l0 = 0.f, l1 = 0.f;
    float accO[12][4];
    #pragma unroll
    for (int j = 0; j < 12; j++)
        #pragma unroll
        for (int c = 0; c < 4; c++) accO[j][c] = 0.f;

    for (int kt = 0; kt < 8; kt++) {
        // load K tile (128 keys x 96) -> B-frag layout
        #pragma unroll
        for (int i = 0; i < 12; i++) {
            int idx = tid + 256 * i;
            int r = idx / 24, q = idx % 24;
            int k0 = q * 4;
            int jn = r >> 3, nn = r & 7;
            int kg = k0 >> 4, k8 = (k0 >> 3) & 1, t0 = (k0 >> 1) & 3;
            int base = ((jn * 6 + kg) * 32 + nn * 4 + t0) * 2 + k8;
            float4 v = *(const float4*)(Kg + (long)(kt * 128 + r) * 2304 + k0);
            sK[base]     = pack_h2(v.x, v.y);
            sK[base + 2] = pack_h2(v.z, v.w);
        }
        // load V tile (96 n-rows x 128 keys) -> B-frag layout
        #pragma unroll
        for (int i = 0; i < 12; i++) {
            int idx = tid + 256 * i;
            int r = idx >> 5, q = idx & 31;
            int k0 = q * 4;
            int jn = r >> 3, nn = r & 7;
            int kg = k0 >> 4, k8 = (k0 >> 3) & 1, t0 = (k0 >> 1) & 3;
            int base = ((jn * 8 + kg) * 32 + nn * 4 + t0) * 2 + k8;
            float4 v = *(const float4*)(Vg + (long)r * 1024 + kt * 128 + k0);
            sV[base]     = pack_h2(v.x, v.y);
            sV[base + 2] = pack_h2(v.z, v.w);
        }
        __syncthreads();

        // S = Q K^T
        float accS[16][4];
        #pragma unroll
        for (int j = 0; j < 16; j++)
            #pragma unroll
            for (int c = 0; c < 4; c++) accS[j][c] = 0.f;
        #pragma unroll
        for (int kg = 0; kg < 6; kg++)
            #pragma unroll
            for (int jn = 0; jn < 16; jn++) {
                uint2 bf = *(const uint2*)&sK[((jn * 6 + kg) * 32 + lane) * 2];
                MMAF16(accS[jn], qf[kg], bf);
            }

        // scale + per-row max (rows g and g+8 within t-quad)
        float mx0 = -1e30f, mx1 = -1e30f;
        #pragma unroll
        for (int jn = 0; jn < 16; jn++) {
            accS[jn][0] *= scale; accS[jn][1] *= scale;
            accS[jn][2] *= scale; accS[jn][3] *= scale;
            mx0 = fmaxf(mx0, fmaxf(accS[jn][0], accS[jn][1]));
            mx1 = fmaxf(mx1, fmaxf(accS[jn][2], accS[jn][3]));
        }
        mx0 = fmaxf(mx0, __shfl_xor_sync(0xffffffffu, mx0, 1));
        mx0 = fmaxf(mx0, __shfl_xor_sync(0xffffffffu, mx0, 2));
        mx1 = fmaxf(mx1, __shfl_xor_sync(0xffffffffu, mx1, 1));
        mx1 = fmaxf(mx1, __shfl_xor_sync(0xffffffffu, mx1, 2));

        float mn0 = fmaxf(mr0, mx0), mn1 = fmaxf(mr1, mx1);
        float cr0 = fexp(mr0 - mn0), cr1 = fexp(mr1 - mn1);

        // P = exp(S - mn), row sums, pack to fp16 A-frags
        float s0 = 0.f, s1 = 0.f;
        uint32_t plo[16], phi[16];
        #pragma unroll
        for (int jn = 0; jn < 16; jn++) {
            float e0 = fexp(accS[jn][0] - mn0);
            float e1 = fexp(accS[jn][1] - mn0);
            float e2 = fexp(accS[jn][2] - mn1);
            float e3 = fexp(accS[jn][3] - mn1);
            s0 += e0 + e1; s1 += e2 + e3;
            plo[jn] = pack_h2(e0, e1);
            phi[jn] = pack_h2(e2, e3);
        }
        s0 += __shfl_xor_sync(0xffffffffu, s0, 1);
        s0 += __shfl_xor_sync(0xffffffffu, s0, 2);
        s1 += __shfl_xor_sync(0xffffffffu, s1, 1);
        s1 += __shfl_xor_sync(0xffffffffu, s1, 2);

        l0 = l0 * cr0 + s0;
        l1 = l1 * cr1 + s1;
        mr0 = mn0; mr1 = mn1;
        #pragma unroll
        for (int j = 0; j < 12; j++) {
            accO[j][0] *= cr0; accO[j][1] *= cr0;
            accO[j][2] *= cr1; accO[j][3] *= cr1;
        }

        // O += P V  (P C-frags repacked as A-frags)
        #pragma unroll
        for (int kg = 0; kg < 8; kg++) {
            uint4 af = make_uint4(plo[2 * kg], phi[2 * kg], plo[2 * kg + 1], phi[2 * kg + 1]);
            #pragma unroll
            for (int jn = 0; jn < 12; jn++) {
                uint2 bf = *(const uint2*)&sV[((jn * 8 + kg) * 32 + lane) * 2];
                MMAF16(accO[jn], af, bf);
            }
        }
        __syncthreads();
    }

    float inv0 = 1.f / l0, inv1 = 1.f / l1;
    long row0 = (long)(b * 1024 + m0 + wid * 16 + g);
    #pragma unroll
    for (int jn = 0; jn < 12; jn++) {
        int col = h * 96 + jn * 8 + t * 2;
        float2 v0, v1;
        v0.x = accO[jn][0] * inv0; v0.y = accO[jn][1] * inv0;
        v1.x = accO[jn][2] * inv1; v1.y = accO[jn][3] * inv1;
        *(float2*)&ocat[row0 * DIM + col] = v0;
        *(float2*)&ocat[(row0 + 8) * DIM + col] = v1;
    }
}

// ---------------- mma.sync fp16 GEMM (verified R5) ----------------
__global__ __launch_bounds__(256, 1)
void mma_gemm(const float* __restrict__ A, long lda,
              const float* __restrict__ Bt, long ldb,
              float* __restrict__ C, long ldc,
              int M, int N, int K,
              const float* __restrict__ bias, float alpha,
              int batchH,
              long aOffB, long aOffH, long bOffB, long bOffH,
              long cOffB, long cOffH) {
    extern __shared__ uint32_t dsm[];

    int z = blockIdx.z;
    int bb = z / batchH, hh = z % batchH;
    A  += bb * aOffB + hh * aOffH;
    Bt += bb * bOffB + hh * bOffH;
    C  += bb * cOffB + hh * cOffH;
    int m0 = blockIdx.y * 128, n0 = blockIdx.x * 128;
    int tid = threadIdx.x, lane = tid & 31, wid = tid >> 5;
    int wm = wid & 1, wn = wid >> 1;

    const float* Ab = A + (long)m0 * lda;

    int aR[4], aQ[4], aBase[4], aOff[4];
    #pragma unroll
    for (int i = 0; i < 4; i++) {
        int idx = tid + 256 * i;
        int r = idx >> 3, q = idx & 7;
        aR[i] = r; aQ[i] = q;
        int im = r >> 4, g = r & 7, row8 = (r >> 3) & 1;
        int ikf = q >> 2, k8 = (q >> 1) & 1;
        aBase[i] = ((im * 2 + ikf) * 32 + g * 4) * 4 + k8 * 2 + row8;
        aOff[i] = 8 * (q & 1);
    }
    int bR[4], bQ[4], bBase[4], bOff[4];
    #pragma unroll
    for (int i = 0; i < 4; i++) {
        int idx = tid + 256 * i;
        int r = idx >> 3, q = idx & 7;
        bR[i] = r; bQ[i] = q;
        int in = r >> 3, nn = r & 7;
        int ikf = q >> 2, k8 = (q >> 1) & 1;
        bBase[i] = ((in * 2 + ikf) * 32 + nn * 4) * 2 + k8;
        bOff[i] = 4 * (q & 1);
    }

    float acc[4][4][4];
    #pragma unroll
    for (int i = 0; i < 4; i++)
        #pragma unroll
        for (int j = 0; j < 4; j++)
            #pragma unroll
            for (int c = 0; c < 4; c++) acc[i][j][c] = 0.f;

    int nch = K >> 5;
    float4 va[4], vb[4];

    #pragma unroll
    for (int i = 0; i < 4; i++)
        va[i] = *(const float4*)(Ab + (long)aR[i] * lda + aQ[i] * 4);
    #pragma unroll
    for (int i = 0; i < 4; i++) {
        int gn = n0 + bR[i];
        vb[i] = (gn < N) ? *(const float4*)(Bt + (long)gn * ldb + bQ[i] * 4)
                         : make_float4(0.f, 0.f, 0.f, 0.f);
    }
    {
        uint32_t* sA0 = dsm;
        uint32_t* sB0 = dsm + 4096;
        #pragma unroll
        for (int i = 0; i < 4; i++) {
            uint32_t* s = &sA0[aBase[i] + aOff[i]];
            s[0] = pack_h2(va[i].x, va[i].y);
            s[4] = pack_h2(va[i].z, va[i].w);
        }
        #pragma unroll
        for (int i = 0; i < 4; i++) {
            uint32_t* s = &sB0[bBase[i] + bOff[i]];
            s[0] = pack_h2(vb[i].x, vb[i].y);
            s[2] = pack_h2(vb[i].z, vb[i].w);
        }
    }
    __syncthreads();

    for (int it = 0; it < nch; it++) {
        int buf = it & 1;
        bool more = (it + 1 < nch);
        if (more) {
            long koff = (long)(it + 1) * 32;
            #pragma unroll
            for (int i = 0; i < 4; i++)
                va[i] = *(const float4*)(Ab + (long)aR[i] * lda + koff + aQ[i] * 4);
            #pragma unroll
            for (int i = 0; i < 4; i++) {
                int gn = n0 + bR[i];
                vb[i] = (gn < N) ? *(const float4*)(Bt + (long)gn * ldb + koff + bQ[i] * 4)
                                 : make_float4(0.f, 0.f, 0.f, 0.f);
            }
        }
        const uint32_t* sAb = dsm + buf * 2048;
        const uint32_t* sBb = dsm + 4096 + buf * 2048;
        #pragma unroll
        for (int ikf = 0; ikf < 2; ikf++) {
            uint4 af[4];
            uint2 bf[4];
            #pragma unroll
            for (int i2 = 0; i2 < 4; i2++)
                af[i2] = *(const uint4*)&sAb[(((wm * 4 + i2) * 2 + ikf) * 32 + lane) * 4];
            #pragma unroll
            for (int j2 = 0; j2 < 4; j2++)
                bf[j2] = *(const uint2*)&sBb[(((wn * 4 + j2) * 2 + ikf) * 32 + lane) * 2];
            #pragma unroll
            for (int i2 = 0; i2 < 4; i2++)
                #pragma unroll
                for (int j2 = 0; j2 < 4; j2++)
                    MMAF16(acc[i2][j2], af[i2], bf[j2]);
        }
        __syncthreads();
        if (more) {
            uint32_t* sAn = dsm + (buf ^ 1) * 2048;
            uint32_t* sBn = dsm + 4096 + (buf ^ 1) * 2048;
            #pragma unroll
            for (int i = 0; i < 4; i++) {
                uint32_t* s = &sAn[aBase[i] + aOff[i]];
                s[0] = pack_h2(va[i].x, va[i].y);
                s[4] = pack_h2(va[i].z, va[i].w);
            }
            #pragma unroll
            for (int i = 0; i < 4; i++) {
                uint32_t* s = &sBn[bBase[i] + bOff[i]];
                s[0] = pack_h2(vb[i].x, vb[i].y);
                s[2] = pack_h2(vb[i].z, vb[i].w);
            }
            __syncthreads();
        }
    }

    int g = lane >> 2, t = lane & 3;
    #pragma unroll
    for (int i2 = 0; i2 < 4; i2++) {
        int gm = m0 + (wm * 4 + i2) * 16 + g;
        #pragma unroll
        for (int j2 = 0; j2 < 4; j2++) {
            int gn = n0 + (wn * 4 + j2) * 8 + t * 2;
            if (gn < N) {
                float b0 = bias ? __ldg(bias + gn) : 0.f;
                float b1 = bias ? __ldg(bias + gn + 1) : 0.f;
                float2 v0, v1;
                v0.x = acc[i2][j2][0] * alpha + b0;
                v0.y = acc[i2][j2][1] * alpha + b1;
                v1.x = acc[i2][j2][2] * alpha + b0;
                v1.y = acc[i2][j2][3] * alpha + b1;
                *(float2*)&C[(long)gm * ldc + gn] = v0;
                *(float2*)&C[(long)(gm + 8) * ldc + gn] = v1;
            }
        }
    }
}

// ---------------- transposes ----------------
__global__ void transpose_kernel(const float* __restrict__ src, float* __restrict__ dst,
                                 int R, int Cc) {
    __shared__ float t[32][33];
    int c0 = blockIdx.x * 32, r0 = blockIdx.y * 32;
    int tx = threadIdx.x, ty = threadIdx.y;
    for (int i = ty; i < 32; i += 8) {
        int r = r0 + i, c = c0 + tx;
        if (r < R && c < Cc) t[i][tx] = src[(long)r * Cc + c];
    }
    __syncthreads();
    for (int i = ty; i < 32; i += 8) {
        int c = c0 + i, r = r0 + tx;
        if (c < Cc && r < R) dst[(long)c * R + r] = t[tx][i];
    }
}

// vt[(b*8+h)*96 + d][t] = qkv[(b*1024+t)*2304 + 1536 + h*96 + d]
__global__ void transpose_v_kernel(const float* __restrict__ qkv, float* __restrict__ vt) {
    int z = blockIdx.z; int b = z >> 3, h = z & 7;
    __shared__ float tb[32][33];
    int d0 = blockIdx.x * 32, t0 = blockIdx.y * 32;
    int tx = threadIdx.x, ty = threadIdx.y;
    const float* src = qkv + (long)b * 1024 * 2304 + 1536 + h * 96;
    for (int i = ty; i < 32; i += 8)
        tb[i][tx] = src[(long)(t0 + i) * 2304 + d0 + tx];
    __syncthreads();
    float* dst = vt + ((long)z * 96 + d0) * 1024 + t0;
    for (int j = ty; j < 32; j += 8)
        dst[(long)j * 1024 + tx] = tb[tx][j];
}

// ---------------- misc elementwise ----------------
__global__ void copy_kernel(const float* __restrict__ src, float* __restrict__ dst, long n) {
    long i = (long)blockIdx.x * blockDim.x + threadIdx.x;
    long stride = (long)gridDim.x * blockDim.x;
    for (; i < n; i += stride) dst[i] = src[i];
}
__global__ void zero_bytes_kernel(unsigned char* p, long n) {
    long i = (long)blockIdx.x * blockDim.x + threadIdx.x;
    long stride = (long)gridDim.x * blockDim.x;
    int* pi = (int*)p;
    long nw = n >> 2;
    for (; i < nw; i += stride) pi[i] = 0;
}

// ---------------- topk select (sim precomputed in fp32) ----------------
__global__ void topk_select_kernel(const float* __restrict__ sim, int* __restrict__ idx_out) {
    long r = blockIdx.x;
    const float* row = sim + r * SEQ;
    __shared__ float s[SEQ];
    __shared__ float bv[256];
    __shared__ int   bi[256];
    int tid = threadIdx.x;
    for (int i = tid; i < SEQ; i += 256) s[i] = row[i];
    __syncthreads();
    for (int sel = 0; sel < KNEIGH; sel++) {
        float v = -INFINITY; int mi = 0x7fffffff;
        for (int t = tid; t < SEQ; t += 256) {
            float sv = s[t];
            if (sv > v || (sv == v && t < mi)) { v = sv; mi = t; }
        }
        bv[tid] = v; bi[tid] = mi;
        __syncthreads();
        for (int o = 128; o > 0; o >>= 1) {
            if (tid < o) {
                if (bv[tid + o] > bv[tid] || (bv[tid + o] == bv[tid] && bi[tid + o] < bi[tid])) {
                    bv[tid] = bv[tid + o]; bi[tid] = bi[tid + o];
                }
            }
            __syncthreads();
        }
        if (tid == 0) { idx_out[r * KNEIGH + sel] = bi[0]; s[bi[0]] = -INFINITY; }
        __syncthreads();
    }
}

// ---------------- adjacency + degree ----------------
__global__ void scatter_adj_kernel(const int* __restrict__ idx, unsigned char* __restrict__ A) {
    int r = blockIdx.x * blockDim.x + threadIdx.x;
    if (r >= ROWS) return;
    int b = r >> 10, s = r & 1023;
    unsigned char* Ab = A + (long long)b * SEQ * SEQ;
    Ab[(long)s * SEQ + s] = 1;
    #pragma unroll
    for (int j = 0; j < KNEIGH; j++) {
        int t = idx[(long)r * KNEIGH + j];
        Ab[(long)s * SEQ + t] = 1;
        Ab[(long)t * SEQ + s] = 1;
    }
}
__global__ void degree_kernel(const unsigned char* __restrict__ A, float* __restrict__ dinv) {
    int r = blockIdx.x * blockDim.x + threadIdx.x;
    if (r >= ROWS) return;
    const uint32_t* row = (const uint32_t*)(A + (long long)r * SEQ);
    int d = 0;
    for (int i = 0; i < SEQ / 4; i++) {
        uint32_t w = row[i];
        d += (w & 0xff) + ((w >> 8) & 0xff) + ((w >> 16) & 0xff) + ((w >> 24) & 0xff);
    }
    dinv[r] = rsqrtf((float)d);
}

// ---------------- sparse GCN aggregate ----------------
__global__ void gcn_agg_kernel(const unsigned char* __restrict__ A, const float* __restrict__ dinv,
                               const float* __restrict__ xw, const float* __restrict__ gcn_b,
                               float* __restrict__ cat) {
    int r = blockIdx.x;
    int b = r >> 10;
    const unsigned char* Arow = A + (long long)r * SEQ;
    __shared__ int   nbr[SEQ];
    __shared__ float wgt[SEQ];
    __shared__ int cnt;
    int tid = threadIdx.x;
    if (tid == 0) cnt = 0;
    __syncthreads();
    for (int t = tid; t < SEQ; t += 256) {
        if (Arow[t]) {
            int p = atomicAdd(&cnt, 1);
            nbr[p] = t;
            wgt[p] = dinv[(b << 10) + t];
        }
    }
    __syncthreads();
    int n = cnt;
    float acc0 = 0.f, acc1 = 0.f, acc2 = 0.f;
    for (int i = 0; i < n; i++) {
        const float* row = xw + ((long)(b << 10) + nbr[i]) * DIM;
        float w = wgt[i];
        acc0 += w * row[tid];
        acc1 += w * row[tid + 256];
        acc2 += w * row[tid + 512];
    }
    float ws = dinv[r];
    long base = (long)r * (2 * DIM);
    cat[base + tid]       = ws * acc0 + gcn_b[tid];
    cat[base + tid + 256] = ws * acc1 + gcn_b[tid + 256];
    cat[base + tid + 512] = ws * acc2 + gcn_b[tid + 512];
}

// ---------------- SIMT fp32 GEMM (kept for exact sim = x x^T) ----------------
template<bool TRANS_B>
__global__ __launch_bounds__(256, 2)
void gemm_kernel(const float* __restrict__ A, long lda,
                 const float* __restrict__ B, long ldb,
                 float* __restrict__ C, long ldc,
                 int M, int N, int K,
                 const float* __restrict__ bias, float alpha,
                 int batchH,
                 long aOffB, long aOffH, long bOffB, long bOffH, long cOffB, long cOffH) {
    int z = blockIdx.z;
    int bb = z / batchH, hh = z % batchH;
    A += bb * aOffB + hh * aOffH;
    B += bb * bOffB + hh * bOffH;
    C += bb * cOffB + hh * cOffH;
    const int BM = 128, BN = 128, BK = 8;
    __shared__ float As[BK][BM];
    __shared__ float Bs[BK][BN];
    int tid = threadIdx.x;
    int tx = tid & 15, ty = tid >> 4;
    int m0 = blockIdx.y * BM, n0 = blockIdx.x * BN;
    float acc[8][8];
    #pragma unroll
    for (int i = 0; i < 8; i++)
        #pragma unroll
        for (int j = 0; j < 8; j++) acc[i][j] = 0.f;
    for (int k0 = 0; k0 < K; k0 += BK) {
        {
            int m  = tid >> 1;
            int kb = (tid & 1) * 4;
            int gm = m0 + m;
            #pragma unroll
            for (int i = 0; i < 4; i++) {
                int kk = kb + i, gk = k0 + kk;
                As[kk][m] = (gm < M && gk < K) ? A[(long)gm * lda + gk] : 0.f;
            }
        }
        if (!TRANS_B) {
            int kk = tid >> 5, nb = tid & 31, gk = k0 + kk;
            #pragma unroll
            for (int i = 0; i < 4; i++) {
                int n = nb + 32 * i, gn = n0 + n;
                Bs[kk][n] = (gk < K && gn < N) ? B[(long)gk * ldb + gn] : 0.f;
            }
        } else {
            int n = tid >> 1, kb = (tid & 1) * 4, gn = n0 + n;
            #pragma unroll
            for (int i = 0; i < 4; i++) {
                int kk = kb + i, gk = k0 + kk;
                Bs[kk][n] = (gn < N && gk < K) ? B[(long)gn * ldb + gk] : 0.f;
            }
        }
        __syncthreads();
        #pragma unroll
        for (int kk = 0; kk < BK; kk++) {
            float a[8], bvals[8];
            #pragma unroll
            for (int i = 0; i < 8; i++) a[i] = As[kk][ty * 8 + i];
            #pragma unroll
            for (int j = 0; j < 8; j++) bvals[j] = Bs[kk][tx * 8 + j];
            #pragma unroll
            for (int i = 0; i < 8; i++)
                #pragma unroll
                for (int j = 0; j < 8; j++) acc[i][j] += a[i] * bvals[j];
        }
        __syncthreads();
    }
    #pragma unroll
    for (int i = 0; i < 8; i++) {
        int gm = m0 + ty * 8 + i;
        if (gm >= M) continue;
        #pragma unroll
        for (int j = 0; j < 8; j++) {
            int gn = n0 + tx * 8 + j;
            if (gn >= N) continue;
            float v = acc[i][j] * alpha;
            if (bias) v += bias[gn];
            C[(long)gm * ldc + gn] = v;
        }
    }
}

// ---------------- gate + residual + layernorm ----------------
__global__ void fuse_ln_kernel(const float* __restrict__ gatelin, const float* __restrict__ cat,
                               float* __restrict__ h,
                               const float* __restrict__ ln_scale, const float* __restrict__ ln_bias) {
    long r = blockIdx.x;
    int tid = threadIdx.x;
    __shared__ float red[256];
    float f[3];
    #pragma unroll
    for (int i = 0; i < 3; i++) {
        int j = tid + 256 * i;
        float g  = gatelin[r * DIM + j];
        float gc = cat[r * (2 * DIM) + j];
        float at = cat[r * (2 * DIM) + DIM + j];
        float sg = 1.f / (1.f + fexp(-g));
        f[i] = sg * gc + (1.f - sg) * at + h[r * DIM + j];
    }
    float s1 = f[0] + f[1] + f[2];
    red[tid] = s1; __syncthreads();
    #pragma unroll
    for (int o = 128; o > 0; o >>= 1) { if (tid < o) red[tid] += red[tid + o]; __syncthreads(); }
    float mu = red[0] * (1.f / DIM);
    __syncthreads();
    float s2 = 0.f;
    #pragma unroll
    for (int i = 0; i < 3; i++) { float d = f[i] - mu; s2 += d * d; }
    red[tid] = s2; __syncthreads();
    #pragma unroll
    for (int o = 128; o > 0; o >>= 1) { if (tid < o) red[tid] += red[tid + o]; __syncthreads(); }
    float var = red[0] * (1.f / DIM);
    float inv = rsqrtf(var + LN_EPS);
    #pragma unroll
    for (int i = 0; i < 3; i++) {
        int j = tid + 256 * i;
        h[r * DIM + j] = (f[i] - mu) * inv * ln_scale[j] + ln_bias[j];
    }
}

// ---------------- host helper ----------------
#define MMA_SMEM 32768

static void launch_mma(const float* A, long lda, const float* Bt, long ldb,
                       float* C, long ldc, int M, int N, int K,
                       const float* bias, float alpha) {
    dim3 grid((N + 127) / 128, M / 128, 1);
    mma_gemm<<<grid, 256, MMA_SMEM>>>(A, lda, Bt, ldb, C, ldc, M, N, K, bias, alpha,
                                      1, 0, 0, 0, 0, 0, 0);
}

extern "C" void kernel_launch(void* const* d_in, const int* in_sizes, int n_in,
                              void* d_out, int out_size) {
    const float* x          = (const float*)d_in[0];
    const float* gcn_w      = (const float*)d_in[1];
    const float* gcn_b      = (const float*)d_in[2];
    const float* attn_in_w  = (const float*)d_in[3];
    const float* attn_in_b  = (const float*)d_in[4];
    const float* attn_out_w = (const float*)d_in[5];
    const float* attn_out_b = (const float*)d_in[6];
    const float* gate_w     = (const float*)d_in[7];
    const float* gate_b     = (const float*)d_in[8];
    const float* ln_scale   = (const float*)d_in[9];
    const float* ln_bias    = (const float*)d_in[10];
    const float* proj_w     = (const float*)d_in[11];
    const float* proj_b     = (const float*)d_in[12];
    float* out = (float*)d_out;

    static bool attr_done = false;
    if (!attr_done) {
        cudaFuncSetAttribute(mma_gemm, cudaFuncAttributeMaxDynamicSharedMemorySize, MMA_SMEM);
        attr_done = true;
    }

    float *p_h, *p_xw, *p_qkv, *p_scores, *p_ocat, *p_cat, *p_gate, *p_dinv, *p_wt, *p_vt;
    unsigned char* p_adj;
    int* p_topk;
    cudaGetSymbolAddress((void**)&p_h, g_h);
    cudaGetSymbolAddress((void**)&p_xw, g_xw);
    cudaGetSymbolAddress((void**)&p_qkv, g_qkv);
    cudaGetSymbolAddress((void**)&p_scores, g_scores);
    cudaGetSymbolAddress((void**)&p_ocat, g_ocat);
    cudaGetSymbolAddress((void**)&p_cat, g_cat);
    cudaGetSymbolAddress((void**)&p_gate, g_gate);
    cudaGetSymbolAddress((void**)&p_dinv, g_dinv);
    cudaGetSymbolAddress((void**)&p_adj, g_adj);
    cudaGetSymbolAddress((void**)&p_topk, g_topk);
    cudaGetSymbolAddress((void**)&p_wt, g_wt);
    cudaGetSymbolAddress((void**)&p_vt, g_vt);

    const float attn_scale = (float)(1.0 / sqrt((double)HDIM));
    dim3 tb(32, 8);

    // h = x
    copy_kernel<<<1024, 256>>>(x, p_h, (long)ROWS * DIM);

    // transpose all weights once: src [K,N] -> dst [N,K]
    for (int l = 0; l < NLAYERS; l++) {
        transpose_kernel<<<dim3(768 / 32, 768 / 32), tb>>>(gcn_w + (long)l * DIM * DIM, p_wt + WT_GCN(l), DIM, DIM);
        transpose_kernel<<<dim3(2304 / 32, 768 / 32), tb>>>(attn_in_w + (long)l * DIM * 3 * DIM, p_wt + WT_AIW(l), DIM, 3 * DIM);
        transpose_kernel<<<dim3(768 / 32, 768 / 32), tb>>>(attn_out_w + (long)l * DIM * DIM, p_wt + WT_AOW(l), DIM, DIM);
        transpose_kernel<<<dim3(768 / 32, 1536 / 32), tb>>>(gate_w + (long)l * 2 * DIM * DIM, p_wt + WT_GW(l), 2 * DIM, DIM);
    }
    transpose_kernel<<<dim3(768 / 32, 768 / 32), tb>>>(proj_w, p_wt + WT_PROJ, DIM, DIM);

    // sim = x x^T (exact fp32 SIMT), then top-5 select
    {
        dim3 grid(SEQ / 128, SEQ / 128, BATCH);
        gemm_kernel<true><<<grid, 256>>>(x, DIM, x, DIM, p_scores, SEQ,
                                         SEQ, SEQ, DIM, nullptr, 1.f,
                                         1, (long)SEQ * DIM, 0, (long)SEQ * DIM, 0,
                                         (long)SEQ * SEQ, 0);
    }
    topk_select_kernel<<<ROWS, 256>>>(p_scores, p_topk);
    zero_bytes_kernel<<<1024, 256>>>(p_adj, (long long)BATCH * SEQ * SEQ);
    scatter_adj_kernel<<<(ROWS + 255) / 256, 256>>>(p_topk, p_adj);
    degree_kernel<<<(ROWS + 255) / 256, 256>>>(p_adj, p_dinv);

    for (int l = 0; l < NLAYERS; l++) {
        const float* gb  = gcn_b + (long)l * DIM;
        const float* aib = attn_in_b + (long)l * 3 * DIM;
        const float* aob = attn_out_b + (long)l * DIM;
        const float* gtb = gate_b + (long)l * DIM;
        const float* lns = ln_scale + (long)l * DIM;
        const float* lnb = ln_bias + (long)l * DIM;

        // XW = h @ gcn_w[l]
        launch_mma(p_h, DIM, p_wt + WT_GCN(l), DIM, p_xw, DIM, ROWS, DIM, DIM, nullptr, 1.f);
        // gcn_out -> cat[:, 0:768]
        gcn_agg_kernel<<<ROWS, 256>>>(p_adj, p_dinv, p_xw, gb, p_cat);
        // qkv = h @ attn_in_w[l] + b
        launch_mma(p_h, DIM, p_wt + WT_AIW(l), DIM, p_qkv, 3 * DIM, ROWS, 3 * DIM, DIM, aib, 1.f);
        // V transpose: [64, 96, 1024]
        transpose_v_kernel<<<dim3(3, 32, 64), tb>>>(p_qkv, p_vt);
        // fused flash attention -> ocat
        flash_kernel<<<dim3(1, 8, 64), 256>>>(p_qkv, p_vt, p_ocat, attn_scale);
        // attn_out = O @ attn_out_w[l] + b -> cat[:, 768:1536]
        launch_mma(p_ocat, DIM, p_wt + WT_AOW(l), DIM, p_cat + DIM, 2 * DIM, ROWS, DIM, DIM, aob, 1.f);
        // gate_lin = cat @ gate_w[l] + b
        launch_mma(p_cat, 2 * DIM, p_wt + WT_GW(l), 2 * DIM, p_gate, DIM, ROWS, DIM, 2 * DIM, gtb, 1.f);
        // h = LN(gate*gcn + (1-gate)*attn + h)
        fuse_ln_kernel<<<ROWS, 256>>>(p_gate, p_cat, p_h, lns, lnb);
    }

    // out = h @ proj_w + proj_b
    launch_mma(p_h, DIM, p_wt + WT_PROJ, DIM, out, DIM, ROWS, DIM, DIM, proj_b, 1.f);
}

// round 7
// speedup vs baseline: 5.4193x; 1.2712x over previous
#include <cuda_runtime.h>
#include <math.h>
#include <stdint.h>

// ---------------- problem constants ----------------
#define BATCH 8
#define SEQ   1024
#define DIM   768
#define HEADS 8
#define HDIM  96
#define KNEIGH 5
#define NLAYERS 3
#define ROWS (BATCH*SEQ)  // 8192
#define LN_EPS 1e-5f

// ---------------- device scratch (static, allocation-free) ----------------
__device__ float g_h[ROWS * DIM];
__device__ float g_xw[ROWS * DIM];
__device__ float g_qkv[ROWS * 3 * DIM];
__device__ float g_scores[(long long)BATCH * SEQ * SEQ]; // sim workspace (32 MB)
__device__ float g_ocat[ROWS * DIM];
__device__ float g_cat[ROWS * 2 * DIM];   // [gcn | attn] stride 1536
__device__ float g_gate[ROWS * DIM];
__device__ unsigned char g_adj[(long long)BATCH * SEQ * SEQ];    // 8 MB
__device__ float g_dinv[ROWS];
__device__ int   g_topk[ROWS * KNEIGH];
__device__ uint32_t g_wp[6488064];        // fp16 fragment-packed weights (26 MB)
__device__ float g_vt[ROWS * DIM];        // V transposed per (b,h): [64, 96, 1024]

// packed weight word offsets (tile-blocked: [nblk][kchunk][2048])
#define WP_GCN(l)  ((long)(l) * 294912)
#define WP_AIW(l)  (884736L + (long)(l) * 884736L)
#define WP_AOW(l)  (3538944L + (long)(l) * 294912L)
#define WP_GW(l)   (4423680L + (long)(l) * 589824L)
#define WP_PROJ    (6193152L)

// pack two floats to half2 (lo = a, hi = b)
__device__ __forceinline__ uint32_t pack_h2(float a, float b) {
    uint32_t r;
    asm("cvt.rn.f16x2.f32 %0, %2, %1;" : "=r"(r) : "f"(a), "f"(b));
    return r;
}

// FMA-only exp (no MUFU)
__device__ __forceinline__ float fexp(float x) {
    x = fmaxf(x, -87.0f);
    float y = x * 1.4426950408889634f;
    int i = __float2int_rn(y);
    float r = (y - (float)i) * 0.6931471805599453f;
    float p = 1.9841270e-4f;
    p = fmaf(p, r, 1.3888889e-3f);
    p = fmaf(p, r, 8.3333333e-3f);
    p = fmaf(p, r, 4.1666667e-2f);
    p = fmaf(p, r, 1.6666667e-1f);
    p = fmaf(p, r, 0.5f);
    p = fmaf(p, r, 1.0f);
    p = fmaf(p, r, 1.0f);
    return p * __int_as_float((i + 127) << 23);
}

#define MMAF16(d, a, b) \
    asm volatile("mma.sync.aligned.m16n8k16.row.col.f32.f16.f16.f32 " \
        "{%0,%1,%2,%3}, {%4,%5,%6,%7}, {%8,%9}, {%0,%1,%2,%3};" \
        : "+f"((d)[0]), "+f"((d)[1]), "+f"((d)[2]), "+f"((d)[3]) \
        : "r"((a).x), "r"((a).y), "r"((a).z), "r"((a).w), \
          "r"((b).x), "r"((b).y))

// ---------------- weight packing: w [K,N] fp32 -> wp fragment-packed fp16 ----------------
// word for (n, k even pair): blk = (n>>7)*nch + (k>>5);
// widx = blk*2048 + (((n>>3 & 15)*2 + ((k>>4)&1))*32 + (n&7)*4 + ((k>>1)&3))*2 + ((k>>3)&1)
__global__ void pack_weights_kernel(const float* __restrict__ w, uint32_t* __restrict__ wp,
                                    int N, int K) {
    int nch = K >> 5;
    long total = (long)N * (K >> 1);
    for (long tId = (long)blockIdx.x * blockDim.x + threadIdx.x; tId < total;
         tId += (long)gridDim.x * blockDim.x) {
        int n = (int)(tId % N);
        int kp = (int)(tId / N);
        int k = kp * 2;
        float v0 = w[(long)k * N + n];
        float v1 = w[(long)(k + 1) * N + n];
        long blk = (long)(n >> 7) * nch + (k >> 5);
        int nloc = n & 127, kloc = k & 31;
        int widx = ((((nloc >> 3) * 2 + ((kloc >> 4) & 1)) * 32
                     + (nloc & 7) * 4 + ((kloc >> 1) & 3)) * 2) + ((kloc >> 3) & 1);
        wp[blk * 2048 + widx] = pack_h2(v0, v1);
    }
}

// ---------------- flash attention (verified R6) ----------------
__global__ __launch_bounds__(256, 1)
void flash_kernel(const float* __restrict__ qkv, const float* __restrict__ vt,
                  float* __restrict__ ocat, float scale) {
    __shared__ uint32_t sK[6144];
    __shared__ uint32_t sV[6144];
    int z = blockIdx.z, b = z >> 3, h = z & 7;
    int m0 = blockIdx.y * 128;
    int tid = threadIdx.x, lane = tid & 31, wid = tid >> 5;
    int t = lane & 3, g = lane >> 2;

    const float* Qg = qkv + ((long)b * 1024 + m0) * 2304 + h * 96;
    const float* Kg = qkv + (long)b * 1024 * 2304 + 768 + h * 96;
    const float* Vg = vt + (long)z * 96 * 1024;

    #pragma unroll
    for (int i = 0; i < 12; i++) {
        int idx = tid + 256 * i;
        int r = idx / 24, q = idx % 24;
        int k0 = q * 4;
        int im = r >> 4, gg = r & 7, row8 = (r >> 3) & 1;
        int kg = k0 >> 4, k8 = (k0 >> 3) & 1, t0 = (k0 >> 1) & 3;
        int base = ((im * 6 + kg) * 32 + gg * 4 + t0) * 4 + row8 + 2 * k8;
        float4 v = *(const float4*)(Qg + (long)r * 2304 + k0);
        sK[base]     = pack_h2(v.x, v.y);
        sK[base + 4] = pack_h2(v.z, v.w);
    }
    __syncthreads();
    uint4 qf[6];
    #pragma unroll
    for (int kg = 0; kg < 6; kg++)
        qf[kg] = *(const uint4*)&sK[((wid * 6 + kg) * 32 + lane) * 4];
    __syncthreads();

    float mr0 = -1e30f, mr1 = -1e30f, l0 = 0.f, l1 = 0.f;
    float accO[12][4];
    #pragma unroll
    for (int j = 0; j < 12; j++)
        #pragma unroll
        for (int c = 0; c < 4; c++) accO[j][c] = 0.f;

    for (int kt = 0; kt < 8; kt++) {
        #pragma unroll
        for (int i = 0; i < 12; i++) {
            int idx = tid + 256 * i;
            int r = idx / 24, q = idx % 24;
            int k0 = q * 4;
            int jn = r >> 3, nn = r & 7;
            int kg = k0 >> 4, k8 = (k0 >> 3) & 1, t0 = (k0 >> 1) & 3;
            int base = ((jn * 6 + kg) * 32 + nn * 4 + t0) * 2 + k8;
            float4 v = *(const float4*)(Kg + (long)(kt * 128 + r) * 2304 + k0);
            sK[base]     = pack_h2(v.x, v.y);
            sK[base + 2] = pack_h2(v.z, v.w);
        }
        #pragma unroll
        for (int i = 0; i < 12; i++) {
            int idx = tid + 256 * i;
            int r = idx >> 5, q = idx & 31;
            int k0 = q * 4;
            int jn = r >> 3, nn = r & 7;
            int kg = k0 >> 4, k8 = (k0 >> 3) & 1, t0 = (k0 >> 1) & 3;
            int base = ((jn * 8 + kg) * 32 + nn * 4 + t0) * 2 + k8;
            float4 v = *(const float4*)(Vg + (long)r * 1024 + kt * 128 + k0);
            sV[base]     = pack_h2(v.x, v.y);
            sV[base + 2] = pack_h2(v.z, v.w);
        }
        __syncthreads();

        float accS[16][4];
        #pragma unroll
        for (int j = 0; j < 16; j++)
            #pragma unroll
            for (int c = 0; c < 4; c++) accS[j][c] = 0.f;
        #pragma unroll
        for (int kg = 0; kg < 6; kg++)
            #pragma unroll
            for (int jn = 0; jn < 16; jn++) {
                uint2 bf = *(const uint2*)&sK[((jn * 6 + kg) * 32 + lane) * 2];
                MMAF16(accS[jn], qf[kg], bf);
            }

        float mx0 = -1e30f, mx1 = -1e30f;
        #pragma unroll
        for (int jn = 0; jn < 16; jn++) {
            accS[jn][0] *= scale; accS[jn][1] *= scale;
            accS[jn][2] *= scale; accS[jn][3] *= scale;
            mx0 = fmaxf(mx0, fmaxf(accS[jn][0], accS[jn][1]));
            mx1 = fmaxf(mx1, fmaxf(accS[jn][2], accS[jn][3]));
        }
        mx0 = fmaxf(mx0, __shfl_xor_sync(0xffffffffu, mx0, 1));
        mx0 = fmaxf(mx0, __shfl_xor_sync(0xffffffffu, mx0, 2));
        mx1 = fmaxf(mx1, __shfl_xor_sync(0xffffffffu, mx1, 1));
        mx1 = fmaxf(mx1, __shfl_xor_sync(0xffffffffu, mx1, 2));

        float mn0 = fmaxf(mr0, mx0), mn1 = fmaxf(mr1, mx1);
        float cr0 = fexp(mr0 - mn0), cr1 = fexp(mr1 - mn1);

        float s0 = 0.f, s1 = 0.f;
        uint32_t plo[16], phi[16];
        #pragma unroll
        for (int jn = 0; jn < 16; jn++) {
            float e0 = fexp(accS[jn][0] - mn0);
            float e1 = fexp(accS[jn][1] - mn0);
            float e2 = fexp(accS[jn][2] - mn1);
            float e3 = fexp(accS[jn][3] - mn1);
            s0 += e0 + e1; s1 += e2 + e3;
            plo[jn] = pack_h2(e0, e1);
            phi[jn] = pack_h2(e2, e3);
        }
        s0 += __shfl_xor_sync(0xffffffffu, s0, 1);
        s0 += __shfl_xor_sync(0xffffffffu, s0, 2);
        s1 += __shfl_xor_sync(0xffffffffu, s1, 1);
        s1 += __shfl_xor_sync(0xffffffffu, s1, 2);

        l0 = l0 * cr0 + s0;
        l1 = l1 * cr1 + s1;
        mr0 = mn0; mr1 = mn1;
        #pragma unroll
        for (int j = 0; j < 12; j++) {
            accO[j][0] *= cr0; accO[j][1] *= cr0;
            accO[j][2] *= cr1; accO[j][3] *= cr1;
        }

        #pragma unroll
        for (int kg = 0; kg < 8; kg++) {
            uint4 af = make_uint4(plo[2 * kg], phi[2 * kg], plo[2 * kg + 1], phi[2 * kg + 1]);
            #pragma unroll
            for (int jn = 0; jn < 12; jn++) {
                uint2 bf = *(const uint2*)&sV[((jn * 8 + kg) * 32 + lane) * 2];
                MMAF16(accO[jn], af, bf);
            }
        }
        __syncthreads();
    }

    float inv0 = 1.f / l0, inv1 = 1.f / l1;
    long row0 = (long)(b * 1024 + m0 + wid * 16 + g);
    #pragma unroll
    for (int jn = 0; jn < 12; jn++) {
        int col = h * 96 + jn * 8 + t * 2;
        float2 v0, v1;
        v0.x = accO[jn][0] * inv0; v0.y = accO[jn][1] * inv0;
        v1.x = accO[jn][2] * inv1; v1.y = accO[jn][3] * inv1;
        *(float2*)&ocat[row0 * DIM + col] = v0;
        *(float2*)&ocat[(row0 + 8) * DIM + col] = v1;
    }
}

// ---------------- mma.sync fp16 GEMM, packed-weight B, 2 CTA/SM ----------------
// C = alpha * A[M,K] @ W^T + bias, W packed per 128-N-tile/32-K-chunk blocks.
__global__ __launch_bounds__(256, 2)
void mma_gemm(const float* __restrict__ A, long lda,
              const uint32_t* __restrict__ Wp,
              float* __restrict__ C, long ldc,
              int M, int N, int K,
              const float* __restrict__ bias, float alpha) {
    __shared__ uint32_t sA[2][2048];
    __shared__ uint32_t sB[2][2048];

    int m0 = blockIdx.y * 128, n0 = blockIdx.x * 128;
    int tid = threadIdx.x, lane = tid & 31, wid = tid >> 5;
    int wm = wid & 1, wn = wid >> 1;
    int nch = K >> 5;

    const float* Ab = A + (long)m0 * lda;
    const uint4* Wb = (const uint4*)(Wp + (long)blockIdx.x * nch * 2048);

    int aR[4], aQ[4], aBase[4], aOff[4];
    #pragma unroll
    for (int i = 0; i < 4; i++) {
        int idx = tid + 256 * i;
        int r = idx >> 3, q = idx & 7;
        aR[i] = r; aQ[i] = q;
        int im = r >> 4, g = r & 7, row8 = (r >> 3) & 1;
        int ikf = q >> 2, k8 = (q >> 1) & 1;
        aBase[i] = ((im * 2 + ikf) * 32 + g * 4) * 4 + k8 * 2 + row8;
        aOff[i] = 8 * (q & 1);
    }

    float acc[4][4][4];
    #pragma unroll
    for (int i = 0; i < 4; i++)
        #pragma unroll
        for (int j = 0; j < 4; j++)
            #pragma unroll
            for (int c = 0; c < 4; c++) acc[i][j][c] = 0.f;

    float4 va[4];
    uint4 vb[2];

    // prologue
    #pragma unroll
    for (int i = 0; i < 4; i++)
        va[i] = *(const float4*)(Ab + (long)aR[i] * lda + aQ[i] * 4);
    vb[0] = Wb[tid];
    vb[1] = Wb[tid + 256];
    #pragma unroll
    for (int i = 0; i < 4; i++) {
        uint32_t* s = &sA[0][aBase[i] + aOff[i]];
        s[0] = pack_h2(va[i].x, va[i].y);
        s[4] = pack_h2(va[i].z, va[i].w);
    }
    ((uint4*)sB[0])[tid] = vb[0];
    ((uint4*)sB[0])[tid + 256] = vb[1];
    __syncthreads();

    for (int it = 0; it < nch; it++) {
        int buf = it & 1;
        bool more = (it + 1 < nch);
        if (more) {
            long koff = (long)(it + 1) * 32;
            #pragma unroll
            for (int i = 0; i < 4; i++)
                va[i] = *(const float4*)(Ab + (long)aR[i] * lda + koff + aQ[i] * 4);
            const uint4* Wn = Wb + (long)(it + 1) * 512;
            vb[0] = Wn[tid];
            vb[1] = Wn[tid + 256];
        }
        #pragma unroll
        for (int ikf = 0; ikf < 2; ikf++) {
            uint4 af[4];
            uint2 bf[4];
            #pragma unroll
            for (int i2 = 0; i2 < 4; i2++)
                af[i2] = *(const uint4*)&sA[buf][(((wm * 4 + i2) * 2 + ikf) * 32 + lane) * 4];
            #pragma unroll
            for (int j2 = 0; j2 < 4; j2++)
                bf[j2] = *(const uint2*)&sB[buf][(((wn * 4 + j2) * 2 + ikf) * 32 + lane) * 2];
            #pragma unroll
            for (int i2 = 0; i2 < 4; i2++)
                #pragma unroll
                for (int j2 = 0; j2 < 4; j2++)
                    MMAF16(acc[i2][j2], af[i2], bf[j2]);
        }
        __syncthreads();
        if (more) {
            int nb = buf ^ 1;
            #pragma unroll
            for (int i = 0; i < 4; i++) {
                uint32_t* s = &sA[nb][aBase[i] + aOff[i]];
                s[0] = pack_h2(va[i].x, va[i].y);
                s[4] = pack_h2(va[i].z, va[i].w);
            }
            ((uint4*)sB[nb])[tid] = vb[0];
            ((uint4*)sB[nb])[tid + 256] = vb[1];
            __syncthreads();
        }
    }

    int g = lane >> 2, t = lane & 3;
    #pragma unroll
    for (int i2 = 0; i2 < 4; i2++) {
        int gm = m0 + (wm * 4 + i2) * 16 + g;
        #pragma unroll
        for (int j2 = 0; j2 < 4; j2++) {
            int gn = n0 + (wn * 4 + j2) * 8 + t * 2;
            float b0 = bias ? __ldg(bias + gn) : 0.f;
            float b1 = bias ? __ldg(bias + gn + 1) : 0.f;
            float2 v0, v1;
            v0.x = acc[i2][j2][0] * alpha + b0;
            v0.y = acc[i2][j2][1] * alpha + b1;
            v1.x = acc[i2][j2][2] * alpha + b0;
            v1.y = acc[i2][j2][3] * alpha + b1;
            *(float2*)&C[(long)gm * ldc + gn] = v0;
            *(float2*)&C[(long)(gm + 8) * ldc + gn] = v1;
        }
    }
}

// ---------------- V transpose for flash ----------------
__global__ void transpose_v_kernel(const float* __restrict__ qkv, float* __restrict__ vt) {
    int z = blockIdx.z; int b = z >> 3, h = z & 7;
    __shared__ float tb[32][33];
    int d0 = blockIdx.x * 32, t0 = blockIdx.y * 32;
    int tx = threadIdx.x, ty = threadIdx.y;
    const float* src = qkv + (long)b * 1024 * 2304 + 1536 + h * 96;
    for (int i = ty; i < 32; i += 8)
        tb[i][tx] = src[(long)(t0 + i) * 2304 + d0 + tx];
    __syncthreads();
    float* dst = vt + ((long)z * 96 + d0) * 1024 + t0;
    for (int j = ty; j < 32; j += 8)
        dst[(long)j * 1024 + tx] = tb[tx][j];
}

// ---------------- misc elementwise ----------------
__global__ void copy_kernel(const float* __restrict__ src, float* __restrict__ dst, long n) {
    long i = (long)blockIdx.x * blockDim.x + threadIdx.x;
    long stride = (long)gridDim.x * blockDim.x;
    for (; i < n; i += stride) dst[i] = src[i];
}
__global__ void zero_bytes_kernel(unsigned char* p, long n) {
    long i = (long)blockIdx.x * blockDim.x + threadIdx.x;
    long stride = (long)gridDim.x * blockDim.x;
    int* pi = (int*)p;
    long nw = n >> 2;
    for (; i < nw; i += stride) pi[i] = 0;
}

// ---------------- topk select ----------------
__global__ void topk_select_kernel(const float* __restrict__ sim, int* __restrict__ idx_out) {
    long r = blockIdx.x;
    const float* row = sim + r * SEQ;
    __shared__ float s[SEQ];
    __shared__ float bv[256];
    __shared__ int   bi[256];
    int tid = threadIdx.x;
    for (int i = tid; i < SEQ; i += 256) s[i] = row[i];
    __syncthreads();
    for (int sel = 0; sel < KNEIGH; sel++) {
        float v = -INFINITY; int mi = 0x7fffffff;
        for (int t = tid; t < SEQ; t += 256) {
            float sv = s[t];
            if (sv > v || (sv == v && t < mi)) { v = sv; mi = t; }
        }
        bv[tid] = v; bi[tid] = mi;
        __syncthreads();
        for (int o = 128; o > 0; o >>= 1) {
            if (tid < o) {
                if (bv[tid + o] > bv[tid] || (bv[tid + o] == bv[tid] && bi[tid + o] < bi[tid])) {
                    bv[tid] = bv[tid + o]; bi[tid] = bi[tid + o];
                }
            }
            __syncthreads();
        }
        if (tid == 0) { idx_out[r * KNEIGH + sel] = bi[0]; s[bi[0]] = -INFINITY; }
        __syncthreads();
    }
}

// ---------------- adjacency + degree ----------------
__global__ void scatter_adj_kernel(const int* __restrict__ idx, unsigned char* __restrict__ A) {
    int r = blockIdx.x * blockDim.x + threadIdx.x;
    if (r >= ROWS) return;
    int b = r >> 10, s = r & 1023;
    unsigned char* Ab = A + (long long)b * SEQ * SEQ;
    Ab[(long)s * SEQ + s] = 1;
    #pragma unroll
    for (int j = 0; j < KNEIGH; j++) {
        int t = idx[(long)r * KNEIGH + j];
        Ab[(long)s * SEQ + t] = 1;
        Ab[(long)t * SEQ + s] = 1;
    }
}
__global__ void degree_kernel(const unsigned char* __restrict__ A, float* __restrict__ dinv) {
    int r = blockIdx.x * blockDim.x + threadIdx.x;
    if (r >= ROWS) return;
    const uint32_t* row = (const uint32_t*)(A + (long long)r * SEQ);
    int d = 0;
    for (int i = 0; i < SEQ / 4; i++) {
        uint32_t w = row[i];
        d += (w & 0xff) + ((w >> 8) & 0xff) + ((w >> 16) & 0xff) + ((w >> 24) & 0xff);
    }
    dinv[r] = rsqrtf((float)d);
}

// ---------------- sparse GCN aggregate ----------------
__global__ void gcn_agg_kernel(const unsigned char* __restrict__ A, const float* __restrict__ dinv,
                               const float* __restrict__ xw, const float* __restrict__ gcn_b,
                               float* __restrict__ cat) {
    int r = blockIdx.x;
    int b = r >> 10;
    const unsigned char* Arow = A + (long long)r * SEQ;
    __shared__ int   nbr[SEQ];
    __shared__ float wgt[SEQ];
    __shared__ int cnt;
    int tid = threadIdx.x;
    if (tid == 0) cnt = 0;
    __syncthreads();
    for (int t = tid; t < SEQ; t += 256) {
        if (Arow[t]) {
            int p = atomicAdd(&cnt, 1);
            nbr[p] = t;
            wgt[p] = dinv[(b << 10) + t];
        }
    }
    __syncthreads();
    int n = cnt;
    float acc0 = 0.f, acc1 = 0.f, acc2 = 0.f;
    for (int i = 0; i < n; i++) {
        const float* row = xw + ((long)(b << 10) + nbr[i]) * DIM;
        float w = wgt[i];
        acc0 += w * row[tid];
        acc1 += w * row[tid + 256];
        acc2 += w * row[tid + 512];
    }
    float ws = dinv[r];
    long base = (long)r * (2 * DIM);
    cat[base + tid]       = ws * acc0 + gcn_b[tid];
    cat[base + tid + 256] = ws * acc1 + gcn_b[tid + 256];
    cat[base + tid + 512] = ws * acc2 + gcn_b[tid + 512];
}

// ---------------- SIMT fp32 GEMM (exact sim = x x^T) ----------------
template<bool TRANS_B>
__global__ __launch_bounds__(256, 2)
void gemm_kernel(const float* __restrict__ A, long lda,
                 const float* __restrict__ B, long ldb,
                 float* __restrict__ C, long ldc,
                 int M, int N, int K,
                 const float* __restrict__ bias, float alpha,
                 int batchH,
                 long aOffB, long aOffH, long bOffB, long bOffH, long cOffB, long cOffH) {
    int z = blockIdx.z;
    int bb = z / batchH, hh = z % batchH;
    A += bb * aOffB + hh * aOffH;
    B += bb * bOffB + hh * bOffH;
    C += bb * cOffB + hh * cOffH;
    const int BM = 128, BN = 128, BK = 8;
    __shared__ float As[BK][BM];
    __shared__ float Bs[BK][BN];
    int tid = threadIdx.x;
    int tx = tid & 15, ty = tid >> 4;
    int m0 = blockIdx.y * BM, n0 = blockIdx.x * BN;
    float acc[8][8];
    #pragma unroll
    for (int i = 0; i < 8; i++)
        #pragma unroll
        for (int j = 0; j < 8; j++) acc[i][j] = 0.f;
    for (int k0 = 0; k0 < K; k0 += BK) {
        {
            int m  = tid >> 1;
            int kb = (tid & 1) * 4;
            int gm = m0 + m;
            #pragma unroll
            for (int i = 0; i < 4; i++) {
                int kk = kb + i, gk = k0 + kk;
                As[kk][m] = (gm < M && gk < K) ? A[(long)gm * lda + gk] : 0.f;
            }
        }
        if (!TRANS_B) {
            int kk = tid >> 5, nb = tid & 31, gk = k0 + kk;
            #pragma unroll
            for (int i = 0; i < 4; i++) {
                int n = nb + 32 * i, gn = n0 + n;
                Bs[kk][n] = (gk < K && gn < N) ? B[(long)gk * ldb + gn] : 0.f;
            }
        } else {
            int n = tid >> 1, kb = (tid & 1) * 4, gn = n0 + n;
            #pragma unroll
            for (int i = 0; i < 4; i++) {
                int kk = kb + i, gk = k0 + kk;
                Bs[kk][n] = (gn < N && gk < K) ? B[(long)gn * ldb + gk] : 0.f;
            }
        }
        __syncthreads();
        #pragma unroll
        for (int kk = 0; kk < BK; kk++) {
            float a[8], bvals[8];
            #pragma unroll
            for (int i = 0; i < 8; i++) a[i] = As[kk][ty * 8 + i];
            #pragma unroll
            for (int j = 0; j < 8; j++) bvals[j] = Bs[kk][tx * 8 + j];
            #pragma unroll
            for (int i = 0; i < 8; i++)
                #pragma unroll
                for (int j = 0; j < 8; j++) acc[i][j] += a[i] * bvals[j];
        }
        __syncthreads();
    }
    #pragma unroll
    for (int i = 0; i < 8; i++) {
        int gm = m0 + ty * 8 + i;
        if (gm >= M) continue;
        #pragma unroll
        for (int j = 0; j < 8; j++) {
            int gn = n0 + tx * 8 + j;
            if (gn >= N) continue;
            float v = acc[i][j] * alpha;
            if (bias) v += bias[gn];
            C[(long)gm * ldc + gn] = v;
        }
    }
}

// ---------------- gate + residual + layernorm ----------------
__global__ void fuse_ln_kernel(const float* __restrict__ gatelin, const float* __restrict__ cat,
                               float* __restrict__ h,
                               const float* __restrict__ ln_scale, const float* __restrict__ ln_bias) {
    long r = blockIdx.x;
    int tid = threadIdx.x;
    __shared__ float red[256];
    float f[3];
    #pragma unroll
    for (int i = 0; i < 3; i++) {
        int j = tid + 256 * i;
        float g  = gatelin[r * DIM + j];
        float gc = cat[r * (2 * DIM) + j];
        float at = cat[r * (2 * DIM) + DIM + j];
        float sg = 1.f / (1.f + fexp(-g));
        f[i] = sg * gc + (1.f - sg) * at + h[r * DIM + j];
    }
    float s1 = f[0] + f[1] + f[2];
    red[tid] = s1; __syncthreads();
    #pragma unroll
    for (int o = 128; o > 0; o >>= 1) { if (tid < o) red[tid] += red[tid + o]; __syncthreads(); }
    float mu = red[0] * (1.f / DIM);
    __syncthreads();
    float s2 = 0.f;
    #pragma unroll
    for (int i = 0; i < 3; i++) { float d = f[i] - mu; s2 += d * d; }
    red[tid] = s2; __syncthreads();
    #pragma unroll
    for (int o = 128; o > 0; o >>= 1) { if (tid < o) red[tid] += red[tid + o]; __syncthreads(); }
    float var = red[0] * (1.f / DIM);
    float inv = rsqrtf(var + LN_EPS);
    #pragma unroll
    for (int i = 0; i < 3; i++) {
        int j = tid + 256 * i;
        h[r * DIM + j] = (f[i] - mu) * inv * ln_scale[j] + ln_bias[j];
    }
}

// ---------------- host helper ----------------
static void launch_mma(const float* A, long lda, const uint32_t* Wp,
                       float* C, long ldc, int M, int N, int K,
                       const float* bias, float alpha) {
    dim3 grid(N / 128, M / 128, 1);
    mma_gemm<<<grid, 256>>>(A, lda, Wp, C, ldc, M, N, K, bias, alpha);
}

extern "C" void kernel_launch(void* const* d_in, const int* in_sizes, int n_in,
                              void* d_out, int out_size) {
    const float* x          = (const float*)d_in[0];
    const float* gcn_w      = (const float*)d_in[1];
    const float* gcn_b      = (const float*)d_in[2];
    const float* attn_in_w  = (const float*)d_in[3];
    const float* attn_in_b  = (const float*)d_in[4];
    const float* attn_out_w = (const float*)d_in[5];
    const float* attn_out_b = (const float*)d_in[6];
    const float* gate_w     = (const float*)d_in[7];
    const float* gate_b     = (const float*)d_in[8];
    const float* ln_scale   = (const float*)d_in[9];
    const float* ln_bias    = (const float*)d_in[10];
    const float* proj_w     = (const float*)d_in[11];
    const float* proj_b     = (const float*)d_in[12];
    float* out = (float*)d_out;

    float *p_h, *p_xw, *p_qkv, *p_scores, *p_ocat, *p_cat, *p_gate, *p_dinv, *p_vt;
    uint32_t* p_wp;
    unsigned char* p_adj;
    int* p_topk;
    cudaGetSymbolAddress((void**)&p_h, g_h);
    cudaGetSymbolAddress((void**)&p_xw, g_xw);
    cudaGetSymbolAddress((void**)&p_qkv, g_qkv);
    cudaGetSymbolAddress((void**)&p_scores, g_scores);
    cudaGetSymbolAddress((void**)&p_ocat, g_ocat);
    cudaGetSymbolAddress((void**)&p_cat, g_cat);
    cudaGetSymbolAddress((void**)&p_gate, g_gate);
    cudaGetSymbolAddress((void**)&p_dinv, g_dinv);
    cudaGetSymbolAddress((void**)&p_adj, g_adj);
    cudaGetSymbolAddress((void**)&p_topk, g_topk);
    cudaGetSymbolAddress((void**)&p_wp, g_wp);
    cudaGetSymbolAddress((void**)&p_vt, g_vt);

    const float attn_scale = (float)(1.0 / sqrt((double)HDIM));
    dim3 tb(32, 8);

    // h = x
    copy_kernel<<<1024, 256>>>(x, p_h, (long)ROWS * DIM);

    // pack all weights to fp16 fragment layout (once per launch)
    for (int l = 0; l < NLAYERS; l++) {
        pack_weights_kernel<<<512, 256>>>(gcn_w + (long)l * DIM * DIM, p_wp + WP_GCN(l), DIM, DIM);
        pack_weights_kernel<<<512, 256>>>(attn_in_w + (long)l * DIM * 3 * DIM, p_wp + WP_AIW(l), 3 * DIM, DIM);
        pack_weights_kernel<<<512, 256>>>(attn_out_w + (long)l * DIM * DIM, p_wp + WP_AOW(l), DIM, DIM);
        pack_weights_kernel<<<512, 256>>>(gate_w + (long)l * 2 * DIM * DIM, p_wp + WP_GW(l), DIM, 2 * DIM);
    }
    pack_weights_kernel<<<512, 256>>>(proj_w, p_wp + WP_PROJ, DIM, DIM);

    // sim = x x^T (exact fp32 SIMT), then top-5 select
    {
        dim3 grid(SEQ / 128, SEQ / 128, BATCH);
        gemm_kernel<true><<<grid, 256>>>(x, DIM, x, DIM, p_scores, SEQ,
                                         SEQ, SEQ, DIM, nullptr, 1.f,
                                         1, (long)SEQ * DIM, 0, (long)SEQ * DIM, 0,
                                         (long)SEQ * SEQ, 0);
    }
    topk_select_kernel<<<ROWS, 256>>>(p_scores, p_topk);
    zero_bytes_kernel<<<1024, 256>>>(p_adj, (long long)BATCH * SEQ * SEQ);
    scatter_adj_kernel<<<(ROWS + 255) / 256, 256>>>(p_topk, p_adj);
    degree_kernel<<<(ROWS + 255) / 256, 256>>>(p_adj, p_dinv);

    for (int l = 0; l < NLAYERS; l++) {
        const float* gb  = gcn_b + (long)l * DIM;
        const float* aib = attn_in_b + (long)l * 3 * DIM;
        const float* aob = attn_out_b + (long)l * DIM;
        const float* gtb = gate_b + (long)l * DIM;
        const float* lns = ln_scale + (long)l * DIM;
        const float* lnb = ln_bias + (long)l * DIM;

        // XW = h @ gcn_w[l]
        launch_mma(p_h, DIM, p_wp + WP_GCN(l), p_xw, DIM, ROWS, DIM, DIM, nullptr, 1.f);
        // gcn_out -> cat[:, 0:768]
        gcn_agg_kernel<<<ROWS, 256>>>(p_adj, p_dinv, p_xw, gb, p_cat);
        // qkv = h @ attn_in_w[l] + b
        launch_mma(p_h, DIM, p_wp + WP_AIW(l), p_qkv, 3 * DIM, ROWS, 3 * DIM, DIM, aib, 1.f);
        // V transpose: [64, 96, 1024]
        transpose_v_kernel<<<dim3(3, 32, 64), tb>>>(p_qkv, p_vt);
        // fused flash attention -> ocat
        flash_kernel<<<dim3(1, 8, 64), 256>>>(p_qkv, p_vt, p_ocat, attn_scale);
        // attn_out = O @ attn_out_w[l] + b -> cat[:, 768:1536]
        launch_mma(p_ocat, DIM, p_wp + WP_AOW(l), p_cat + DIM, 2 * DIM, ROWS, DIM, DIM, aob, 1.f);
        // gate_lin = cat @ gate_w[l] + b
        launch_mma(p_cat, 2 * DIM, p_wp + WP_GW(l), p_gate, DIM, ROWS, DIM, 2 * DIM, gtb, 1.f);
        // h = LN(gate*gcn + (1-gate)*attn + h)
        fuse_ln_kernel<<<ROWS, 256>>>(p_gate, p_cat, p_h, lns, lnb);
    }

    // out = h @ proj_w + proj_b
    launch_mma(p_h, DIM, p_wp + WP_PROJ, out, DIM, ROWS, DIM, DIM, proj_b, 1.f);
}

// round 9
// speedup vs baseline: 6.2947x; 1.1615x over previous
#include <cuda_runtime.h>
#include <math.h>
#include <stdint.h>

// ---------------- problem constants ----------------
#define BATCH 8
#define SEQ   1024
#define DIM   768
#define HEADS 8
#define HDIM  96
#define KNEIGH 5
#define NLAYERS 3
#define ROWS (BATCH*SEQ)  // 8192
#define LN_EPS 1e-5f

// ---------------- device scratch (static, allocation-free) ----------------
__device__ float g_h[ROWS * DIM];
__device__ float g_xw[ROWS * DIM];
__device__ float g_qkv[ROWS * 3 * DIM];
__device__ float g_scores[(long long)BATCH * SEQ * SEQ]; // sim workspace (32 MB)
__device__ float g_ocat[ROWS * DIM];
__device__ float g_cat[ROWS * 2 * DIM];   // [gcn | attn] stride 1536
__device__ float g_gate[ROWS * DIM];
__device__ unsigned char g_adj[(long long)BATCH * SEQ * SEQ];    // 8 MB
__device__ float g_dinv[ROWS];
__device__ int   g_topk[ROWS * KNEIGH];
__device__ uint32_t g_wp[6488064];        // fp16 fragment-packed weights (26 MB)
__device__ float g_vt[ROWS * DIM];        // V transposed per (b,h): [64, 96, 1024]

// packed weight word offsets
// per-layer fused blob: [gcn (6 nblk) | attn_in (18 nblk)] x 24 kch x 2048 words
#define WP_FUSED(l) ((long)(l) * 1179648)
#define WP_AOW(l)   (3538944L + (long)(l) * 294912L)
#define WP_GW(l)    (4423680L + (long)(l) * 589824L)
#define WP_PROJ     (6193152L)

// pack two floats to half2 (lo = a, hi = b)
__device__ __forceinline__ uint32_t pack_h2(float a, float b) {
    uint32_t r;
    asm("cvt.rn.f16x2.f32 %0, %2, %1;" : "=r"(r) : "f"(a), "f"(b));
    return r;
}
// unpack halves of a packed f16x2 word to fp32 (no cuda_fp16.h dependency)
__device__ __forceinline__ float h2f_lo(uint32_t h) {
    float f;
    asm("{.reg .b16 lo, hi;\n\t"
        "mov.b32 {lo, hi}, %1;\n\t"
        "cvt.f32.f16 %0, lo;}" : "=f"(f) : "r"(h));
    return f;
}
__device__ __forceinline__ float h2f_hi(uint32_t h) {
    float f;
    asm("{.reg .b16 lo, hi;\n\t"
        "mov.b32 {lo, hi}, %1;\n\t"
        "cvt.f32.f16 %0, hi;}" : "=f"(f) : "r"(h));
    return f;
}

// FMA-only exp (no MUFU)
__device__ __forceinline__ float fexp(float x) {
    x = fmaxf(x, -87.0f);
    float y = x * 1.4426950408889634f;
    int i = __float2int_rn(y);
    float r = (y - (float)i) * 0.6931471805599453f;
    float p = 1.9841270e-4f;
    p = fmaf(p, r, 1.3888889e-3f);
    p = fmaf(p, r, 8.3333333e-3f);
    p = fmaf(p, r, 4.1666667e-2f);
    p = fmaf(p, r, 1.6666667e-1f);
    p = fmaf(p, r, 0.5f);
    p = fmaf(p, r, 1.0f);
    p = fmaf(p, r, 1.0f);
    return p * __int_as_float((i + 127) << 23);
}

#define MMAF16(d, a, b) \
    asm volatile("mma.sync.aligned.m16n8k16.row.col.f32.f16.f16.f32 " \
        "{%0,%1,%2,%3}, {%4,%5,%6,%7}, {%8,%9}, {%0,%1,%2,%3};" \
        : "+f"((d)[0]), "+f"((d)[1]), "+f"((d)[2]), "+f"((d)[3]) \
        : "r"((a).x), "r"((a).y), "r"((a).z), "r"((a).w), \
          "r"((b).x), "r"((b).y))

// ---------------- weight packing: w [K,N] fp32 -> fragment-packed fp16 ----------------
__global__ void pack_weights_kernel(const float* __restrict__ w, uint32_t* __restrict__ wp,
                                    int N, int K) {
    int nch = K >> 5;
    long total = (long)N * (K >> 1);
    for (long tId = (long)blockIdx.x * blockDim.x + threadIdx.x; tId < total;
         tId += (long)gridDim.x * blockDim.x) {
        int n = (int)(tId % N);
        int kp = (int)(tId / N);
        int k = kp * 2;
        float v0 = w[(long)k * N + n];
        float v1 = w[(long)(k + 1) * N + n];
        long blk = (long)(n >> 7) * nch + (k >> 5);
        int nloc = n & 127, kloc = k & 31;
        int widx = ((((nloc >> 3) * 2 + ((kloc >> 4) & 1)) * 32
                     + (nloc & 7) * 4 + ((kloc >> 1) & 3)) * 2) + ((kloc >> 3) & 1);
        wp[blk * 2048 + widx] = pack_h2(v0, v1);
    }
}

// ---------------- sim = x x^T via fp16 hi/lo split (≈fp32 precision) ----------------
// acc = Ahi*Bhi + Ahi*Blo + Alo*Bhi  (lo*lo dropped, ~2^-22 relative)
__global__ __launch_bounds__(256, 2)
void sim_gemm(const float* __restrict__ x, float* __restrict__ scores) {
    __shared__ uint32_t sAh[2048], sAl[2048], sBh[2048], sBl[2048];
    int b = blockIdx.z;
    int m0 = blockIdx.y * 128, n0 = blockIdx.x * 128;
    int tid = threadIdx.x, lane = tid & 31, wid = tid >> 5;
    int wm = wid & 1, wn = wid >> 1;
    const float* Xm = x + (long)b * SEQ * DIM + (long)m0 * DIM;
    const float* Xn = x + (long)b * SEQ * DIM + (long)n0 * DIM;

    int aR[4], aQ[4], aBase[4];
    #pragma unroll
    for (int i = 0; i < 4; i++) {
        int idx = tid + 256 * i;
        int r = idx >> 3, q = idx & 7;
        aR[i] = r; aQ[i] = q;
        int im = r >> 4, g = r & 7, row8 = (r >> 3) & 1;
        int ikf = q >> 2, k8 = (q >> 1) & 1;
        aBase[i] = ((im * 2 + ikf) * 32 + g * 4) * 4 + k8 * 2 + row8 + 8 * (q & 1);
    }
    int bR[4], bQ[4], bBase[4];
    #pragma unroll
    for (int i = 0; i < 4; i++) {
        int idx = tid + 256 * i;
        int r = idx >> 3, q = idx & 7;
        bR[i] = r; bQ[i] = q;
        int in = r >> 3, nn = r & 7;
        int ikf = q >> 2, k8 = (q >> 1) & 1;
        bBase[i] = ((in * 2 + ikf) * 32 + nn * 4) * 2 + k8 + 4 * (q & 1);
    }

    float acc[4][4][4];
    #pragma unroll
    for (int i = 0; i < 4; i++)
        #pragma unroll
        for (int j = 0; j < 4; j++)
            #pragma unroll
            for (int c = 0; c < 4; c++) acc[i][j][c] = 0.f;

    for (int it = 0; it < DIM / 32; it++) {
        long koff = (long)it * 32;
        float4 va[4], vb[4];
        #pragma unroll
        for (int i = 0; i < 4; i++)
            va[i] = *(const float4*)(Xm + (long)aR[i] * DIM + koff + aQ[i] * 4);
        #pragma unroll
        for (int i = 0; i < 4; i++)
            vb[i] = *(const float4*)(Xn + (long)bR[i] * DIM + koff + bQ[i] * 4);
        __syncthreads();   // previous chunk's MMA reads complete before overwrite
        #pragma unroll
        for (int i = 0; i < 4; i++) {
            uint32_t h0 = pack_h2(va[i].x, va[i].y);
            uint32_t h1 = pack_h2(va[i].z, va[i].w);
            uint32_t l0 = pack_h2(va[i].x - h2f_lo(h0), va[i].y - h2f_hi(h0));
            uint32_t l1 = pack_h2(va[i].z - h2f_lo(h1), va[i].w - h2f_hi(h1));
            sAh[aBase[i]] = h0; sAh[aBase[i] + 4] = h1;
            sAl[aBase[i]] = l0; sAl[aBase[i] + 4] = l1;
        }
        #pragma unroll
        for (int i = 0; i < 4; i++) {
            uint32_t h0 = pack_h2(vb[i].x, vb[i].y);
            uint32_t h1 = pack_h2(vb[i].z, vb[i].w);
            uint32_t l0 = pack_h2(vb[i].x - h2f_lo(h0), vb[i].y - h2f_hi(h0));
            uint32_t l1 = pack_h2(vb[i].z - h2f_lo(h1), vb[i].w - h2f_hi(h1));
            sBh[bBase[i]] = h0; sBh[bBase[i] + 2] = h1;
            sBl[bBase[i]] = l0; sBl[bBase[i] + 2] = l1;
        }
        __syncthreads();
        #pragma unroll
        for (int ikf = 0; ikf < 2; ikf++) {
            uint2 bh[4], bl[4];
            #pragma unroll
            for (int j2 = 0; j2 < 4; j2++) {
                int o = (((wn * 4 + j2) * 2 + ikf) * 32 + lane) * 2;
                bh[j2] = *(const uint2*)&sBh[o];
                bl[j2] = *(const uint2*)&sBl[o];
            }
            #pragma unroll
            for (int i2 = 0; i2 < 4; i2++) {
                int o = (((wm * 4 + i2) * 2 + ikf) * 32 + lane) * 4;
                uint4 ah = *(const uint4*)&sAh[o];
                uint4 al = *(const uint4*)&sAl[o];
                #pragma unroll
                for (int j2 = 0; j2 < 4; j2++) {
                    MMAF16(acc[i2][j2], ah, bh[j2]);
                    MMAF16(acc[i2][j2], ah, bl[j2]);
                    MMAF16(acc[i2][j2], al, bh[j2]);
                }
            }
        }
    }

    int g = lane >> 2, t = lane & 3;
    float* C = scores + (long)b * SEQ * SEQ;
    #pragma unroll
    for (int i2 = 0; i2 < 4; i2++) {
        int gm = m0 + (wm * 4 + i2) * 16 + g;
        #pragma unroll
        for (int j2 = 0; j2 < 4; j2++) {
            int gn = n0 + (wn * 4 + j2) * 8 + t * 2;
            *(float2*)&C[(long)gm * SEQ + gn] = make_float2(acc[i2][j2][0], acc[i2][j2][1]);
            *(float2*)&C[(long)(gm + 8) * SEQ + gn] = make_float2(acc[i2][j2][2], acc[i2][j2][3]);
        }
    }
}

// ---------------- flash attention (verified R6) ----------------
__global__ __launch_bounds__(256, 1)
void flash_kernel(const float* __restrict__ qkv, const float* __restrict__ vt,
                  float* __restrict__ ocat, float scale) {
    __shared__ uint32_t sK[6144];
    __shared__ uint32_t sV[6144];
    int z = blockIdx.z, b = z >> 3, h = z & 7;
    int m0 = blockIdx.y * 128;
    int tid = threadIdx.x, lane = tid & 31, wid = tid >> 5;
    int t = lane & 3, g = lane >> 2;

    const float* Qg = qkv + ((long)b * 1024 + m0) * 2304 + h * 96;
    const float* Kg = qkv + (long)b * 1024 * 2304 + 768 + h * 96;
    const float* Vg = vt + (long)z * 96 * 1024;

    #pragma unroll
    for (int i = 0; i < 12; i++) {
        int idx = tid + 256 * i;
        int r = idx / 24, q = idx % 24;
        int k0 = q * 4;
        int im = r >> 4, gg = r & 7, row8 = (r >> 3) & 1;
        int kg = k0 >> 4, k8 = (k0 >> 3) & 1, t0 = (k0 >> 1) & 3;
        int base = ((im * 6 + kg) * 32 + gg * 4 + t0) * 4 + row8 + 2 * k8;
        float4 v = *(const float4*)(Qg + (long)r * 2304 + k0);
        sK[base]     = pack_h2(v.x, v.y);
        sK[base + 4] = pack_h2(v.z, v.w);
    }
    __syncthreads();
    uint4 qf[6];
    #pragma unroll
    for (int kg = 0; kg < 6; kg++)
        qf[kg] = *(const uint4*)&sK[((wid * 6 + kg) * 32 + lane) * 4];
    __syncthreads();

    float mr0 = -1e30f, mr1 = -1e30f, l0 = 0.f, l1 = 0.f;
    float accO[12][4];
    #pragma unroll
    for (int j = 0; j < 12; j++)
        #pragma unroll
        for (int c = 0; c < 4; c++) accO[j][c] = 0.f;

    for (int kt = 0; kt < 8; kt++) {
        #pragma unroll
        for (int i = 0; i < 12; i++) {
            int idx = tid + 256 * i;
            int r = idx / 24, q = idx % 24;
            int k0 = q * 4;
            int jn = r >> 3, nn = r & 7;
            int kg = k0 >> 4, k8 = (k0 >> 3) & 1, t0 = (k0 >> 1) & 3;
            int base = ((jn * 6 + kg) * 32 + nn * 4 + t0) * 2 + k8;
            float4 v = *(const float4*)(Kg + (long)(kt * 128 + r) * 2304 + k0);
            sK[base]     = pack_h2(v.x, v.y);
            sK[base + 2] = pack_h2(v.z, v.w);
        }
        #pragma unroll
        for (int i = 0; i < 12; i++) {
            int idx = tid + 256 * i;
            int r = idx >> 5, q = idx & 31;
            int k0 = q * 4;
            int jn = r >> 3, nn = r & 7;
            int kg = k0 >> 4, k8 = (k0 >> 3) & 1, t0 = (k0 >> 1) & 3;
            int base = ((jn * 8 + kg) * 32 + nn * 4 + t0) * 2 + k8;
            float4 v = *(const float4*)(Vg + (long)r * 1024 + kt * 128 + k0);
            sV[base]     = pack_h2(v.x, v.y);
            sV[base + 2] = pack_h2(v.z, v.w);
        }
        __syncthreads();

        float accS[16][4];
        #pragma unroll
        for (int j = 0; j < 16; j++)
            #pragma unroll
            for (int c = 0; c < 4; c++) accS[j][c] = 0.f;
        #pragma unroll
        for (int kg = 0; kg < 6; kg++)
            #pragma unroll
            for (int jn = 0; jn < 16; jn++) {
                uint2 bf = *(const uint2*)&sK[((jn * 6 + kg) * 32 + lane) * 2];
                MMAF16(accS[jn], qf[kg], bf);
            }

        float mx0 = -1e30f, mx1 = -1e30f;
        #pragma unroll
        for (int jn = 0; jn < 16; jn++) {
            accS[jn][0] *= scale; accS[jn][1] *= scale;
            accS[jn][2] *= scale; accS[jn][3] *= scale;
            mx0 = fmaxf(mx0, fmaxf(accS[jn][0], accS[jn][1]));
            mx1 = fmaxf(mx1, fmaxf(accS[jn][2], accS[jn][3]));
        }
        mx0 = fmaxf(mx0, __shfl_xor_sync(0xffffffffu, mx0, 1));
        mx0 = fmaxf(mx0, __shfl_xor_sync(0xffffffffu, mx0, 2));
        mx1 = fmaxf(mx1, __shfl_xor_sync(0xffffffffu, mx1, 1));
        mx1 = fmaxf(mx1, __shfl_xor_sync(0xffffffffu, mx1, 2));

        float mn0 = fmaxf(mr0, mx0), mn1 = fmaxf(mr1, mx1);
        float cr0 = fexp(mr0 - mn0), cr1 = fexp(mr1 - mn1);

        float s0 = 0.f, s1 = 0.f;
        uint32_t plo[16], phi[16];
        #pragma unroll
        for (int jn = 0; jn < 16; jn++) {
            float e0 = fexp(accS[jn][0] - mn0);
            float e1 = fexp(accS[jn][1] - mn0);
            float e2 = fexp(accS[jn][2] - mn1);
            float e3 = fexp(accS[jn][3] - mn1);
            s0 += e0 + e1; s1 += e2 + e3;
            plo[jn] = pack_h2(e0, e1);
            phi[jn] = pack_h2(e2, e3);
        }
        s0 += __shfl_xor_sync(0xffffffffu, s0, 1);
        s0 += __shfl_xor_sync(0xffffffffu, s0, 2);
        s1 += __shfl_xor_sync(0xffffffffu, s1, 1);
        s1 += __shfl_xor_sync(0xffffffffu, s1, 2);

        l0 = l0 * cr0 + s0;
        l1 = l1 * cr1 + s1;
        mr0 = mn0; mr1 = mn1;
        #pragma unroll
        for (int j = 0; j < 12; j++) {
            accO[j][0] *= cr0; accO[j][1] *= cr0;
            accO[j][2] *= cr1; accO[j][3] *= cr1;
        }

        #pragma unroll
        for (int kg = 0; kg < 8; kg++) {
            uint4 af = make_uint4(plo[2 * kg], phi[2 * kg], plo[2 * kg + 1], phi[2 * kg + 1]);
            #pragma unroll
            for (int jn = 0; jn < 12; jn++) {
                uint2 bf = *(const uint2*)&sV[((jn * 8 + kg) * 32 + lane) * 2];
                MMAF16(accO[jn], af, bf);
            }
        }
        __syncthreads();
    }

    float inv0 = 1.f / l0, inv1 = 1.f / l1;
    long row0 = (long)(b * 1024 + m0 + wid * 16 + g);
    #pragma unroll
    for (int jn = 0; jn < 12; jn++) {
        int col = h * 96 + jn * 8 + t * 2;
        float2 v0, v1;
        v0.x = accO[jn][0] * inv0; v0.y = accO[jn][1] * inv0;
        v1.x = accO[jn][2] * inv1; v1.y = accO[jn][3] * inv1;
        *(float2*)&ocat[row0 * DIM + col] = v0;
        *(float2*)&ocat[(row0 + 8) * DIM + col] = v1;
    }
}

// ---------------- mma.sync fp16 GEMM, packed-weight B, dual-output routing ----------------
// n-blocks [0, nsplit) -> C0/bias0/ldc0 ; n-blocks >= nsplit -> C1/bias1/ldc1
__global__ __launch_bounds__(256, 2)
void mma_gemm(const float* __restrict__ A, long lda,
              const uint32_t* __restrict__ Wp,
              float* __restrict__ C0, long ldc0, const float* __restrict__ bias0, int nsplit,
              float* __restrict__ C1, long ldc1, const float* __restrict__ bias1,
              int M, int K) {
    __shared__ uint32_t sA[2][2048];
    __shared__ uint32_t sB[2][2048];

    int m0 = blockIdx.y * 128;
    int tid = threadIdx.x, lane = tid & 31, wid = tid >> 5;
    int wm = wid & 1, wn = wid >> 1;
    int nch = K >> 5;

    const float* Ab = A + (long)m0 * lda;
    const uint4* Wb = (const uint4*)(Wp + (long)blockIdx.x * nch * 2048);

    int aR[4], aQ[4], aBase[4];
    #pragma unroll
    for (int i = 0; i < 4; i++) {
        int idx = tid + 256 * i;
        int r = idx >> 3, q = idx & 7;
        aR[i] = r; aQ[i] = q;
        int im = r >> 4, g = r & 7, row8 = (r >> 3) & 1;
        int ikf = q >> 2, k8 = (q >> 1) & 1;
        aBase[i] = ((im * 2 + ikf) * 32 + g * 4) * 4 + k8 * 2 + row8 + 8 * (q & 1);
    }

    float acc[4][4][4];
    #pragma unroll
    for (int i = 0; i < 4; i++)
        #pragma unroll
        for (int j = 0; j < 4; j++)
            #pragma unroll
            for (int c = 0; c < 4; c++) acc[i][j][c] = 0.f;

    float4 va[4];
    uint4 vb[2];

    #pragma unroll
    for (int i = 0; i < 4; i++)
        va[i] = *(const float4*)(Ab + (long)aR[i] * lda + aQ[i] * 4);
    vb[0] = Wb[tid];
    vb[1] = Wb[tid + 256];
    #pragma unroll
    for (int i = 0; i < 4; i++) {
        uint32_t* s = &sA[0][aBase[i]];
        s[0] = pack_h2(va[i].x, va[i].y);
        s[4] = pack_h2(va[i].z, va[i].w);
    }
    ((uint4*)sB[0])[tid] = vb[0];
    ((uint4*)sB[0])[tid + 256] = vb[1];
    __syncthreads();

    for (int it = 0; it < nch; it++) {
        int buf = it & 1;
        bool more = (it + 1 < nch);
        if (more) {
            long koff = (long)(it + 1) * 32;
            #pragma unroll
            for (int i = 0; i < 4; i++)
                va[i] = *(const float4*)(Ab + (long)aR[i] * lda + koff + aQ[i] * 4);
            const uint4* Wn = Wb + (long)(it + 1) * 512;
            vb[0] = Wn[tid];
            vb[1] = Wn[tid + 256];
        }
        #pragma unroll
        for (int ikf = 0; ikf < 2; ikf++) {
            uint4 af[4];
            uint2 bf[4];
            #pragma unroll
            for (int i2 = 0; i2 < 4; i2++)
                af[i2] = *(const uint4*)&sA[buf][(((wm * 4 + i2) * 2 + ikf) * 32 + lane) * 4];
            #pragma unroll
            for (int j2 = 0; j2 < 4; j2++)
                bf[j2] = *(const uint2*)&sB[buf][(((wn * 4 + j2) * 2 + ikf) * 32 + lane) * 2];
            #pragma unroll
            for (int i2 = 0; i2 < 4; i2++)
                #pragma unroll
                for (int j2 = 0; j2 < 4; j2++)
                    MMAF16(acc[i2][j2], af[i2], bf[j2]);
        }
        __syncthreads();
        if (more) {
            int nb = buf ^ 1;
            #pragma unroll
            for (int i = 0; i < 4; i++) {
                uint32_t* s = &sA[nb][aBase[i]];
                s[0] = pack_h2(va[i].x, va[i].y);
                s[4] = pack_h2(va[i].z, va[i].w);
            }
            ((uint4*)sB[nb])[tid] = vb[0];
            ((uint4*)sB[nb])[tid + 256] = vb[1];
            __syncthreads();
        }
    }

    float* C; long ldc; const float* bias; int n0;
    if ((int)blockIdx.x < nsplit) {
        C = C0; ldc = ldc0; bias = bias0; n0 = blockIdx.x * 128;
    } else {
        C = C1; ldc = ldc1; bias = bias1; n0 = (blockIdx.x - nsplit) * 128;
    }
    int g = lane >> 2, t = lane & 3;
    #pragma unroll
    for (int i2 = 0; i2 < 4; i2++) {
        int gm = m0 + (wm * 4 + i2) * 16 + g;
        #pragma unroll
        for (int j2 = 0; j2 < 4; j2++) {
            int gn = n0 + (wn * 4 + j2) * 8 + t * 2;
            float b0 = __ldg(bias + gn);
            float b1 = __ldg(bias + gn + 1);
            float2 v0, v1;
            v0.x = acc[i2][j2][0] + b0;
            v0.y = acc[i2][j2][1] + b1;
            v1.x = acc[i2][j2][2] + b0;
            v1.y = acc[i2][j2][3] + b1;
            *(float2*)&C[(long)gm * ldc + gn] = v0;
            *(float2*)&C[(long)(gm + 8) * ldc + gn] = v1;
        }
    }
}

// ---------------- V transpose for flash ----------------
__global__ void transpose_v_kernel(const float* __restrict__ qkv, float* __restrict__ vt) {
    int z = blockIdx.z; int b = z >> 3, h = z & 7;
    __shared__ float tb[32][33];
    int d0 = blockIdx.x * 32, t0 = blockIdx.y * 32;
    int tx = threadIdx.x, ty = threadIdx.y;
    const float* src = qkv + (long)b * 1024 * 2304 + 1536 + h * 96;
    for (int i = ty; i < 32; i += 8)
        tb[i][tx] = src[(long)(t0 + i) * 2304 + d0 + tx];
    __syncthreads();
    float* dst = vt + ((long)z * 96 + d0) * 1024 + t0;
    for (int j = ty; j < 32; j += 8)
        dst[(long)j * 1024 + tx] = tb[tx][j];
}

// ---------------- misc ----------------
__global__ void zero_bytes_kernel(unsigned char* p, long n) {
    long i = (long)blockIdx.x * blockDim.x + threadIdx.x;
    long stride = (long)gridDim.x * blockDim.x;
    int* pi = (int*)p;
    long nw = n >> 2;
    for (; i < nw; i += stride) pi[i] = 0;
}

// ---------------- topk select ----------------
__global__ void topk_select_kernel(const float* __restrict__ sim, int* __restrict__ idx_out) {
    long r = blockIdx.x;
    const float* row = sim + r * SEQ;
    __shared__ float s[SEQ];
    __shared__ float bv[256];
    __shared__ int   bi[256];
    int tid = threadIdx.x;
    for (int i = tid; i < SEQ; i += 256) s[i] = row[i];
    __syncthreads();
    for (int sel = 0; sel < KNEIGH; sel++) {
        float v = -INFINITY; int mi = 0x7fffffff;
        for (int t = tid; t < SEQ; t += 256) {
            float sv = s[t];
            if (sv > v || (sv == v && t < mi)) { v = sv; mi = t; }
        }
        bv[tid] = v; bi[tid] = mi;
        __syncthreads();
        for (int o = 128; o > 0; o >>= 1) {
            if (tid < o) {
                if (bv[tid + o] > bv[tid] || (bv[tid + o] == bv[tid] && bi[tid + o] < bi[tid])) {
                    bv[tid] = bv[tid + o]; bi[tid] = bi[tid + o];
                }
            }
            __syncthreads();
        }
        if (tid == 0) { idx_out[r * KNEIGH + sel] = bi[0]; s[bi[0]] = -INFINITY; }
        __syncthreads();
    }
}

// ---------------- adjacency + degree ----------------
__global__ void scatter_adj_kernel(const int* __restrict__ idx, unsigned char* __restrict__ A) {
    int r = blockIdx.x * blockDim.x + threadIdx.x;
    if (r >= ROWS) return;
    int b = r >> 10, s = r & 1023;
    unsigned char* Ab = A + (long long)b * SEQ * SEQ;
    Ab[(long)s * SEQ + s] = 1;
    #pragma unroll
    for (int j = 0; j < KNEIGH; j++) {
        int t = idx[(long)r * KNEIGH + j];
        Ab[(long)s * SEQ + t] = 1;
        Ab[(long)t * SEQ + s] = 1;
    }
}
__global__ void degree_kernel(const unsigned char* __restrict__ A, float* __restrict__ dinv) {
    int r = blockIdx.x * blockDim.x + threadIdx.x;
    if (r >= ROWS) return;
    const uint32_t* row = (const uint32_t*)(A + (long long)r * SEQ);
    int d = 0;
    for (int i = 0; i < SEQ / 4; i++) {
        uint32_t w = row[i];
        d += (w & 0xff) + ((w >> 8) & 0xff) + ((w >> 16) & 0xff) + ((w >> 24) & 0xff);
    }
    dinv[r] = rsqrtf((float)d);
}

// ---------------- sparse GCN aggregate ----------------
__global__ void gcn_agg_kernel(const unsigned char* __restrict__ A, const float* __restrict__ dinv,
                               const float* __restrict__ xw, const float* __restrict__ gcn_b,
                               float* __restrict__ cat) {
    int r = blockIdx.x;
    int b = r >> 10;
    const unsigned char* Arow = A + (long long)r * SEQ;
    __shared__ int   nbr[SEQ];
    __shared__ float wgt[SEQ];
    __shared__ int cnt;
    int tid = threadIdx.x;
    if (tid == 0) cnt = 0;
    __syncthreads();
    for (int t = tid; t < SEQ; t += 256) {
        if (Arow[t]) {
            int p = atomicAdd(&cnt, 1);
            nbr[p] = t;
            wgt[p] = dinv[(b << 10) + t];
        }
    }
    __syncthreads();
    int n = cnt;
    float acc0 = 0.f, acc1 = 0.f, acc2 = 0.f;
    for (int i = 0; i < n; i++) {
        const float* row = xw + ((long)(b << 10) + nbr[i]) * DIM;
        float w = wgt[i];
        acc0 += w * row[tid];
        acc1 += w * row[tid + 256];
        acc2 += w * row[tid + 512];
    }
    float ws = dinv[r];
    long base = (long)r * (2 * DIM);
    cat[base + tid]       = ws * acc0 + gcn_b[tid];
    cat[base + tid + 256] = ws * acc1 + gcn_b[tid + 256];
    cat[base + tid + 512] = ws * acc2 + gcn_b[tid + 512];
}

// ---------------- gate + residual + layernorm ----------------
__global__ void fuse_ln_kernel(const float* __restrict__ gatelin, const float* __restrict__ cat,
                               const float* __restrict__ hin, float* __restrict__ hout,
                               const float* __restrict__ ln_scale, const float* __restrict__ ln_bias) {
    long r = blockIdx.x;
    int tid = threadIdx.x;
    __shared__ float red[256];
    float f[3];
    #pragma unroll
    for (int i = 0; i < 3; i++) {
        int j = tid + 256 * i;
        float g  = gatelin[r * DIM + j];
        float gc = cat[r * (2 * DIM) + j];
        float at = cat[r * (2 * DIM) + DIM + j];
        float sg = 1.f / (1.f + fexp(-g));
        f[i] = sg * gc + (1.f - sg) * at + hin[r * DIM + j];
    }
    float s1 = f[0] + f[1] + f[2];
    red[tid] = s1; __syncthreads();
    #pragma unroll
    for (int o = 128; o > 0; o >>= 1) { if (tid < o) red[tid] += red[tid + o]; __syncthreads(); }
    float mu = red[0] * (1.f / DIM);
    __syncthreads();
    float s2 = 0.f;
    #pragma unroll
    for (int i = 0; i < 3; i++) { float d = f[i] - mu; s2 += d * d; }
    red[tid] = s2; __syncthreads();
    #pragma unroll
    for (int o = 128; o > 0; o >>= 1) { if (tid < o) red[tid] += red[tid + o]; __syncthreads(); }
    float var = red[0] * (1.f / DIM);
    float inv = rsqrtf(var + LN_EPS);
    #pragma unroll
    for (int i = 0; i < 3; i++) {
        int j = tid + 256 * i;
        hout[r * DIM + j] = (f[i] - mu) * inv * ln_scale[j] + ln_bias[j];
    }
}

// ---------------- host helper ----------------
static void launch_mma(const float* A, const uint32_t* Wp, float* C, long ldc,
                       const float* bias, int M, int N, int K) {
    dim3 grid(N / 128, M / 128, 1);
    mma_gemm<<<grid, 256>>>(A, K, Wp, C, ldc, bias, N / 128, C, ldc, bias, M, K);
}

extern "C" void kernel_launch(void* const* d_in, const int* in_sizes, int n_in,
                              void* d_out, int out_size) {
    const float* x          = (const float*)d_in[0];
    const float* gcn_w      = (const float*)d_in[1];
    const float* gcn_b      = (const float*)d_in[2];
    const float* attn_in_w  = (const float*)d_in[3];
    const float* attn_in_b  = (const float*)d_in[4];
    const float* attn_out_w = (const float*)d_in[5];
    const float* attn_out_b = (const float*)d_in[6];
    const float* gate_w     = (const float*)d_in[7];
    const float* gate_b     = (const float*)d_in[8];
    const float* ln_scale   = (const float*)d_in[9];
    const float* ln_bias    = (const float*)d_in[10];
    const float* proj_w     = (const float*)d_in[11];
    const float* proj_b     = (const float*)d_in[12];
    float* out = (float*)d_out;

    float *p_h, *p_xw, *p_qkv, *p_scores, *p_ocat, *p_cat, *p_gate, *p_dinv, *p_vt;
    uint32_t* p_wp;
    unsigned char* p_adj;
    int* p_topk;
    cudaGetSymbolAddress((void**)&p_h, g_h);
    cudaGetSymbolAddress((void**)&p_xw, g_xw);
    cudaGetSymbolAddress((void**)&p_qkv, g_qkv);
    cudaGetSymbolAddress((void**)&p_scores, g_scores);
    cudaGetSymbolAddress((void**)&p_ocat, g_ocat);
    cudaGetSymbolAddress((void**)&p_cat, g_cat);
    cudaGetSymbolAddress((void**)&p_gate, g_gate);
    cudaGetSymbolAddress((void**)&p_dinv, g_dinv);
    cudaGetSymbolAddress((void**)&p_adj, g_adj);
    cudaGetSymbolAddress((void**)&p_topk, g_topk);
    cudaGetSymbolAddress((void**)&p_wp, g_wp);
    cudaGetSymbolAddress((void**)&p_vt, g_vt);

    const float attn_scale = (float)(1.0 / sqrt((double)HDIM));
    dim3 tb(32, 8);

    // pack all weights to fp16 fragment layout (once per launch)
    for (int l = 0; l < NLAYERS; l++) {
        pack_weights_kernel<<<512, 256>>>(gcn_w + (long)l * DIM * DIM, p_wp + WP_FUSED(l), DIM, DIM);
        pack_weights_kernel<<<512, 256>>>(attn_in_w + (long)l * DIM * 3 * DIM,
                                          p_wp + WP_FUSED(l) + 294912, 3 * DIM, DIM);
        pack_weights_kernel<<<512, 256>>>(attn_out_w + (long)l * DIM * DIM, p_wp + WP_AOW(l), DIM, DIM);
        pack_weights_kernel<<<512, 256>>>(gate_w + (long)l * 2 * DIM * DIM, p_wp + WP_GW(l), DIM, 2 * DIM);
    }
    pack_weights_kernel<<<512, 256>>>(proj_w, p_wp + WP_PROJ, DIM, DIM);

    // sim = x x^T via fp16 hi/lo split tensor cores, then top-5 select
    sim_gemm<<<dim3(8, 8, BATCH), 256>>>(x, p_scores);
    topk_select_kernel<<<ROWS, 256>>>(p_scores, p_topk);
    zero_bytes_kernel<<<1024, 256>>>(p_adj, (long long)BATCH * SEQ * SEQ);
    scatter_adj_kernel<<<(ROWS + 255) / 256, 256>>>(p_topk, p_adj);
    degree_kernel<<<(ROWS + 255) / 256, 256>>>(p_adj, p_dinv);

    for (int l = 0; l < NLAYERS; l++) {
        const float* gb  = gcn_b + (long)l * DIM;
        const float* aib = attn_in_b + (long)l * 3 * DIM;
        const float* aob = attn_out_b + (long)l * DIM;
        const float* gtb = gate_b + (long)l * DIM;
        const float* lns = ln_scale + (long)l * DIM;
        const float* lnb = ln_bias + (long)l * DIM;
        const float* hin = (l == 0) ? x : p_h;

        // fused: XW -> xw (n-blocks 0-5), QKV -> qkv (n-blocks 6-23)
        {
            dim3 grid(24, ROWS / 128, 1);
            mma_gemm<<<grid, 256>>>(hin, DIM, p_wp + WP_FUSED(l),
                                    p_xw, DIM, gb, 6,
                                    p_qkv, 3 * DIM, aib,
                                    ROWS, DIM);
        }
        // gcn_out -> cat[:, 0:768]
        gcn_agg_kernel<<<ROWS, 256>>>(p_adj, p_dinv, p_xw, gb, p_cat);
        // V transpose: [64, 96, 1024]
        transpose_v_kernel<<<dim3(3, 32, 64), tb>>>(p_qkv, p_vt);
        // fused flash attention -> ocat
        flash_kernel<<<dim3(1, 8, 64), 256>>>(p_qkv, p_vt, p_ocat, attn_scale);
        // attn_out = O @ attn_out_w[l] + b -> cat[:, 768:1536]
        launch_mma(p_ocat, p_wp + WP_AOW(l), p_cat + DIM, 2 * DIM, aob, ROWS, DIM, DIM);
        // gate_lin = cat @ gate_w[l] + b
        launch_mma(p_cat, p_wp + WP_GW(l), p_gate, DIM, gtb, ROWS, DIM, 2 * DIM);
        // h = LN(gate*gcn + (1-gate)*attn + hin)
        fuse_ln_kernel<<<ROWS, 256>>>(p_gate, p_cat, hin, p_h, lns, lnb);
    }

    // out = h @ proj_w + proj_b
    launch_mma(p_h, p_wp + WP_PROJ, out, DIM, proj_b, ROWS, DIM, DIM);
}

// round 10
// speedup vs baseline: 6.9732x; 1.1078x over previous
#include <cuda_runtime.h>
#include <math.h>
#include <stdint.h>

// ---------------- problem constants ----------------
#define BATCH 8
#define SEQ   1024
#define DIM   768
#define HEADS 8
#define HDIM  96
#define KNEIGH 5
#define NLAYERS 3
#define ROWS (BATCH*SEQ)  // 8192
#define LN_EPS 1e-5f

// ---------------- device scratch (static, allocation-free) ----------------
__device__ float g_h[ROWS * DIM];
__device__ float g_xw[ROWS * DIM];
__device__ float g_qkv[ROWS * 3 * DIM];
__device__ float g_scores[(long long)BATCH * SEQ * SEQ]; // sim workspace (32 MB)
__device__ float g_ocat[ROWS * DIM];
__device__ float g_cat[ROWS * 2 * DIM];   // [gcn | attn] stride 1536
__device__ float g_gate[ROWS * DIM];
__device__ unsigned char g_adj[(long long)BATCH * SEQ * SEQ];    // 8 MB
__device__ float g_dinv[ROWS];
__device__ int   g_topk[ROWS * KNEIGH];
__device__ uint32_t g_wp[6488064];        // fp16 fragment-packed weights (26 MB)
__device__ uint32_t g_ap[6291456];        // fp16 fragment-packed activations (25 MB)
__device__ float g_vt[ROWS * DIM];        // V transposed per (b,h): [64, 96, 1024]

// packed weight word offsets
// per-layer fused blob: [gcn (6 nblk) | attn_in (18 nblk)] x 24 kch x 2048 words
#define WP_FUSED(l) ((long)(l) * 1179648)
#define WP_AOW(l)   (3538944L + (long)(l) * 294912L)
#define WP_GW(l)    (4423680L + (long)(l) * 589824L)
#define WP_PROJ     (6193152L)

// pack two floats to half2 (lo = a, hi = b)
__device__ __forceinline__ uint32_t pack_h2(float a, float b) {
    uint32_t r;
    asm("cvt.rn.f16x2.f32 %0, %2, %1;" : "=r"(r) : "f"(a), "f"(b));
    return r;
}
// unpack halves of a packed f16x2 word to fp32 (no cuda_fp16.h dependency)
__device__ __forceinline__ float h2f_lo(uint32_t h) {
    float f;
    asm("{.reg .b16 lo, hi;\n\t"
        "mov.b32 {lo, hi}, %1;\n\t"
        "cvt.f32.f16 %0, lo;}" : "=f"(f) : "r"(h));
    return f;
}
__device__ __forceinline__ float h2f_hi(uint32_t h) {
    float f;
    asm("{.reg .b16 lo, hi;\n\t"
        "mov.b32 {lo, hi}, %1;\n\t"
        "cvt.f32.f16 %0, hi;}" : "=f"(f) : "r"(h));
    return f;
}

// FMA-only exp (no MUFU)
__device__ __forceinline__ float fexp(float x) {
    x = fmaxf(x, -87.0f);
    float y = x * 1.4426950408889634f;
    int i = __float2int_rn(y);
    float r = (y - (float)i) * 0.6931471805599453f;
    float p = 1.9841270e-4f;
    p = fmaf(p, r, 1.3888889e-3f);
    p = fmaf(p, r, 8.3333333e-3f);
    p = fmaf(p, r, 4.1666667e-2f);
    p = fmaf(p, r, 1.6666667e-1f);
    p = fmaf(p, r, 0.5f);
    p = fmaf(p, r, 1.0f);
    p = fmaf(p, r, 1.0f);
    return p * __int_as_float((i + 127) << 23);
}

#define MMAF16(d, a, b) \
    asm volatile("mma.sync.aligned.m16n8k16.row.col.f32.f16.f16.f32 " \
        "{%0,%1,%2,%3}, {%4,%5,%6,%7}, {%8,%9}, {%0,%1,%2,%3};" \
        : "+f"((d)[0]), "+f"((d)[1]), "+f"((d)[2]), "+f"((d)[3]) \
        : "r"((a).x), "r"((a).y), "r"((a).z), "r"((a).w), \
          "r"((b).x), "r"((b).y))

// ---------------- weight packing: w [K,N] fp32 -> fragment-packed fp16 (B-layout) ----------------
__global__ void pack_weights_kernel(const float* __restrict__ w, uint32_t* __restrict__ wp,
                                    int N, int K) {
    int nch = K >> 5;
    long total = (long)N * (K >> 1);
    for (long tId = (long)blockIdx.x * blockDim.x + threadIdx.x; tId < total;
         tId += (long)gridDim.x * blockDim.x) {
        int n = (int)(tId % N);
        int kp = (int)(tId / N);
        int k = kp * 2;
        float v0 = w[(long)k * N + n];
        float v1 = w[(long)(k + 1) * N + n];
        long blk = (long)(n >> 7) * nch + (k >> 5);
        int nloc = n & 127, kloc = k & 31;
        int widx = ((((nloc >> 3) * 2 + ((kloc >> 4) & 1)) * 32
                     + (nloc & 7) * 4 + ((kloc >> 1) & 3)) * 2) + ((kloc >> 3) & 1);
        wp[blk * 2048 + widx] = pack_h2(v0, v1);
    }
}

// ---------------- activation packing: act [M,K] fp32 -> fragment-packed fp16 (A-layout) ----------------
// blob word for (r local in 128-block, k local in 32-chunk):
//   w = (im*2+ikf)*128 + (g*4+t)*4 + (row8 + 2*k8), with r=im*16+row8*8+g, k=ikf*16+k8*8+t*2
__global__ void pack_act_kernel(const float* __restrict__ act, uint32_t* __restrict__ blob,
                                int K) {
    int kch = blockIdx.x, mblk = blockIdx.y;
    int nch = gridDim.x;
    const float* a0 = act + (long)mblk * 128 * K + kch * 32;
    uint32_t* out = blob + ((long)mblk * nch + kch) * 2048;
    int tid = threadIdx.x;
    #pragma unroll
    for (int i = 0; i < 8; i++) {
        int w = tid + 256 * i;
        int c = w & 3, lanep = (w >> 2) & 31, ikf = (w >> 7) & 1, im = w >> 8;
        int r = im * 16 + (c & 1) * 8 + (lanep >> 2);
        int k = ikf * 16 + ((c >> 1) & 1) * 8 + (lanep & 3) * 2;
        float2 v = *(const float2*)(a0 + (long)r * K + k);
        out[w] = pack_h2(v.x, v.y);
    }
}

// ---------------- sim = x x^T via fp16 hi/lo split (≈fp32 precision, verified R9) ----------------
__global__ __launch_bounds__(256, 2)
void sim_gemm(const float* __restrict__ x, float* __restrict__ scores) {
    __shared__ uint32_t sAh[2048], sAl[2048], sBh[2048], sBl[2048];
    int b = blockIdx.z;
    int m0 = blockIdx.y * 128, n0 = blockIdx.x * 128;
    int tid = threadIdx.x, lane = tid & 31, wid = tid >> 5;
    int wm = wid & 1, wn = wid >> 1;
    const float* Xm = x + (long)b * SEQ * DIM + (long)m0 * DIM;
    const float* Xn = x + (long)b * SEQ * DIM + (long)n0 * DIM;

    int aR[4], aQ[4], aBase[4];
    #pragma unroll
    for (int i = 0; i < 4; i++) {
        int idx = tid + 256 * i;
        int r = idx >> 3, q = idx & 7;
        aR[i] = r; aQ[i] = q;
        int im = r >> 4, g = r & 7, row8 = (r >> 3) & 1;
        int ikf = q >> 2, k8 = (q >> 1) & 1;
        aBase[i] = ((im * 2 + ikf) * 32 + g * 4) * 4 + k8 * 2 + row8 + 8 * (q & 1);
    }
    int bR[4], bQ[4], bBase[4];
    #pragma unroll
    for (int i = 0; i < 4; i++) {
        int idx = tid + 256 * i;
        int r = idx >> 3, q = idx & 7;
        bR[i] = r; bQ[i] = q;
        int in = r >> 3, nn = r & 7;
        int ikf = q >> 2, k8 = (q >> 1) & 1;
        bBase[i] = ((in * 2 + ikf) * 32 + nn * 4) * 2 + k8 + 4 * (q & 1);
    }

    float acc[4][4][4];
    #pragma unroll
    for (int i = 0; i < 4; i++)
        #pragma unroll
        for (int j = 0; j < 4; j++)
            #pragma unroll
            for (int c = 0; c < 4; c++) acc[i][j][c] = 0.f;

    for (int it = 0; it < DIM / 32; it++) {
        long koff = (long)it * 32;
        float4 va[4], vb[4];
        #pragma unroll
        for (int i = 0; i < 4; i++)
            va[i] = *(const float4*)(Xm + (long)aR[i] * DIM + koff + aQ[i] * 4);
        #pragma unroll
        for (int i = 0; i < 4; i++)
            vb[i] = *(const float4*)(Xn + (long)bR[i] * DIM + koff + bQ[i] * 4);
        __syncthreads();
        #pragma unroll
        for (int i = 0; i < 4; i++) {
            uint32_t h0 = pack_h2(va[i].x, va[i].y);
            uint32_t h1 = pack_h2(va[i].z, va[i].w);
            uint32_t l0 = pack_h2(va[i].x - h2f_lo(h0), va[i].y - h2f_hi(h0));
            uint32_t l1 = pack_h2(va[i].z - h2f_lo(h1), va[i].w - h2f_hi(h1));
            sAh[aBase[i]] = h0; sAh[aBase[i] + 4] = h1;
            sAl[aBase[i]] = l0; sAl[aBase[i] + 4] = l1;
        }
        #pragma unroll
        for (int i = 0; i < 4; i++) {
            uint32_t h0 = pack_h2(vb[i].x, vb[i].y);
            uint32_t h1 = pack_h2(vb[i].z, vb[i].w);
            uint32_t l0 = pack_h2(vb[i].x - h2f_lo(h0), vb[i].y - h2f_hi(h0));
            uint32_t l1 = pack_h2(vb[i].z - h2f_lo(h1), vb[i].w - h2f_hi(h1));
            sBh[bBase[i]] = h0; sBh[bBase[i] + 2] = h1;
            sBl[bBase[i]] = l0; sBl[bBase[i] + 2] = l1;
        }
        __syncthreads();
        #pragma unroll
        for (int ikf = 0; ikf < 2; ikf++) {
            uint2 bh[4], bl[4];
            #pragma unroll
            for (int j2 = 0; j2 < 4; j2++) {
                int o = (((wn * 4 + j2) * 2 + ikf) * 32 + lane) * 2;
                bh[j2] = *(const uint2*)&sBh[o];
                bl[j2] = *(const uint2*)&sBl[o];
            }
            #pragma unroll
            for (int i2 = 0; i2 < 4; i2++) {
                int o = (((wm * 4 + i2) * 2 + ikf) * 32 + lane) * 4;
                uint4 ah = *(const uint4*)&sAh[o];
                uint4 al = *(const uint4*)&sAl[o];
                #pragma unroll
                for (int j2 = 0; j2 < 4; j2++) {
                    MMAF16(acc[i2][j2], ah, bh[j2]);
                    MMAF16(acc[i2][j2], ah, bl[j2]);
                    MMAF16(acc[i2][j2], al, bh[j2]);
                }
            }
        }
    }

    int g = lane >> 2, t = lane & 3;
    float* C = scores + (long)b * SEQ * SEQ;
    #pragma unroll
    for (int i2 = 0; i2 < 4; i2++) {
        int gm = m0 + (wm * 4 + i2) * 16 + g;
        #pragma unroll
        for (int j2 = 0; j2 < 4; j2++) {
            int gn = n0 + (wn * 4 + j2) * 8 + t * 2;
            *(float2*)&C[(long)gm * SEQ + gn] = make_float2(acc[i2][j2][0], acc[i2][j2][1]);
            *(float2*)&C[(long)(gm + 8) * SEQ + gn] = make_float2(acc[i2][j2][2], acc[i2][j2][3]);
        }
    }
}

// ---------------- flash attention (verified R6) ----------------
__global__ __launch_bounds__(256, 1)
void flash_kernel(const float* __restrict__ qkv, const float* __restrict__ vt,
                  float* __restrict__ ocat, float scale) {
    __shared__ uint32_t sK[6144];
    __shared__ uint32_t sV[6144];
    int z = blockIdx.z, b = z >> 3, h = z & 7;
    int m0 = blockIdx.y * 128;
    int tid = threadIdx.x, lane = tid & 31, wid = tid >> 5;
    int t = lane & 3, g = lane >> 2;

    const float* Qg = qkv + ((long)b * 1024 + m0) * 2304 + h * 96;
    const float* Kg = qkv + (long)b * 1024 * 2304 + 768 + h * 96;
    const float* Vg = vt + (long)z * 96 * 1024;

    #pragma unroll
    for (int i = 0; i < 12; i++) {
        int idx = tid + 256 * i;
        int r = idx / 24, q = idx % 24;
        int k0 = q * 4;
        int im = r >> 4, gg = r & 7, row8 = (r >> 3) & 1;
        int kg = k0 >> 4, k8 = (k0 >> 3) & 1, t0 = (k0 >> 1) & 3;
        int base = ((im * 6 + kg) * 32 + gg * 4 + t0) * 4 + row8 + 2 * k8;
        float4 v = *(const float4*)(Qg + (long)r * 2304 + k0);
        sK[base]     = pack_h2(v.x, v.y);
        sK[base + 4] = pack_h2(v.z, v.w);
    }
    __syncthreads();
    uint4 qf[6];
    #pragma unroll
    for (int kg = 0; kg < 6; kg++)
        qf[kg] = *(const uint4*)&sK[((wid * 6 + kg) * 32 + lane) * 4];
    __syncthreads();

    float mr0 = -1e30f, mr1 = -1e30f, l0 = 0.f, l1 = 0.f;
    float accO[12][4];
    #pragma unroll
    for (int j = 0; j < 12; j++)
        #pragma unroll
        for (int c = 0; c < 4; c++) accO[j][c] = 0.f;

    for (int kt = 0; kt < 8; kt++) {
        #pragma unroll
        for (int i = 0; i < 12; i++) {
            int idx = tid + 256 * i;
            int r = idx / 24, q = idx % 24;
            int k0 = q * 4;
            int jn = r >> 3, nn = r & 7;
            int kg = k0 >> 4, k8 = (k0 >> 3) & 1, t0 = (k0 >> 1) & 3;
            int base = ((jn * 6 + kg) * 32 + nn * 4 + t0) * 2 + k8;
            float4 v = *(const float4*)(Kg + (long)(kt * 128 + r) * 2304 + k0);
            sK[base]     = pack_h2(v.x, v.y);
            sK[base + 2] = pack_h2(v.z, v.w);
        }
        #pragma unroll
        for (int i = 0; i < 12; i++) {
            int idx = tid + 256 * i;
            int r = idx >> 5, q = idx & 31;
            int k0 = q * 4;
            int jn = r >> 3, nn = r & 7;
            int kg = k0 >> 4, k8 = (k0 >> 3) & 1, t0 = (k0 >> 1) & 3;
            int base = ((jn * 8 + kg) * 32 + nn * 4 + t0) * 2 + k8;
            float4 v = *(const float4*)(Vg + (long)r * 1024 + kt * 128 + k0);
            sV[base]     = pack_h2(v.x, v.y);
            sV[base + 2] = pack_h2(v.z, v.w);
        }
        __syncthreads();

        float accS[16][4];
        #pragma unroll
        for (int j = 0; j < 16; j++)
            #pragma unroll
            for (int c = 0; c < 4; c++) accS[j][c] = 0.f;
        #pragma unroll
        for (int kg = 0; kg < 6; kg++)
            #pragma unroll
            for (int jn = 0; jn < 16; jn++) {
                uint2 bf = *(const uint2*)&sK[((jn * 6 + kg) * 32 + lane) * 2];
                MMAF16(accS[jn], qf[kg], bf);
            }

        float mx0 = -1e30f, mx1 = -1e30f;
        #pragma unroll
        for (int jn = 0; jn < 16; jn++) {
            accS[jn][0] *= scale; accS[jn][1] *= scale;
            accS[jn][2] *= scale; accS[jn][3] *= scale;
            mx0 = fmaxf(mx0, fmaxf(accS[jn][0], accS[jn][1]));
            mx1 = fmaxf(mx1, fmaxf(accS[jn][2], accS[jn][3]));
        }
        mx0 = fmaxf(mx0, __shfl_xor_sync(0xffffffffu, mx0, 1));
        mx0 = fmaxf(mx0, __shfl_xor_sync(0xffffffffu, mx0, 2));
        mx1 = fmaxf(mx1, __shfl_xor_sync(0xffffffffu, mx1, 1));
        mx1 = fmaxf(mx1, __shfl_xor_sync(0xffffffffu, mx1, 2));

        float mn0 = fmaxf(mr0, mx0), mn1 = fmaxf(mr1, mx1);
        float cr0 = fexp(mr0 - mn0), cr1 = fexp(mr1 - mn1);

        float s0 = 0.f, s1 = 0.f;
        uint32_t plo[16], phi[16];
        #pragma unroll
        for (int jn = 0; jn < 16; jn++) {
            float e0 = fexp(accS[jn][0] - mn0);
            float e1 = fexp(accS[jn][1] - mn0);
            float e2 = fexp(accS[jn][2] - mn1);
            float e3 = fexp(accS[jn][3] - mn1);
            s0 += e0 + e1; s1 += e2 + e3;
            plo[jn] = pack_h2(e0, e1);
            phi[jn] = pack_h2(e2, e3);
        }
        s0 += __shfl_xor_sync(0xffffffffu, s0, 1);
        s0 += __shfl_xor_sync(0xffffffffu, s0, 2);
        s1 += __shfl_xor_sync(0xffffffffu, s1, 1);
        s1 += __shfl_xor_sync(0xffffffffu, s1, 2);

        l0 = l0 * cr0 + s0;
        l1 = l1 * cr1 + s1;
        mr0 = mn0; mr1 = mn1;
        #pragma unroll
        for (int j = 0; j < 12; j++) {
            accO[j][0] *= cr0; accO[j][1] *= cr0;
            accO[j][2] *= cr1; accO[j][3] *= cr1;
        }

        #pragma unroll
        for (int kg = 0; kg < 8; kg++) {
            uint4 af = make_uint4(plo[2 * kg], phi[2 * kg], plo[2 * kg + 1], phi[2 * kg + 1]);
            #pragma unroll
            for (int jn = 0; jn < 12; jn++) {
                uint2 bf = *(const uint2*)&sV[((jn * 8 + kg) * 32 + lane) * 2];
                MMAF16(accO[jn], af, bf);
            }
        }
        __syncthreads();
    }

    float inv0 = 1.f / l0, inv1 = 1.f / l1;
    long row0 = (long)(b * 1024 + m0 + wid * 16 + g);
    #pragma unroll
    for (int jn = 0; jn < 12; jn++) {
        int col = h * 96 + jn * 8 + t * 2;
        float2 v0, v1;
        v0.x = accO[jn][0] * inv0; v0.y = accO[jn][1] * inv0;
        v1.x = accO[jn][2] * inv1; v1.y = accO[jn][3] * inv1;
        *(float2*)&ocat[row0 * DIM + col] = v0;
        *(float2*)&ocat[(row0 + 8) * DIM + col] = v1;
    }
}

// ---------------- mma.sync fp16 GEMM: BOTH operands pre-packed blobs ----------------
// Ap: A-layout blob [mblk][nch][2048]; Wp: B-layout blob [nblk][nch][2048].
// n-blocks [0, nsplit) -> C0/bias0/ldc0 ; n-blocks >= nsplit -> C1/bias1/ldc1
__global__ __launch_bounds__(256, 2)
void mma_gemm(const uint32_t* __restrict__ Ap,
              const uint32_t* __restrict__ Wp,
              float* __restrict__ C0, long ldc0, const float* __restrict__ bias0, int nsplit,
              float* __restrict__ C1, long ldc1, const float* __restrict__ bias1,
              int nch) {
    __shared__ uint32_t sA[2][2048];
    __shared__ uint32_t sB[2][2048];

    int m0 = blockIdx.y * 128;
    int tid = threadIdx.x, lane = tid & 31, wid = tid >> 5;
    int wm = wid & 1, wn = wid >> 1;

    const uint4* Ab = (const uint4*)(Ap + (long)blockIdx.y * nch * 2048);
    const uint4* Wb = (const uint4*)(Wp + (long)blockIdx.x * nch * 2048);

    float acc[4][4][4];
    #pragma unroll
    for (int i = 0; i < 4; i++)
        #pragma unroll
        for (int j = 0; j < 4; j++)
            #pragma unroll
            for (int c = 0; c < 4; c++) acc[i][j][c] = 0.f;

    uint4 va0 = Ab[tid], va1 = Ab[tid + 256];
    uint4 vb0 = Wb[tid], vb1 = Wb[tid + 256];
    ((uint4*)sA[0])[tid] = va0; ((uint4*)sA[0])[tid + 256] = va1;
    ((uint4*)sB[0])[tid] = vb0; ((uint4*)sB[0])[tid + 256] = vb1;
    __syncthreads();

    for (int it = 0; it < nch; it++) {
        int buf = it & 1;
        bool more = (it + 1 < nch);
        if (more) {
            const uint4* An = Ab + (long)(it + 1) * 512;
            const uint4* Wn = Wb + (long)(it + 1) * 512;
            va0 = An[tid]; va1 = An[tid + 256];
            vb0 = Wn[tid]; vb1 = Wn[tid + 256];
        }
        #pragma unroll
        for (int ikf = 0; ikf < 2; ikf++) {
            uint4 af[4];
            uint2 bf[4];
            #pragma unroll
            for (int i2 = 0; i2 < 4; i2++)
                af[i2] = *(const uint4*)&sA[buf][(((wm * 4 + i2) * 2 + ikf) * 32 + lane) * 4];
            #pragma unroll
            for (int j2 = 0; j2 < 4; j2++)
                bf[j2] = *(const uint2*)&sB[buf][(((wn * 4 + j2) * 2 + ikf) * 32 + lane) * 2];
            #pragma unroll
            for (int i2 = 0; i2 < 4; i2++)
                #pragma unroll
                for (int j2 = 0; j2 < 4; j2++)
                    MMAF16(acc[i2][j2], af[i2], bf[j2]);
        }
        __syncthreads();
        if (more) {
            int nb = buf ^ 1;
            ((uint4*)sA[nb])[tid] = va0; ((uint4*)sA[nb])[tid + 256] = va1;
            ((uint4*)sB[nb])[tid] = vb0; ((uint4*)sB[nb])[tid + 256] = vb1;
            __syncthreads();
        }
    }

    float* C; long ldc; const float* bias; int n0;
    if ((int)blockIdx.x < nsplit) {
        C = C0; ldc = ldc0; bias = bias0; n0 = blockIdx.x * 128;
    } else {
        C = C1; ldc = ldc1; bias = bias1; n0 = (blockIdx.x - nsplit) * 128;
    }
    int g = lane >> 2, t = lane & 3;
    #pragma unroll
    for (int i2 = 0; i2 < 4; i2++) {
        int gm = m0 + (wm * 4 + i2) * 16 + g;
        #pragma unroll
        for (int j2 = 0; j2 < 4; j2++) {
            int gn = n0 + (wn * 4 + j2) * 8 + t * 2;
            float b0 = __ldg(bias + gn);
            float b1 = __ldg(bias + gn + 1);
            float2 v0, v1;
            v0.x = acc[i2][j2][0] + b0;
            v0.y = acc[i2][j2][1] + b1;
            v1.x = acc[i2][j2][2] + b0;
            v1.y = acc[i2][j2][3] + b1;
            *(float2*)&C[(long)gm * ldc + gn] = v0;
            *(float2*)&C[(long)(gm + 8) * ldc + gn] = v1;
        }
    }
}

// ---------------- V transpose for flash ----------------
__global__ void transpose_v_kernel(const float* __restrict__ qkv, float* __restrict__ vt) {
    int z = blockIdx.z; int b = z >> 3, h = z & 7;
    __shared__ float tb[32][33];
    int d0 = blockIdx.x * 32, t0 = blockIdx.y * 32;
    int tx = threadIdx.x, ty = threadIdx.y;
    const float* src = qkv + (long)b * 1024 * 2304 + 1536 + h * 96;
    for (int i = ty; i < 32; i += 8)
        tb[i][tx] = src[(long)(t0 + i) * 2304 + d0 + tx];
    __syncthreads();
    float* dst = vt + ((long)z * 96 + d0) * 1024 + t0;
    for (int j = ty; j < 32; j += 8)
        dst[(long)j * 1024 + tx] = tb[tx][j];
}

// ---------------- misc ----------------
__global__ void zero_bytes_kernel(unsigned char* p, long n) {
    long i = (long)blockIdx.x * blockDim.x + threadIdx.x;
    long stride = (long)gridDim.x * blockDim.x;
    int* pi = (int*)p;
    long nw = n >> 2;
    for (; i < nw; i += stride) pi[i] = 0;
}

// ---------------- topk select ----------------
__global__ void topk_select_kernel(const float* __restrict__ sim, int* __restrict__ idx_out) {
    long r = blockIdx.x;
    const float* row = sim + r * SEQ;
    __shared__ float s[SEQ];
    __shared__ float bv[256];
    __shared__ int   bi[256];
    int tid = threadIdx.x;
    for (int i = tid; i < SEQ; i += 256) s[i] = row[i];
    __syncthreads();
    for (int sel = 0; sel < KNEIGH; sel++) {
        float v = -INFINITY; int mi = 0x7fffffff;
        for (int t = tid; t < SEQ; t += 256) {
            float sv = s[t];
            if (sv > v || (sv == v && t < mi)) { v = sv; mi = t; }
        }
        bv[tid] = v; bi[tid] = mi;
        __syncthreads();
        for (int o = 128; o > 0; o >>= 1) {
            if (tid < o) {
                if (bv[tid + o] > bv[tid] || (bv[tid + o] == bv[tid] && bi[tid + o] < bi[tid])) {
                    bv[tid] = bv[tid + o]; bi[tid] = bi[tid + o];
                }
            }
            __syncthreads();
        }
        if (tid == 0) { idx_out[r * KNEIGH + sel] = bi[0]; s[bi[0]] = -INFINITY; }
        __syncthreads();
    }
}

// ---------------- adjacency + degree ----------------
__global__ void scatter_adj_kernel(const int* __restrict__ idx, unsigned char* __restrict__ A) {
    int r = blockIdx.x * blockDim.x + threadIdx.x;
    if (r >= ROWS) return;
    int b = r >> 10, s = r & 1023;
    unsigned char* Ab = A + (long long)b * SEQ * SEQ;
    Ab[(long)s * SEQ + s] = 1;
    #pragma unroll
    for (int j = 0; j < KNEIGH; j++) {
        int t = idx[(long)r * KNEIGH + j];
        Ab[(long)s * SEQ + t] = 1;
        Ab[(long)t * SEQ + s] = 1;
    }
}
__global__ void degree_kernel(const unsigned char* __restrict__ A, float* __restrict__ dinv) {
    int r = blockIdx.x * blockDim.x + threadIdx.x;
    if (r >= ROWS) return;
    const uint32_t* row = (const uint32_t*)(A + (long long)r * SEQ);
    int d = 0;
    for (int i = 0; i < SEQ / 4; i++) {
        uint32_t w = row[i];
        d += (w & 0xff) + ((w >> 8) & 0xff) + ((w >> 16) & 0xff) + ((w >> 24) & 0xff);
    }
    dinv[r] = rsqrtf((float)d);
}

// ---------------- sparse GCN aggregate ----------------
__global__ void gcn_agg_kernel(const unsigned char* __restrict__ A, const float* __restrict__ dinv,
                               const float* __restrict__ xw, const float* __restrict__ gcn_b,
                               float* __restrict__ cat) {
    int r = blockIdx.x;
    int b = r >> 10;
    const unsigned char* Arow = A + (long long)r * SEQ;
    __shared__ int   nbr[SEQ];
    __shared__ float wgt[SEQ];
    __shared__ int cnt;
    int tid = threadIdx.x;
    if (tid == 0) cnt = 0;
    __syncthreads();
    for (int t = tid; t < SEQ; t += 256) {
        if (Arow[t]) {
            int p = atomicAdd(&cnt, 1);
            nbr[p] = t;
            wgt[p] = dinv[(b << 10) + t];
        }
    }
    __syncthreads();
    int n = cnt;
    float acc0 = 0.f, acc1 = 0.f, acc2 = 0.f;
    for (int i = 0; i < n; i++) {
        const float* row = xw + ((long)(b << 10) + nbr[i]) * DIM;
        float w = wgt[i];
        acc0 += w * row[tid];
        acc1 += w * row[tid + 256];
        acc2 += w * row[tid + 512];
    }
    float ws = dinv[r];
    long base = (long)r * (2 * DIM);
    cat[base + tid]       = ws * acc0 + gcn_b[tid];
    cat[base + tid + 256] = ws * acc1 + gcn_b[tid + 256];
    cat[base + tid + 512] = ws * acc2 + gcn_b[tid + 512];
}

// ---------------- gate + residual + layernorm ----------------
__global__ void fuse_ln_kernel(const float* __restrict__ gatelin, const float* __restrict__ cat,
                               const float* __restrict__ hin, float* __restrict__ hout,
                               const float* __restrict__ ln_scale, const float* __restrict__ ln_bias) {
    long r = blockIdx.x;
    int tid = threadIdx.x;
    __shared__ float red[256];
    float f[3];
    #pragma unroll
    for (int i = 0; i < 3; i++) {
        int j = tid + 256 * i;
        float g  = gatelin[r * DIM + j];
        float gc = cat[r * (2 * DIM) + j];
        float at = cat[r * (2 * DIM) + DIM + j];
        float sg = 1.f / (1.f + fexp(-g));
        f[i] = sg * gc + (1.f - sg) * at + hin[r * DIM + j];
    }
    float s1 = f[0] + f[1] + f[2];
    red[tid] = s1; __syncthreads();
    #pragma unroll
    for (int o = 128; o > 0; o >>= 1) { if (tid < o) red[tid] += red[tid + o]; __syncthreads(); }
    float mu = red[0] * (1.f / DIM);
    __syncthreads();
    float s2 = 0.f;
    #pragma unroll
    for (int i = 0; i < 3; i++) { float d = f[i] - mu; s2 += d * d; }
    red[tid] = s2; __syncthreads();
    #pragma unroll
    for (int o = 128; o > 0; o >>= 1) { if (tid < o) red[tid] += red[tid + o]; __syncthreads(); }
    float var = red[0] * (1.f / DIM);
    float inv = rsqrtf(var + LN_EPS);
    #pragma unroll
    for (int i = 0; i < 3; i++) {
        int j = tid + 256 * i;
        hout[r * DIM + j] = (f[i] - mu) * inv * ln_scale[j] + ln_bias[j];
    }
}

// ---------------- host helper ----------------
static void launch_mma(const uint32_t* Ap, const uint32_t* Wp, float* C, long ldc,
                       const float* bias, int M, int N, int K) {
    dim3 grid(N / 128, M / 128, 1);
    mma_gemm<<<grid, 256>>>(Ap, Wp, C, ldc, bias, N / 128, C, ldc, bias, K / 32);
}

extern "C" void kernel_launch(void* const* d_in, const int* in_sizes, int n_in,
                              void* d_out, int out_size) {
    const float* x          = (const float*)d_in[0];
    const float* gcn_w      = (const float*)d_in[1];
    const float* gcn_b      = (const float*)d_in[2];
    const float* attn_in_w  = (const float*)d_in[3];
    const float* attn_in_b  = (const float*)d_in[4];
    const float* attn_out_w = (const float*)d_in[5];
    const float* attn_out_b = (const float*)d_in[6];
    const float* gate_w     = (const float*)d_in[7];
    const float* gate_b     = (const float*)d_in[8];
    const float* ln_scale   = (const float*)d_in[9];
    const float* ln_bias    = (const float*)d_in[10];
    const float* proj_w     = (const float*)d_in[11];
    const float* proj_b     = (const float*)d_in[12];
    float* out = (float*)d_out;

    float *p_h, *p_xw, *p_qkv, *p_scores, *p_ocat, *p_cat, *p_gate, *p_dinv, *p_vt;
    uint32_t *p_wp, *p_ap;
    unsigned char* p_adj;
    int* p_topk;
    cudaGetSymbolAddress((void**)&p_h, g_h);
    cudaGetSymbolAddress((void**)&p_xw, g_xw);
    cudaGetSymbolAddress((void**)&p_qkv, g_qkv);
    cudaGetSymbolAddress((void**)&p_scores, g_scores);
    cudaGetSymbolAddress((void**)&p_ocat, g_ocat);
    cudaGetSymbolAddress((void**)&p_cat, g_cat);
    cudaGetSymbolAddress((void**)&p_gate, g_gate);
    cudaGetSymbolAddress((void**)&p_dinv, g_dinv);
    cudaGetSymbolAddress((void**)&p_adj, g_adj);
    cudaGetSymbolAddress((void**)&p_topk, g_topk);
    cudaGetSymbolAddress((void**)&p_wp, g_wp);
    cudaGetSymbolAddress((void**)&p_ap, g_ap);
    cudaGetSymbolAddress((void**)&p_vt, g_vt);

    const float attn_scale = (float)(1.0 / sqrt((double)HDIM));
    dim3 tb(32, 8);

    // pack all weights to fp16 fragment layout (once per launch)
    for (int l = 0; l < NLAYERS; l++) {
        pack_weights_kernel<<<512, 256>>>(gcn_w + (long)l * DIM * DIM, p_wp + WP_FUSED(l), DIM, DIM);
        pack_weights_kernel<<<512, 256>>>(attn_in_w + (long)l * DIM * 3 * DIM,
                                          p_wp + WP_FUSED(l) + 294912, 3 * DIM, DIM);
        pack_weights_kernel<<<512, 256>>>(attn_out_w + (long)l * DIM * DIM, p_wp + WP_AOW(l), DIM, DIM);
        pack_weights_kernel<<<512, 256>>>(gate_w + (long)l * 2 * DIM * DIM, p_wp + WP_GW(l), DIM, 2 * DIM);
    }
    pack_weights_kernel<<<512, 256>>>(proj_w, p_wp + WP_PROJ, DIM, DIM);

    // sim = x x^T via fp16 hi/lo split tensor cores, then top-5 select
    sim_gemm<<<dim3(8, 8, BATCH), 256>>>(x, p_scores);
    topk_select_kernel<<<ROWS, 256>>>(p_scores, p_topk);
    zero_bytes_kernel<<<1024, 256>>>(p_adj, (long long)BATCH * SEQ * SEQ);
    scatter_adj_kernel<<<(ROWS + 255) / 256, 256>>>(p_topk, p_adj);
    degree_kernel<<<(ROWS + 255) / 256, 256>>>(p_adj, p_dinv);

    for (int l = 0; l < NLAYERS; l++) {
        const float* gb  = gcn_b + (long)l * DIM;
        const float* aib = attn_in_b + (long)l * 3 * DIM;
        const float* aob = attn_out_b + (long)l * DIM;
        const float* gtb = gate_b + (long)l * DIM;
        const float* lns = ln_scale + (long)l * DIM;
        const float* lnb = ln_bias + (long)l * DIM;
        const float* hin = (l == 0) ? x : p_h;

        // pack hin -> A blob; fused: XW -> xw (n-blocks 0-5), QKV -> qkv (n-blocks 6-23)
        pack_act_kernel<<<dim3(24, 64), 256>>>(hin, p_ap, DIM);
        {
            dim3 grid(24, ROWS / 128, 1);
            mma_gemm<<<grid, 256>>>(p_ap, p_wp + WP_FUSED(l),
                                    p_xw, DIM, gb, 6,
                                    p_qkv, 3 * DIM, aib,
                                    24);
        }
        // gcn_out -> cat[:, 0:768]
        gcn_agg_kernel<<<ROWS, 256>>>(p_adj, p_dinv, p_xw, gb, p_cat);
        // V transpose: [64, 96, 1024]
        transpose_v_kernel<<<dim3(3, 32, 64), tb>>>(p_qkv, p_vt);
        // fused flash attention -> ocat
        flash_kernel<<<dim3(1, 8, 64), 256>>>(p_qkv, p_vt, p_ocat, attn_scale);
        // attn_out = O @ attn_out_w[l] + b -> cat[:, 768:1536]
        pack_act_kernel<<<dim3(24, 64), 256>>>(p_ocat, p_ap, DIM);
        launch_mma(p_ap, p_wp + WP_AOW(l), p_cat + DIM, 2 * DIM, aob, ROWS, DIM, DIM);
        // gate_lin = cat @ gate_w[l] + b
        pack_act_kernel<<<dim3(48, 64), 256>>>(p_cat, p_ap, 2 * DIM);
        launch_mma(p_ap, p_wp + WP_GW(l), p_gate, DIM, gtb, ROWS, DIM, 2 * DIM);
        // h = LN(gate*gcn + (1-gate)*attn + hin)
        fuse_ln_kernel<<<ROWS, 256>>>(p_gate, p_cat, hin, p_h, lns, lnb);
    }

    // out = h @ proj_w + proj_b
    pack_act_kernel<<<dim3(24, 64), 256>>>(p_h, p_ap, DIM);
    launch_mma(p_ap, p_wp + WP_PROJ, out, DIM, proj_b, ROWS, DIM, DIM);
}

// round 11
// speedup vs baseline: 7.3197x; 1.0497x over previous
#include <cuda_runtime.h>
#include <math.h>
#include <stdint.h>

// ---------------- problem constants ----------------
#define BATCH 8
#define SEQ   1024
#define DIM   768
#define HEADS 8
#define HDIM  96
#define KNEIGH 5
#define NLAYERS 3
#define ROWS (BATCH*SEQ)  // 8192
#define LN_EPS 1e-5f

// ---------------- device scratch (static, allocation-free) ----------------
__device__ float g_h[ROWS * DIM];
__device__ float g_xw[ROWS * DIM];
__device__ float g_qkv[ROWS * 3 * DIM];
__device__ float g_scores[(long long)BATCH * SEQ * SEQ]; // sim workspace (32 MB)
__device__ float g_ocat[ROWS * DIM];
__device__ float g_cat[ROWS * 2 * DIM];   // [gcn | attn] stride 1536
__device__ float g_gate[ROWS * DIM];
__device__ unsigned char g_adj[(long long)BATCH * SEQ * SEQ];    // 8 MB
__device__ float g_dinv[ROWS];
__device__ int   g_topk[ROWS * KNEIGH];
__device__ uint32_t g_wp[6488064];        // fp16 fragment-packed weights (26 MB)
__device__ uint32_t g_ap[6291456];        // fp16 fragment-packed activations (25 MB)
__device__ float g_vt[ROWS * DIM];        // V transposed per (b,h): [64, 96, 1024]

// packed weight word offsets
// per-layer fused blob: [gcn (6 nblk) | attn_in (18 nblk)] x 24 kch x 2048 words
#define WP_FUSED(l) ((long)(l) * 1179648)
#define WP_AOW(l)   (3538944L + (long)(l) * 294912L)
#define WP_GW(l)    (4423680L + (long)(l) * 589824L)
#define WP_PROJ     (6193152L)

// pack two floats to half2 (lo = a, hi = b)
__device__ __forceinline__ uint32_t pack_h2(float a, float b) {
    uint32_t r;
    asm("cvt.rn.f16x2.f32 %0, %2, %1;" : "=r"(r) : "f"(a), "f"(b));
    return r;
}
// unpack halves of a packed f16x2 word to fp32 (no cuda_fp16.h dependency)
__device__ __forceinline__ float h2f_lo(uint32_t h) {
    float f;
    asm("{.reg .b16 lo, hi;\n\t"
        "mov.b32 {lo, hi}, %1;\n\t"
        "cvt.f32.f16 %0, lo;}" : "=f"(f) : "r"(h));
    return f;
}
__device__ __forceinline__ float h2f_hi(uint32_t h) {
    float f;
    asm("{.reg .b16 lo, hi;\n\t"
        "mov.b32 {lo, hi}, %1;\n\t"
        "cvt.f32.f16 %0, hi;}" : "=f"(f) : "r"(h));
    return f;
}

// FMA-only exp (no MUFU)
__device__ __forceinline__ float fexp(float x) {
    x = fmaxf(x, -87.0f);
    float y = x * 1.4426950408889634f;
    int i = __float2int_rn(y);
    float r = (y - (float)i) * 0.6931471805599453f;
    float p = 1.9841270e-4f;
    p = fmaf(p, r, 1.3888889e-3f);
    p = fmaf(p, r, 8.3333333e-3f);
    p = fmaf(p, r, 4.1666667e-2f);
    p = fmaf(p, r, 1.6666667e-1f);
    p = fmaf(p, r, 0.5f);
    p = fmaf(p, r, 1.0f);
    p = fmaf(p, r, 1.0f);
    return p * __int_as_float((i + 127) << 23);
}

#define MMAF16(d, a, b) \
    asm volatile("mma.sync.aligned.m16n8k16.row.col.f32.f16.f16.f32 " \
        "{%0,%1,%2,%3}, {%4,%5,%6,%7}, {%8,%9}, {%0,%1,%2,%3};" \
        : "+f"((d)[0]), "+f"((d)[1]), "+f"((d)[2]), "+f"((d)[3]) \
        : "r"((a).x), "r"((a).y), "r"((a).z), "r"((a).w), \
          "r"((b).x), "r"((b).y))

// ---------------- weight packing: w [K,N] fp32 -> fragment-packed fp16 (B-layout) ----------------
__global__ void pack_weights_kernel(const float* __restrict__ w, uint32_t* __restrict__ wp,
                                    int N, int K) {
    int nch = K >> 5;
    long total = (long)N * (K >> 1);
    for (long tId = (long)blockIdx.x * blockDim.x + threadIdx.x; tId < total;
         tId += (long)gridDim.x * blockDim.x) {
        int n = (int)(tId % N);
        int kp = (int)(tId / N);
        int k = kp * 2;
        float v0 = w[(long)k * N + n];
        float v1 = w[(long)(k + 1) * N + n];
        long blk = (long)(n >> 7) * nch + (k >> 5);
        int nloc = n & 127, kloc = k & 31;
        int widx = ((((nloc >> 3) * 2 + ((kloc >> 4) & 1)) * 32
                     + (nloc & 7) * 4 + ((kloc >> 1) & 3)) * 2) + ((kloc >> 3) & 1);
        wp[blk * 2048 + widx] = pack_h2(v0, v1);
    }
}

// ---------------- activation packing: act [M,K] fp32 -> fragment-packed fp16 (A-layout) ----------------
__global__ void pack_act_kernel(const float* __restrict__ act, uint32_t* __restrict__ blob,
                                int K) {
    int kch = blockIdx.x, mblk = blockIdx.y;
    int nch = gridDim.x;
    const float* a0 = act + (long)mblk * 128 * K + kch * 32;
    uint32_t* out = blob + ((long)mblk * nch + kch) * 2048;
    int tid = threadIdx.x;
    #pragma unroll
    for (int i = 0; i < 8; i++) {
        int w = tid + 256 * i;
        int c = w & 3, lanep = (w >> 2) & 31, ikf = (w >> 7) & 1, im = w >> 8;
        int r = im * 16 + (c & 1) * 8 + (lanep >> 2);
        int k = ikf * 16 + ((c >> 1) & 1) * 8 + (lanep & 3) * 2;
        float2 v = *(const float2*)(a0 + (long)r * K + k);
        out[w] = pack_h2(v.x, v.y);
    }
}

// ---------------- sim = x x^T via fp16 hi/lo split (≈fp32 precision, verified R9) ----------------
__global__ __launch_bounds__(256, 2)
void sim_gemm(const float* __restrict__ x, float* __restrict__ scores) {
    __shared__ uint32_t sAh[2048], sAl[2048], sBh[2048], sBl[2048];
    int b = blockIdx.z;
    int m0 = blockIdx.y * 128, n0 = blockIdx.x * 128;
    int tid = threadIdx.x, lane = tid & 31, wid = tid >> 5;
    int wm = wid & 1, wn = wid >> 1;
    const float* Xm = x + (long)b * SEQ * DIM + (long)m0 * DIM;
    const float* Xn = x + (long)b * SEQ * DIM + (long)n0 * DIM;

    int aR[4], aQ[4], aBase[4];
    #pragma unroll
    for (int i = 0; i < 4; i++) {
        int idx = tid + 256 * i;
        int r = idx >> 3, q = idx & 7;
        aR[i] = r; aQ[i] = q;
        int im = r >> 4, g = r & 7, row8 = (r >> 3) & 1;
        int ikf = q >> 2, k8 = (q >> 1) & 1;
        aBase[i] = ((im * 2 + ikf) * 32 + g * 4) * 4 + k8 * 2 + row8 + 8 * (q & 1);
    }
    int bR[4], bQ[4], bBase[4];
    #pragma unroll
    for (int i = 0; i < 4; i++) {
        int idx = tid + 256 * i;
        int r = idx >> 3, q = idx & 7;
        bR[i] = r; bQ[i] = q;
        int in = r >> 3, nn = r & 7;
        int ikf = q >> 2, k8 = (q >> 1) & 1;
        bBase[i] = ((in * 2 + ikf) * 32 + nn * 4) * 2 + k8 + 4 * (q & 1);
    }

    float acc[4][4][4];
    #pragma unroll
    for (int i = 0; i < 4; i++)
        #pragma unroll
        for (int j = 0; j < 4; j++)
            #pragma unroll
            for (int c = 0; c < 4; c++) acc[i][j][c] = 0.f;

    for (int it = 0; it < DIM / 32; it++) {
        long koff = (long)it * 32;
        float4 va[4], vb[4];
        #pragma unroll
        for (int i = 0; i < 4; i++)
            va[i] = *(const float4*)(Xm + (long)aR[i] * DIM + koff + aQ[i] * 4);
        #pragma unroll
        for (int i = 0; i < 4; i++)
            vb[i] = *(const float4*)(Xn + (long)bR[i] * DIM + koff + bQ[i] * 4);
        __syncthreads();
        #pragma unroll
        for (int i = 0; i < 4; i++) {
            uint32_t h0 = pack_h2(va[i].x, va[i].y);
            uint32_t h1 = pack_h2(va[i].z, va[i].w);
            uint32_t l0 = pack_h2(va[i].x - h2f_lo(h0), va[i].y - h2f_hi(h0));
            uint32_t l1 = pack_h2(va[i].z - h2f_lo(h1), va[i].w - h2f_hi(h1));
            sAh[aBase[i]] = h0; sAh[aBase[i] + 4] = h1;
            sAl[aBase[i]] = l0; sAl[aBase[i] + 4] = l1;
        }
        #pragma unroll
        for (int i = 0; i < 4; i++) {
            uint32_t h0 = pack_h2(vb[i].x, vb[i].y);
            uint32_t h1 = pack_h2(vb[i].z, vb[i].w);
            uint32_t l0 = pack_h2(vb[i].x - h2f_lo(h0), vb[i].y - h2f_hi(h0));
            uint32_t l1 = pack_h2(vb[i].z - h2f_lo(h1), vb[i].w - h2f_hi(h1));
            sBh[bBase[i]] = h0; sBh[bBase[i] + 2] = h1;
            sBl[bBase[i]] = l0; sBl[bBase[i] + 2] = l1;
        }
        __syncthreads();
        #pragma unroll
        for (int ikf = 0; ikf < 2; ikf++) {
            uint2 bh[4], bl[4];
            #pragma unroll
            for (int j2 = 0; j2 < 4; j2++) {
                int o = (((wn * 4 + j2) * 2 + ikf) * 32 + lane) * 2;
                bh[j2] = *(const uint2*)&sBh[o];
                bl[j2] = *(const uint2*)&sBl[o];
            }
            #pragma unroll
            for (int i2 = 0; i2 < 4; i2++) {
                int o = (((wm * 4 + i2) * 2 + ikf) * 32 + lane) * 4;
                uint4 ah = *(const uint4*)&sAh[o];
                uint4 al = *(const uint4*)&sAl[o];
                #pragma unroll
                for (int j2 = 0; j2 < 4; j2++) {
                    MMAF16(acc[i2][j2], ah, bh[j2]);
                    MMAF16(acc[i2][j2], ah, bl[j2]);
                    MMAF16(acc[i2][j2], al, bh[j2]);
                }
            }
        }
    }

    int g = lane >> 2, t = lane & 3;
    float* C = scores + (long)b * SEQ * SEQ;
    #pragma unroll
    for (int i2 = 0; i2 < 4; i2++) {
        int gm = m0 + (wm * 4 + i2) * 16 + g;
        #pragma unroll
        for (int j2 = 0; j2 < 4; j2++) {
            int gn = n0 + (wn * 4 + j2) * 8 + t * 2;
            *(float2*)&C[(long)gm * SEQ + gn] = make_float2(acc[i2][j2][0], acc[i2][j2][1]);
            *(float2*)&C[(long)(gm + 8) * SEQ + gn] = make_float2(acc[i2][j2][2], acc[i2][j2][3]);
        }
    }
}

// ---------------- flash attention (verified R6) ----------------
__global__ __launch_bounds__(256, 1)
void flash_kernel(const float* __restrict__ qkv, const float* __restrict__ vt,
                  float* __restrict__ ocat, float scale) {
    __shared__ uint32_t sK[6144];
    __shared__ uint32_t sV[6144];
    int z = blockIdx.z, b = z >> 3, h = z & 7;
    int m0 = blockIdx.y * 128;
    int tid = threadIdx.x, lane = tid & 31, wid = tid >> 5;
    int t = lane & 3, g = lane >> 2;

    const float* Qg = qkv + ((long)b * 1024 + m0) * 2304 + h * 96;
    const float* Kg = qkv + (long)b * 1024 * 2304 + 768 + h * 96;
    const float* Vg = vt + (long)z * 96 * 1024;

    #pragma unroll
    for (int i = 0; i < 12; i++) {
        int idx = tid + 256 * i;
        int r = idx / 24, q = idx % 24;
        int k0 = q * 4;
        int im = r >> 4, gg = r & 7, row8 = (r >> 3) & 1;
        int kg = k0 >> 4, k8 = (k0 >> 3) & 1, t0 = (k0 >> 1) & 3;
        int base = ((im * 6 + kg) * 32 + gg * 4 + t0) * 4 + row8 + 2 * k8;
        float4 v = *(const float4*)(Qg + (long)r * 2304 + k0);
        sK[base]     = pack_h2(v.x, v.y);
        sK[base + 4] = pack_h2(v.z, v.w);
    }
    __syncthreads();
    uint4 qf[6];
    #pragma unroll
    for (int kg = 0; kg < 6; kg++)
        qf[kg] = *(const uint4*)&sK[((wid * 6 + kg) * 32 + lane) * 4];
    __syncthreads();

    float mr0 = -1e30f, mr1 = -1e30f, l0 = 0.f, l1 = 0.f;
    float accO[12][4];
    #pragma unroll
    for (int j = 0; j < 12; j++)
        #pragma unroll
        for (int c = 0; c < 4; c++) accO[j][c] = 0.f;

    for (int kt = 0; kt < 8; kt++) {
        #pragma unroll
        for (int i = 0; i < 12; i++) {
            int idx = tid + 256 * i;
            int r = idx / 24, q = idx % 24;
            int k0 = q * 4;
            int jn = r >> 3, nn = r & 7;
            int kg = k0 >> 4, k8 = (k0 >> 3) & 1, t0 = (k0 >> 1) & 3;
            int base = ((jn * 6 + kg) * 32 + nn * 4 + t0) * 2 + k8;
            float4 v = *(const float4*)(Kg + (long)(kt * 128 + r) * 2304 + k0);
            sK[base]     = pack_h2(v.x, v.y);
            sK[base + 2] = pack_h2(v.z, v.w);
        }
        #pragma unroll
        for (int i = 0; i < 12; i++) {
            int idx = tid + 256 * i;
            int r = idx >> 5, q = idx & 31;
            int k0 = q * 4;
            int jn = r >> 3, nn = r & 7;
            int kg = k0 >> 4, k8 = (k0 >> 3) & 1, t0 = (k0 >> 1) & 3;
            int base = ((jn * 8 + kg) * 32 + nn * 4 + t0) * 2 + k8;
            float4 v = *(const float4*)(Vg + (long)r * 1024 + kt * 128 + k0);
            sV[base]     = pack_h2(v.x, v.y);
            sV[base + 2] = pack_h2(v.z, v.w);
        }
        __syncthreads();

        float accS[16][4];
        #pragma unroll
        for (int j = 0; j < 16; j++)
            #pragma unroll
            for (int c = 0; c < 4; c++) accS[j][c] = 0.f;
        #pragma unroll
        for (int kg = 0; kg < 6; kg++)
            #pragma unroll
            for (int jn = 0; jn < 16; jn++) {
                uint2 bf = *(const uint2*)&sK[((jn * 6 + kg) * 32 + lane) * 2];
                MMAF16(accS[jn], qf[kg], bf);
            }

        float mx0 = -1e30f, mx1 = -1e30f;
        #pragma unroll
        for (int jn = 0; jn < 16; jn++) {
            accS[jn][0] *= scale; accS[jn][1] *= scale;
            accS[jn][2] *= scale; accS[jn][3] *= scale;
            mx0 = fmaxf(mx0, fmaxf(accS[jn][0], accS[jn][1]));
            mx1 = fmaxf(mx1, fmaxf(accS[jn][2], accS[jn][3]));
        }
        mx0 = fmaxf(mx0, __shfl_xor_sync(0xffffffffu, mx0, 1));
        mx0 = fmaxf(mx0, __shfl_xor_sync(0xffffffffu, mx0, 2));
        mx1 = fmaxf(mx1, __shfl_xor_sync(0xffffffffu, mx1, 1));
        mx1 = fmaxf(mx1, __shfl_xor_sync(0xffffffffu, mx1, 2));

        float mn0 = fmaxf(mr0, mx0), mn1 = fmaxf(mr1, mx1);
        float cr0 = fexp(mr0 - mn0), cr1 = fexp(mr1 - mn1);

        float s0 = 0.f, s1 = 0.f;
        uint32_t plo[16], phi[16];
        #pragma unroll
        for (int jn = 0; jn < 16; jn++) {
            float e0 = fexp(accS[jn][0] - mn0);
            float e1 = fexp(accS[jn][1] - mn0);
            float e2 = fexp(accS[jn][2] - mn1);
            float e3 = fexp(accS[jn][3] - mn1);
            s0 += e0 + e1; s1 += e2 + e3;
            plo[jn] = pack_h2(e0, e1);
            phi[jn] = pack_h2(e2, e3);
        }
        s0 += __shfl_xor_sync(0xffffffffu, s0, 1);
        s0 += __shfl_xor_sync(0xffffffffu, s0, 2);
        s1 += __shfl_xor_sync(0xffffffffu, s1, 1);
        s1 += __shfl_xor_sync(0xffffffffu, s1, 2);

        l0 = l0 * cr0 + s0;
        l1 = l1 * cr1 + s1;
        mr0 = mn0; mr1 = mn1;
        #pragma unroll
        for (int j = 0; j < 12; j++) {
            accO[j][0] *= cr0; accO[j][1] *= cr0;
            accO[j][2] *= cr1; accO[j][3] *= cr1;
        }

        #pragma unroll
        for (int kg = 0; kg < 8; kg++) {
            uint4 af = make_uint4(plo[2 * kg], phi[2 * kg], plo[2 * kg + 1], phi[2 * kg + 1]);
            #pragma unroll
            for (int jn = 0; jn < 12; jn++) {
                uint2 bf = *(const uint2*)&sV[((jn * 8 + kg) * 32 + lane) * 2];
                MMAF16(accO[jn], af, bf);
            }
        }
        __syncthreads();
    }

    float inv0 = 1.f / l0, inv1 = 1.f / l1;
    long row0 = (long)(b * 1024 + m0 + wid * 16 + g);
    #pragma unroll
    for (int jn = 0; jn < 12; jn++) {
        int col = h * 96 + jn * 8 + t * 2;
        float2 v0, v1;
        v0.x = accO[jn][0] * inv0; v0.y = accO[jn][1] * inv0;
        v1.x = accO[jn][2] * inv1; v1.y = accO[jn][3] * inv1;
        *(float2*)&ocat[row0 * DIM + col] = v0;
        *(float2*)&ocat[(row0 + 8) * DIM + col] = v1;
    }
}

// ---------------- mma.sync fp16 GEMM: BOTH operands pre-packed blobs ----------------
__global__ __launch_bounds__(256, 2)
void mma_gemm(const uint32_t* __restrict__ Ap,
              const uint32_t* __restrict__ Wp,
              float* __restrict__ C0, long ldc0, const float* __restrict__ bias0, int nsplit,
              float* __restrict__ C1, long ldc1, const float* __restrict__ bias1,
              int nch) {
    __shared__ uint32_t sA[2][2048];
    __shared__ uint32_t sB[2][2048];

    int m0 = blockIdx.y * 128;
    int tid = threadIdx.x, lane = tid & 31, wid = tid >> 5;
    int wm = wid & 1, wn = wid >> 1;

    const uint4* Ab = (const uint4*)(Ap + (long)blockIdx.y * nch * 2048);
    const uint4* Wb = (const uint4*)(Wp + (long)blockIdx.x * nch * 2048);

    float acc[4][4][4];
    #pragma unroll
    for (int i = 0; i < 4; i++)
        #pragma unroll
        for (int j = 0; j < 4; j++)
            #pragma unroll
            for (int c = 0; c < 4; c++) acc[i][j][c] = 0.f;

    uint4 va0 = Ab[tid], va1 = Ab[tid + 256];
    uint4 vb0 = Wb[tid], vb1 = Wb[tid + 256];
    ((uint4*)sA[0])[tid] = va0; ((uint4*)sA[0])[tid + 256] = va1;
    ((uint4*)sB[0])[tid] = vb0; ((uint4*)sB[0])[tid + 256] = vb1;
    __syncthreads();

    for (int it = 0; it < nch; it++) {
        int buf = it & 1;
        bool more = (it + 1 < nch);
        if (more) {
            const uint4* An = Ab + (long)(it + 1) * 512;
            const uint4* Wn = Wb + (long)(it + 1) * 512;
            va0 = An[tid]; va1 = An[tid + 256];
            vb0 = Wn[tid]; vb1 = Wn[tid + 256];
        }
        #pragma unroll
        for (int ikf = 0; ikf < 2; ikf++) {
            uint4 af[4];
            uint2 bf[4];
            #pragma unroll
            for (int i2 = 0; i2 < 4; i2++)
                af[i2] = *(const uint4*)&sA[buf][(((wm * 4 + i2) * 2 + ikf) * 32 + lane) * 4];
            #pragma unroll
            for (int j2 = 0; j2 < 4; j2++)
                bf[j2] = *(const uint2*)&sB[buf][(((wn * 4 + j2) * 2 + ikf) * 32 + lane) * 2];
            #pragma unroll
            for (int i2 = 0; i2 < 4; i2++)
                #pragma unroll
                for (int j2 = 0; j2 < 4; j2++)
                    MMAF16(acc[i2][j2], af[i2], bf[j2]);
        }
        __syncthreads();
        if (more) {
            int nb = buf ^ 1;
            ((uint4*)sA[nb])[tid] = va0; ((uint4*)sA[nb])[tid + 256] = va1;
            ((uint4*)sB[nb])[tid] = vb0; ((uint4*)sB[nb])[tid + 256] = vb1;
            __syncthreads();
        }
    }

    float* C; long ldc; const float* bias; int n0;
    if ((int)blockIdx.x < nsplit) {
        C = C0; ldc = ldc0; bias = bias0; n0 = blockIdx.x * 128;
    } else {
        C = C1; ldc = ldc1; bias = bias1; n0 = (blockIdx.x - nsplit) * 128;
    }
    int g = lane >> 2, t = lane & 3;
    #pragma unroll
    for (int i2 = 0; i2 < 4; i2++) {
        int gm = m0 + (wm * 4 + i2) * 16 + g;
        #pragma unroll
        for (int j2 = 0; j2 < 4; j2++) {
            int gn = n0 + (wn * 4 + j2) * 8 + t * 2;
            float b0 = __ldg(bias + gn);
            float b1 = __ldg(bias + gn + 1);
            float2 v0, v1;
            v0.x = acc[i2][j2][0] + b0;
            v0.y = acc[i2][j2][1] + b1;
            v1.x = acc[i2][j2][2] + b0;
            v1.y = acc[i2][j2][3] + b1;
            *(float2*)&C[(long)gm * ldc + gn] = v0;
            *(float2*)&C[(long)(gm + 8) * ldc + gn] = v1;
        }
    }
}

// ---------------- V transpose for flash ----------------
__global__ void transpose_v_kernel(const float* __restrict__ qkv, float* __restrict__ vt) {
    int z = blockIdx.z; int b = z >> 3, h = z & 7;
    __shared__ float tb[32][33];
    int d0 = blockIdx.x * 32, t0 = blockIdx.y * 32;
    int tx = threadIdx.x, ty = threadIdx.y;
    const float* src = qkv + (long)b * 1024 * 2304 + 1536 + h * 96;
    for (int i = ty; i < 32; i += 8)
        tb[i][tx] = src[(long)(t0 + i) * 2304 + d0 + tx];
    __syncthreads();
    float* dst = vt + ((long)z * 96 + d0) * 1024 + t0;
    for (int j = ty; j < 32; j += 8)
        dst[(long)j * 1024 + tx] = tb[tx][j];
}

// ---------------- misc ----------------
__global__ void zero_bytes_kernel(unsigned char* p, long n) {
    long i = (long)blockIdx.x * blockDim.x + threadIdx.x;
    long stride = (long)gridDim.x * blockDim.x;
    int* pi = (int*)p;
    long nw = n >> 2;
    for (; i < nw; i += stride) pi[i] = 0;
}

// ---------------- topk select ----------------
__global__ void topk_select_kernel(const float* __restrict__ sim, int* __restrict__ idx_out) {
    long r = blockIdx.x;
    const float* row = sim + r * SEQ;
    __shared__ float s[SEQ];
    __shared__ float bv[256];
    __shared__ int   bi[256];
    int tid = threadIdx.x;
    for (int i = tid; i < SEQ; i += 256) s[i] = row[i];
    __syncthreads();
    for (int sel = 0; sel < KNEIGH; sel++) {
        float v = -INFINITY; int mi = 0x7fffffff;
        for (int t = tid; t < SEQ; t += 256) {
            float sv = s[t];
            if (sv > v || (sv == v && t < mi)) { v = sv; mi = t; }
        }
        bv[tid] = v; bi[tid] = mi;
        __syncthreads();
        for (int o = 128; o > 0; o >>= 1) {
            if (tid < o) {
                if (bv[tid + o] > bv[tid] || (bv[tid + o] == bv[tid] && bi[tid + o] < bi[tid])) {
                    bv[tid] = bv[tid + o]; bi[tid] = bi[tid + o];
                }
            }
            __syncthreads();
        }
        if (tid == 0) { idx_out[r * KNEIGH + sel] = bi[0]; s[bi[0]] = -INFINITY; }
        __syncthreads();
    }
}

// ---------------- adjacency + degree ----------------
__global__ void scatter_adj_kernel(const int* __restrict__ idx, unsigned char* __restrict__ A) {
    int r = blockIdx.x * blockDim.x + threadIdx.x;
    if (r >= ROWS) return;
    int b = r >> 10, s = r & 1023;
    unsigned char* Ab = A + (long long)b * SEQ * SEQ;
    Ab[(long)s * SEQ + s] = 1;
    #pragma unroll
    for (int j = 0; j < KNEIGH; j++) {
        int t = idx[(long)r * KNEIGH + j];
        Ab[(long)s * SEQ + t] = 1;
        Ab[(long)t * SEQ + s] = 1;
    }
}
__global__ void degree_kernel(const unsigned char* __restrict__ A, float* __restrict__ dinv) {
    int r = blockIdx.x * blockDim.x + threadIdx.x;
    if (r >= ROWS) return;
    const uint32_t* row = (const uint32_t*)(A + (long long)r * SEQ);
    int d = 0;
    for (int i = 0; i < SEQ / 4; i++) {
        uint32_t w = row[i];
        d += (w & 0xff) + ((w >> 8) & 0xff) + ((w >> 16) & 0xff) + ((w >> 24) & 0xff);
    }
    dinv[r] = rsqrtf((float)d);
}

// ---------------- sparse GCN aggregate ----------------
__global__ void gcn_agg_kernel(const unsigned char* __restrict__ A, const float* __restrict__ dinv,
                               const float* __restrict__ xw, const float* __restrict__ gcn_b,
                               float* __restrict__ cat) {
    int r = blockIdx.x;
    int b = r >> 10;
    const unsigned char* Arow = A + (long long)r * SEQ;
    __shared__ int   nbr[SEQ];
    __shared__ float wgt[SEQ];
    __shared__ int cnt;
    int tid = threadIdx.x;
    if (tid == 0) cnt = 0;
    __syncthreads();
    for (int t = tid; t < SEQ; t += 256) {
        if (Arow[t]) {
            int p = atomicAdd(&cnt, 1);
            nbr[p] = t;
            wgt[p] = dinv[(b << 10) + t];
        }
    }
    __syncthreads();
    int n = cnt;
    float acc0 = 0.f, acc1 = 0.f, acc2 = 0.f;
    for (int i = 0; i < n; i++) {
        const float* row = xw + ((long)(b << 10) + nbr[i]) * DIM;
        float w = wgt[i];
        acc0 += w * row[tid];
        acc1 += w * row[tid + 256];
        acc2 += w * row[tid + 512];
    }
    float ws = dinv[r];
    long base = (long)r * (2 * DIM);
    cat[base + tid]       = ws * acc0 + gcn_b[tid];
    cat[base + tid + 256] = ws * acc1 + gcn_b[tid + 256];
    cat[base + tid + 512] = ws * acc2 + gcn_b[tid + 512];
}

// ---------------- gate + residual + layernorm ----------------
__global__ void fuse_ln_kernel(const float* __restrict__ gatelin, const float* __restrict__ cat,
                               const float* __restrict__ hin, float* __restrict__ hout,
                               const float* __restrict__ ln_scale, const float* __restrict__ ln_bias) {
    long r = blockIdx.x;
    int tid = threadIdx.x;
    __shared__ float red[256];
    float f[3];
    #pragma unroll
    for (int i = 0; i < 3; i++) {
        int j = tid + 256 * i;
        float g  = gatelin[r * DIM + j];
        float gc = cat[r * (2 * DIM) + j];
        float at = cat[r * (2 * DIM) + DIM + j];
        float sg = 1.f / (1.f + fexp(-g));
        f[i] = sg * gc + (1.f - sg) * at + hin[r * DIM + j];
    }
    float s1 = f[0] + f[1] + f[2];
    red[tid] = s1; __syncthreads();
    #pragma unroll
    for (int o = 128; o > 0; o >>= 1) { if (tid < o) red[tid] += red[tid + o]; __syncthreads(); }
    float mu = red[0] * (1.f / DIM);
    __syncthreads();
    float s2 = 0.f;
    #pragma unroll
    for (int i = 0; i < 3; i++) { float d = f[i] - mu; s2 += d * d; }
    red[tid] = s2; __syncthreads();
    #pragma unroll
    for (int o = 128; o > 0; o >>= 1) { if (tid < o) red[tid] += red[tid + o]; __syncthreads(); }
    float var = red[0] * (1.f / DIM);
    float inv = rsqrtf(var + LN_EPS);
    #pragma unroll
    for (int i = 0; i < 3; i++) {
        int j = tid + 256 * i;
        hout[r * DIM + j] = (f[i] - mu) * inv * ln_scale[j] + ln_bias[j];
    }
}

// ---------------- host helper ----------------
static void launch_mma_s(cudaStream_t st, const uint32_t* Ap, const uint32_t* Wp,
                         float* C, long ldc, const float* bias, int M, int N, int K) {
    dim3 grid(N / 128, M / 128, 1);
    mma_gemm<<<grid, 256, 0, st>>>(Ap, Wp, C, ldc, bias, N / 128, C, ldc, bias, K / 32);
}

extern "C" void kernel_launch(void* const* d_in, const int* in_sizes, int n_in,
                              void* d_out, int out_size) {
    const float* x          = (const float*)d_in[0];
    const float* gcn_w      = (const float*)d_in[1];
    const float* gcn_b      = (const float*)d_in[2];
    const float* attn_in_w  = (const float*)d_in[3];
    const float* attn_in_b  = (const float*)d_in[4];
    const float* attn_out_w = (const float*)d_in[5];
    const float* attn_out_b = (const float*)d_in[6];
    const float* gate_w     = (const float*)d_in[7];
    const float* gate_b     = (const float*)d_in[8];
    const float* ln_scale   = (const float*)d_in[9];
    const float* ln_bias    = (const float*)d_in[10];
    const float* proj_w     = (const float*)d_in[11];
    const float* proj_b     = (const float*)d_in[12];
    float* out = (float*)d_out;

    static cudaStream_t s_side = nullptr;
    static cudaEvent_t ev_fork = nullptr, ev_graph = nullptr;
    if (!s_side) {
        cudaStreamCreateWithFlags(&s_side, cudaStreamNonBlocking);
        cudaEventCreateWithFlags(&ev_fork, cudaEventDisableTiming);
        cudaEventCreateWithFlags(&ev_graph, cudaEventDisableTiming);
    }

    float *p_h, *p_xw, *p_qkv, *p_scores, *p_ocat, *p_cat, *p_gate, *p_dinv, *p_vt;
    uint32_t *p_wp, *p_ap;
    unsigned char* p_adj;
    int* p_topk;
    cudaGetSymbolAddress((void**)&p_h, g_h);
    cudaGetSymbolAddress((void**)&p_xw, g_xw);
    cudaGetSymbolAddress((void**)&p_qkv, g_qkv);
    cudaGetSymbolAddress((void**)&p_scores, g_scores);
    cudaGetSymbolAddress((void**)&p_ocat, g_ocat);
    cudaGetSymbolAddress((void**)&p_cat, g_cat);
    cudaGetSymbolAddress((void**)&p_gate, g_gate);
    cudaGetSymbolAddress((void**)&p_dinv, g_dinv);
    cudaGetSymbolAddress((void**)&p_adj, g_adj);
    cudaGetSymbolAddress((void**)&p_topk, g_topk);
    cudaGetSymbolAddress((void**)&p_wp, g_wp);
    cudaGetSymbolAddress((void**)&p_ap, g_ap);
    cudaGetSymbolAddress((void**)&p_vt, g_vt);

    const float attn_scale = (float)(1.0 / sqrt((double)HDIM));
    dim3 tb(32, 8);

    // ---- fork: graph-construction chain on side stream ----
    cudaEventRecord(ev_fork, 0);
    cudaStreamWaitEvent(s_side, ev_fork, 0);
    sim_gemm<<<dim3(8, 8, BATCH), 256, 0, s_side>>>(x, p_scores);
    topk_select_kernel<<<ROWS, 256, 0, s_side>>>(p_scores, p_topk);
    zero_bytes_kernel<<<1024, 256, 0, s_side>>>(p_adj, (long long)BATCH * SEQ * SEQ);
    scatter_adj_kernel<<<(ROWS + 255) / 256, 256, 0, s_side>>>(p_topk, p_adj);
    degree_kernel<<<(ROWS + 255) / 256, 256, 0, s_side>>>(p_adj, p_dinv);
    cudaEventRecord(ev_graph, s_side);

    // ---- main stream: weight packs ----
    for (int l = 0; l < NLAYERS; l++) {
        pack_weights_kernel<<<512, 256>>>(gcn_w + (long)l * DIM * DIM, p_wp + WP_FUSED(l), DIM, DIM);
        pack_weights_kernel<<<512, 256>>>(attn_in_w + (long)l * DIM * 3 * DIM,
                                          p_wp + WP_FUSED(l) + 294912, 3 * DIM, DIM);
        pack_weights_kernel<<<512, 256>>>(attn_out_w + (long)l * DIM * DIM, p_wp + WP_AOW(l), DIM, DIM);
        pack_weights_kernel<<<512, 256>>>(gate_w + (long)l * 2 * DIM * DIM, p_wp + WP_GW(l), DIM, 2 * DIM);
    }
    pack_weights_kernel<<<512, 256>>>(proj_w, p_wp + WP_PROJ, DIM, DIM);

    bool joined = false;
    for (int l = 0; l < NLAYERS; l++) {
        const float* gb  = gcn_b + (long)l * DIM;
        const float* aib = attn_in_b + (long)l * 3 * DIM;
        const float* aob = attn_out_b + (long)l * DIM;
        const float* gtb = gate_b + (long)l * DIM;
        const float* lns = ln_scale + (long)l * DIM;
        const float* lnb = ln_bias + (long)l * DIM;
        const float* hin = (l == 0) ? x : p_h;

        // pack hin -> A blob; fused: XW -> xw (n-blocks 0-5), QKV -> qkv (n-blocks 6-23)
        pack_act_kernel<<<dim3(24, 64), 256>>>(hin, p_ap, DIM);
        {
            dim3 grid(24, ROWS / 128, 1);
            mma_gemm<<<grid, 256>>>(p_ap, p_wp + WP_FUSED(l),
                                    p_xw, DIM, gb, 6,
                                    p_qkv, 3 * DIM, aib,
                                    24);
        }
        // V transpose + flash attention (independent of graph chain)
        transpose_v_kernel<<<dim3(3, 32, 64), tb>>>(p_qkv, p_vt);
        flash_kernel<<<dim3(1, 8, 64), 256>>>(p_qkv, p_vt, p_ocat, attn_scale);
        // attn_out = O @ attn_out_w[l] + b -> cat[:, 768:1536]
        pack_act_kernel<<<dim3(24, 64), 256>>>(p_ocat, p_ap, DIM);
        launch_mma_s(0, p_ap, p_wp + WP_AOW(l), p_cat + DIM, 2 * DIM, aob, ROWS, DIM, DIM);
        // join with graph chain before first gcn_agg
        if (!joined) { cudaStreamWaitEvent(0, ev_graph, 0); joined = true; }
        // gcn_out -> cat[:, 0:768]
        gcn_agg_kernel<<<ROWS, 256>>>(p_adj, p_dinv, p_xw, gb, p_cat);
        // gate_lin = cat @ gate_w[l] + b
        pack_act_kernel<<<dim3(48, 64), 256>>>(p_cat, p_ap, 2 * DIM);
        launch_mma_s(0, p_ap, p_wp + WP_GW(l), p_gate, DIM, gtb, ROWS, DIM, 2 * DIM);
        // h = LN(gate*gcn + (1-gate)*attn + hin)
        fuse_ln_kernel<<<ROWS, 256>>>(p_gate, p_cat, hin, p_h, lns, lnb);
    }

    // out = h @ proj_w + proj_b
    pack_act_kernel<<<dim3(24, 64), 256>>>(p_h, p_ap, DIM);
    launch_mma_s(0, p_ap, p_wp + WP_PROJ, out, DIM, proj_b, ROWS, DIM, DIM);
}

// round 12
// speedup vs baseline: 7.4597x; 1.0191x over previous
#include <cuda_runtime.h>
#include <math.h>
#include <stdint.h>

// ---------------- problem constants ----------------
#define BATCH 8
#define SEQ   1024
#define DIM   768
#define HEADS 8
#define HDIM  96
#define KNEIGH 5
#define NLAYERS 3
#define ROWS (BATCH*SEQ)  // 8192
#define LN_EPS 1e-5f

// ---------------- device scratch (static, allocation-free) ----------------
__device__ float g_h[ROWS * DIM];
__device__ float g_xw[ROWS * DIM];
__device__ float g_qkv[ROWS * 3 * DIM];
__device__ float g_scores[(long long)BATCH * SEQ * SEQ]; // sim workspace (32 MB)
__device__ float g_cat[ROWS * 2 * DIM];   // [gcn | attn] stride 1536 (fp32 for fuse_ln)
__device__ float g_gate[ROWS * DIM];
__device__ unsigned char g_adj[(long long)BATCH * SEQ * SEQ];    // 8 MB
__device__ float g_dinv[ROWS];
__device__ int   g_topk[ROWS * KNEIGH];
__device__ uint32_t g_wp[6488064];         // fp16 fragment-packed weights (26 MB)
__device__ uint32_t g_ap[12582912];        // fp16 fragment-packed activations (50 MB)
__device__ float g_vt[ROWS * DIM];         // V transposed per (b,h): [64, 96, 1024]

// A-blob regions inside g_ap (words)
#define AP_H   0L          // h / x blob: 64 mblk x 24 kch
#define AP_O   3145728L    // attention-output blob: 64 x 24
#define AP_CAT 6291456L    // cat blob: 64 mblk x 48 kch

// packed weight word offsets
#define WP_FUSED(l) ((long)(l) * 1179648)
#define WP_AOW(l)   (3538944L + (long)(l) * 294912L)
#define WP_GW(l)    (4423680L + (long)(l) * 589824L)
#define WP_PROJ     (6193152L)

// pack two floats to half2 (lo = a, hi = b)
__device__ __forceinline__ uint32_t pack_h2(float a, float b) {
    uint32_t r;
    asm("cvt.rn.f16x2.f32 %0, %2, %1;" : "=r"(r) : "f"(a), "f"(b));
    return r;
}
__device__ __forceinline__ float h2f_lo(uint32_t h) {
    float f;
    asm("{.reg .b16 lo, hi;\n\t"
        "mov.b32 {lo, hi}, %1;\n\t"
        "cvt.f32.f16 %0, lo;}" : "=f"(f) : "r"(h));
    return f;
}
__device__ __forceinline__ float h2f_hi(uint32_t h) {
    float f;
    asm("{.reg .b16 lo, hi;\n\t"
        "mov.b32 {lo, hi}, %1;\n\t"
        "cvt.f32.f16 %0, hi;}" : "=f"(f) : "r"(h));
    return f;
}

// FMA-only exp (no MUFU)
__device__ __forceinline__ float fexp(float x) {
    x = fmaxf(x, -87.0f);
    float y = x * 1.4426950408889634f;
    int i = __float2int_rn(y);
    float r = (y - (float)i) * 0.6931471805599453f;
    float p = 1.9841270e-4f;
    p = fmaf(p, r, 1.3888889e-3f);
    p = fmaf(p, r, 8.3333333e-3f);
    p = fmaf(p, r, 4.1666667e-2f);
    p = fmaf(p, r, 1.6666667e-1f);
    p = fmaf(p, r, 0.5f);
    p = fmaf(p, r, 1.0f);
    p = fmaf(p, r, 1.0f);
    return p * __int_as_float((i + 127) << 23);
}

#define MMAF16(d, a, b) \
    asm volatile("mma.sync.aligned.m16n8k16.row.col.f32.f16.f16.f32 " \
        "{%0,%1,%2,%3}, {%4,%5,%6,%7}, {%8,%9}, {%0,%1,%2,%3};" \
        : "+f"((d)[0]), "+f"((d)[1]), "+f"((d)[2]), "+f"((d)[3]) \
        : "r"((a).x), "r"((a).y), "r"((a).z), "r"((a).w), \
          "r"((b).x), "r"((b).y))

// ---------------- weight packing: w [K,N] fp32 -> fragment-packed fp16 (B-layout) ----------------
__global__ void pack_weights_kernel(const float* __restrict__ w, uint32_t* __restrict__ wp,
                                    int N, int K) {
    int nch = K >> 5;
    long total = (long)N * (K >> 1);
    for (long tId = (long)blockIdx.x * blockDim.x + threadIdx.x; tId < total;
         tId += (long)gridDim.x * blockDim.x) {
        int n = (int)(tId % N);
        int kp = (int)(tId / N);
        int k = kp * 2;
        float v0 = w[(long)k * N + n];
        float v1 = w[(long)(k + 1) * N + n];
        long blk = (long)(n >> 7) * nch + (k >> 5);
        int nloc = n & 127, kloc = k & 31;
        int widx = ((((nloc >> 3) * 2 + ((kloc >> 4) & 1)) * 32
                     + (nloc & 7) * 4 + ((kloc >> 1) & 3)) * 2) + ((kloc >> 3) & 1);
        wp[blk * 2048 + widx] = pack_h2(v0, v1);
    }
}

// ---------------- activation packing (used only for x at layer 0) ----------------
__global__ void pack_act_kernel(const float* __restrict__ act, uint32_t* __restrict__ blob,
                                int K) {
    int kch = blockIdx.x, mblk = blockIdx.y;
    int nch = gridDim.x;
    const float* a0 = act + (long)mblk * 128 * K + kch * 32;
    uint32_t* out = blob + ((long)mblk * nch + kch) * 2048;
    int tid = threadIdx.x;
    #pragma unroll
    for (int i = 0; i < 8; i++) {
        int w = tid + 256 * i;
        int c = w & 3, lanep = (w >> 2) & 31, ikf = (w >> 7) & 1, im = w >> 8;
        int r = im * 16 + (c & 1) * 8 + (lanep >> 2);
        int k = ikf * 16 + ((c >> 1) & 1) * 8 + (lanep & 3) * 2;
        float2 v = *(const float2*)(a0 + (long)r * K + k);
        out[w] = pack_h2(v.x, v.y);
    }
}

// ---------------- sim = x x^T via fp16 hi/lo split (verified R9) ----------------
__global__ __launch_bounds__(256, 2)
void sim_gemm(const float* __restrict__ x, float* __restrict__ scores) {
    __shared__ uint32_t sAh[2048], sAl[2048], sBh[2048], sBl[2048];
    int b = blockIdx.z;
    int m0 = blockIdx.y * 128, n0 = blockIdx.x * 128;
    int tid = threadIdx.x, lane = tid & 31, wid = tid >> 5;
    int wm = wid & 1, wn = wid >> 1;
    const float* Xm = x + (long)b * SEQ * DIM + (long)m0 * DIM;
    const float* Xn = x + (long)b * SEQ * DIM + (long)n0 * DIM;

    int aR[4], aQ[4], aBase[4];
    #pragma unroll
    for (int i = 0; i < 4; i++) {
        int idx = tid + 256 * i;
        int r = idx >> 3, q = idx & 7;
        aR[i] = r; aQ[i] = q;
        int im = r >> 4, g = r & 7, row8 = (r >> 3) & 1;
        int ikf = q >> 2, k8 = (q >> 1) & 1;
        aBase[i] = ((im * 2 + ikf) * 32 + g * 4) * 4 + k8 * 2 + row8 + 8 * (q & 1);
    }
    int bR[4], bQ[4], bBase[4];
    #pragma unroll
    for (int i = 0; i < 4; i++) {
        int idx = tid + 256 * i;
        int r = idx >> 3, q = idx & 7;
        bR[i] = r; bQ[i] = q;
        int in = r >> 3, nn = r & 7;
        int ikf = q >> 2, k8 = (q >> 1) & 1;
        bBase[i] = ((in * 2 + ikf) * 32 + nn * 4) * 2 + k8 + 4 * (q & 1);
    }

    float acc[4][4][4];
    #pragma unroll
    for (int i = 0; i < 4; i++)
        #pragma unroll
        for (int j = 0; j < 4; j++)
            #pragma unroll
            for (int c = 0; c < 4; c++) acc[i][j][c] = 0.f;

    for (int it = 0; it < DIM / 32; it++) {
        long koff = (long)it * 32;
        float4 va[4], vb[4];
        #pragma unroll
        for (int i = 0; i < 4; i++)
            va[i] = *(const float4*)(Xm + (long)aR[i] * DIM + koff + aQ[i] * 4);
        #pragma unroll
        for (int i = 0; i < 4; i++)
            vb[i] = *(const float4*)(Xn + (long)bR[i] * DIM + koff + bQ[i] * 4);
        __syncthreads();
        #pragma unroll
        for (int i = 0; i < 4; i++) {
            uint32_t h0 = pack_h2(va[i].x, va[i].y);
            uint32_t h1 = pack_h2(va[i].z, va[i].w);
            uint32_t l0 = pack_h2(va[i].x - h2f_lo(h0), va[i].y - h2f_hi(h0));
            uint32_t l1 = pack_h2(va[i].z - h2f_lo(h1), va[i].w - h2f_hi(h1));
            sAh[aBase[i]] = h0; sAh[aBase[i] + 4] = h1;
            sAl[aBase[i]] = l0; sAl[aBase[i] + 4] = l1;
        }
        #pragma unroll
        for (int i = 0; i < 4; i++) {
            uint32_t h0 = pack_h2(vb[i].x, vb[i].y);
            uint32_t h1 = pack_h2(vb[i].z, vb[i].w);
            uint32_t l0 = pack_h2(vb[i].x - h2f_lo(h0), vb[i].y - h2f_hi(h0));
            uint32_t l1 = pack_h2(vb[i].z - h2f_lo(h1), vb[i].w - h2f_hi(h1));
            sBh[bBase[i]] = h0; sBh[bBase[i] + 2] = h1;
            sBl[bBase[i]] = l0; sBl[bBase[i] + 2] = l1;
        }
        __syncthreads();
        #pragma unroll
        for (int ikf = 0; ikf < 2; ikf++) {
            uint2 bh[4], bl[4];
            #pragma unroll
            for (int j2 = 0; j2 < 4; j2++) {
                int o = (((wn * 4 + j2) * 2 + ikf) * 32 + lane) * 2;
                bh[j2] = *(const uint2*)&sBh[o];
                bl[j2] = *(const uint2*)&sBl[o];
            }
            #pragma unroll
            for (int i2 = 0; i2 < 4; i2++) {
                int o = (((wm * 4 + i2) * 2 + ikf) * 32 + lane) * 4;
                uint4 ah = *(const uint4*)&sAh[o];
                uint4 al = *(const uint4*)&sAl[o];
                #pragma unroll
                for (int j2 = 0; j2 < 4; j2++) {
                    MMAF16(acc[i2][j2], ah, bh[j2]);
                    MMAF16(acc[i2][j2], ah, bl[j2]);
                    MMAF16(acc[i2][j2], al, bh[j2]);
                }
            }
        }
    }

    int g = lane >> 2, t = lane & 3;
    float* C = scores + (long)b * SEQ * SEQ;
    #pragma unroll
    for (int i2 = 0; i2 < 4; i2++) {
        int gm = m0 + (wm * 4 + i2) * 16 + g;
        #pragma unroll
        for (int j2 = 0; j2 < 4; j2++) {
            int gn = n0 + (wn * 4 + j2) * 8 + t * 2;
            *(float2*)&C[(long)gm * SEQ + gn] = make_float2(acc[i2][j2][0], acc[i2][j2][1]);
            *(float2*)&C[(long)(gm + 8) * SEQ + gn] = make_float2(acc[i2][j2][2], acc[i2][j2][3]);
        }
    }
}

// ---------------- flash attention: output written directly as packed A-blob ----------------
__global__ __launch_bounds__(256, 1)
void flash_kernel(const float* __restrict__ qkv, const float* __restrict__ vt,
                  uint32_t* __restrict__ oblob, float scale) {
    __shared__ uint32_t sK[6144];
    __shared__ uint32_t sV[6144];
    int z = blockIdx.z, b = z >> 3, h = z & 7;
    int m0 = blockIdx.y * 128;
    int tid = threadIdx.x, lane = tid & 31, wid = tid >> 5;
    int t = lane & 3, g = lane >> 2;

    const float* Qg = qkv + ((long)b * 1024 + m0) * 2304 + h * 96;
    const float* Kg = qkv + (long)b * 1024 * 2304 + 768 + h * 96;
    const float* Vg = vt + (long)z * 96 * 1024;

    #pragma unroll
    for (int i = 0; i < 12; i++) {
        int idx = tid + 256 * i;
        int r = idx / 24, q = idx % 24;
        int k0 = q * 4;
        int im = r >> 4, gg = r & 7, row8 = (r >> 3) & 1;
        int kg = k0 >> 4, k8 = (k0 >> 3) & 1, t0 = (k0 >> 1) & 3;
        int base = ((im * 6 + kg) * 32 + gg * 4 + t0) * 4 + row8 + 2 * k8;
        float4 v = *(const float4*)(Qg + (long)r * 2304 + k0);
        sK[base]     = pack_h2(v.x, v.y);
        sK[base + 4] = pack_h2(v.z, v.w);
    }
    __syncthreads();
    uint4 qf[6];
    #pragma unroll
    for (int kg = 0; kg < 6; kg++)
        qf[kg] = *(const uint4*)&sK[((wid * 6 + kg) * 32 + lane) * 4];
    __syncthreads();

    float mr0 = -1e30f, mr1 = -1e30f, l0 = 0.f, l1 = 0.f;
    float accO[12][4];
    #pragma unroll
    for (int j = 0; j < 12; j++)
        #pragma unroll
        for (int c = 0; c < 4; c++) accO[j][c] = 0.f;

    for (int kt = 0; kt < 8; kt++) {
        #pragma unroll
        for (int i = 0; i < 12; i++) {
            int idx = tid + 256 * i;
            int r = idx / 24, q = idx % 24;
            int k0 = q * 4;
            int jn = r >> 3, nn = r & 7;
            int kg = k0 >> 4, k8 = (k0 >> 3) & 1, t0 = (k0 >> 1) & 3;
            int base = ((jn * 6 + kg) * 32 + nn * 4 + t0) * 2 + k8;
            float4 v = *(const float4*)(Kg + (long)(kt * 128 + r) * 2304 + k0);
            sK[base]     = pack_h2(v.x, v.y);
            sK[base + 2] = pack_h2(v.z, v.w);
        }
        #pragma unroll
        for (int i = 0; i < 12; i++) {
            int idx = tid + 256 * i;
            int r = idx >> 5, q = idx & 31;
            int k0 = q * 4;
            int jn = r >> 3, nn = r & 7;
            int kg = k0 >> 4, k8 = (k0 >> 3) & 1, t0 = (k0 >> 1) & 3;
            int base = ((jn * 8 + kg) * 32 + nn * 4 + t0) * 2 + k8;
            float4 v = *(const float4*)(Vg + (long)r * 1024 + kt * 128 + k0);
            sV[base]     = pack_h2(v.x, v.y);
            sV[base + 2] = pack_h2(v.z, v.w);
        }
        __syncthreads();

        float accS[16][4];
        #pragma unroll
        for (int j = 0; j < 16; j++)
            #pragma unroll
            for (int c = 0; c < 4; c++) accS[j][c] = 0.f;
        #pragma unroll
        for (int kg = 0; kg < 6; kg++)
            #pragma unroll
            for (int jn = 0; jn < 16; jn++) {
                uint2 bf = *(const uint2*)&sK[((jn * 6 + kg) * 32 + lane) * 2];
                MMAF16(accS[jn], qf[kg], bf);
            }

        float mx0 = -1e30f, mx1 = -1e30f;
        #pragma unroll
        for (int jn = 0; jn < 16; jn++) {
            accS[jn][0] *= scale; accS[jn][1] *= scale;
            accS[jn][2] *= scale; accS[jn][3] *= scale;
            mx0 = fmaxf(mx0, fmaxf(accS[jn][0], accS[jn][1]));
            mx1 = fmaxf(mx1, fmaxf(accS[jn][2], accS[jn][3]));
        }
        mx0 = fmaxf(mx0, __shfl_xor_sync(0xffffffffu, mx0, 1));
        mx0 = fmaxf(mx0, __shfl_xor_sync(0xffffffffu, mx0, 2));
        mx1 = fmaxf(mx1, __shfl_xor_sync(0xffffffffu, mx1, 1));
        mx1 = fmaxf(mx1, __shfl_xor_sync(0xffffffffu, mx1, 2));

        float mn0 = fmaxf(mr0, mx0), mn1 = fmaxf(mr1, mx1);
        float cr0 = fexp(mr0 - mn0), cr1 = fexp(mr1 - mn1);

        float s0 = 0.f, s1 = 0.f;
        uint32_t plo[16], phi[16];
        #pragma unroll
        for (int jn = 0; jn < 16; jn++) {
            float e0 = fexp(accS[jn][0] - mn0);
            float e1 = fexp(accS[jn][1] - mn0);
            float e2 = fexp(accS[jn][2] - mn1);
            float e3 = fexp(accS[jn][3] - mn1);
            s0 += e0 + e1; s1 += e2 + e3;
            plo[jn] = pack_h2(e0, e1);
            phi[jn] = pack_h2(e2, e3);
        }
        s0 += __shfl_xor_sync(0xffffffffu, s0, 1);
        s0 += __shfl_xor_sync(0xffffffffu, s0, 2);
        s1 += __shfl_xor_sync(0xffffffffu, s1, 1);
        s1 += __shfl_xor_sync(0xffffffffu, s1, 2);

        l0 = l0 * cr0 + s0;
        l1 = l1 * cr1 + s1;
        mr0 = mn0; mr1 = mn1;
        #pragma unroll
        for (int j = 0; j < 12; j++) {
            accO[j][0] *= cr0; accO[j][1] *= cr0;
            accO[j][2] *= cr1; accO[j][3] *= cr1;
        }

        #pragma unroll
        for (int kg = 0; kg < 8; kg++) {
            uint4 af = make_uint4(plo[2 * kg], phi[2 * kg], plo[2 * kg + 1], phi[2 * kg + 1]);
            #pragma unroll
            for (int jn = 0; jn < 12; jn++) {
                uint2 bf = *(const uint2*)&sV[((jn * 8 + kg) * 32 + lane) * 2];
                MMAF16(accO[jn], af, bf);
            }
        }
        __syncthreads();
    }

    // epilogue: write packed A-blob words directly (verified lane identity)
    float inv0 = 1.f / l0, inv1 = 1.f / l1;
    long row0 = (long)(b * 1024 + m0 + wid * 16 + g);
    long mblk = row0 >> 7;
    #pragma unroll
    for (int jn = 0; jn < 12; jn++) {
        int kglob = h * 96 + jn * 8 + t * 2;
        int kch = kglob >> 5;
        int ikf = (jn >> 1) & 1, k8 = jn & 1;
        long word = ((mblk * 24 + kch) * 2048) + wid * 256 + ikf * 128 + lane * 4 + 2 * k8;
        uint2 pw;
        pw.x = pack_h2(accO[jn][0] * inv0, accO[jn][1] * inv0);
        pw.y = pack_h2(accO[jn][2] * inv1, accO[jn][3] * inv1);
        *(uint2*)&oblob[word] = pw;
    }
}

// ---------------- mma.sync fp16 GEMM + optional packed-A-blob emitter ----------------
__global__ __launch_bounds__(256, 2)
void mma_gemm(const uint32_t* __restrict__ Ap,
              const uint32_t* __restrict__ Wp,
              float* __restrict__ C0, long ldc0, const float* __restrict__ bias0, int nsplit,
              float* __restrict__ C1, long ldc1, const float* __restrict__ bias1,
              int nch,
              uint32_t* __restrict__ packBlob, int packNch, int packKchBase) {
    __shared__ uint32_t sA[2][2048];
    __shared__ uint32_t sB[2][2048];

    int tid = threadIdx.x, lane = tid & 31, wid = tid >> 5;
    int wm = wid & 1, wn = wid >> 1;

    const uint4* Ab = (const uint4*)(Ap + (long)blockIdx.y * nch * 2048);
    const uint4* Wb = (const uint4*)(Wp + (long)blockIdx.x * nch * 2048);

    float acc[4][4][4];
    #pragma unroll
    for (int i = 0; i < 4; i++)
        #pragma unroll
        for (int j = 0; j < 4; j++)
            #pragma unroll
            for (int c = 0; c < 4; c++) acc[i][j][c] = 0.f;

    uint4 va0 = Ab[tid], va1 = Ab[tid + 256];
    uint4 vb0 = Wb[tid], vb1 = Wb[tid + 256];
    ((uint4*)sA[0])[tid] = va0; ((uint4*)sA[0])[tid + 256] = va1;
    ((uint4*)sB[0])[tid] = vb0; ((uint4*)sB[0])[tid + 256] = vb1;
    __syncthreads();

    for (int it = 0; it < nch; it++) {
        int buf = it & 1;
        bool more = (it + 1 < nch);
        if (more) {
            const uint4* An = Ab + (long)(it + 1) * 512;
            const uint4* Wn = Wb + (long)(it + 1) * 512;
            va0 = An[tid]; va1 = An[tid + 256];
            vb0 = Wn[tid]; vb1 = Wn[tid + 256];
        }
        #pragma unroll
        for (int ikf = 0; ikf < 2; ikf++) {
            uint4 af[4];
            uint2 bf[4];
            #pragma unroll
            for (int i2 = 0; i2 < 4; i2++)
                af[i2] = *(const uint4*)&sA[buf][(((wm * 4 + i2) * 2 + ikf) * 32 + lane) * 4];
            #pragma unroll
            for (int j2 = 0; j2 < 4; j2++)
                bf[j2] = *(const uint2*)&sB[buf][(((wn * 4 + j2) * 2 + ikf) * 32 + lane) * 2];
            #pragma unroll
            for (int i2 = 0; i2 < 4; i2++)
                #pragma unroll
                for (int j2 = 0; j2 < 4; j2++)
                    MMAF16(acc[i2][j2], af[i2], bf[j2]);
        }
        __syncthreads();
        if (more) {
            int nb = buf ^ 1;
            ((uint4*)sA[nb])[tid] = va0; ((uint4*)sA[nb])[tid + 256] = va1;
            ((uint4*)sB[nb])[tid] = vb0; ((uint4*)sB[nb])[tid + 256] = vb1;
            __syncthreads();
        }
    }

    float* C; long ldc; const float* bias; int n0;
    if ((int)blockIdx.x < nsplit) {
        C = C0; ldc = ldc0; bias = bias0; n0 = blockIdx.x * 128;
    } else {
        C = C1; ldc = ldc1; bias = bias1; n0 = (blockIdx.x - nsplit) * 128;
    }
    int m0 = blockIdx.y * 128;
    int g = lane >> 2, t = lane & 3;
    #pragma unroll
    for (int i2 = 0; i2 < 4; i2++) {
        int im = wm * 4 + i2;
        int gm = m0 + im * 16 + g;
        #pragma unroll
        for (int j2 = 0; j2 < 4; j2++) {
            int gn = n0 + (wn * 4 + j2) * 8 + t * 2;
            float b0 = __ldg(bias + gn);
            float b1 = __ldg(bias + gn + 1);
            float2 v0, v1;
            v0.x = acc[i2][j2][0] + b0;
            v0.y = acc[i2][j2][1] + b1;
            v1.x = acc[i2][j2][2] + b0;
            v1.y = acc[i2][j2][3] + b1;
            *(float2*)&C[(long)gm * ldc + gn] = v0;
            *(float2*)&C[(long)(gm + 8) * ldc + gn] = v1;
            if (packBlob) {
                int kch = packKchBase + (n0 >> 5) + wn;
                long word = (((long)blockIdx.y * packNch + kch) * 2048)
                          + im * 256 + (j2 >> 1) * 128 + lane * 4 + 2 * (j2 & 1);
                uint2 pw;
                pw.x = pack_h2(v0.x, v0.y);
                pw.y = pack_h2(v1.x, v1.y);
                *(uint2*)&packBlob[word] = pw;
            }
        }
    }
}

// ---------------- V transpose for flash ----------------
__global__ void transpose_v_kernel(const float* __restrict__ qkv, float* __restrict__ vt) {
    int z = blockIdx.z; int b = z >> 3, h = z & 7;
    __shared__ float tb[32][33];
    int d0 = blockIdx.x * 32, t0 = blockIdx.y * 32;
    int tx = threadIdx.x, ty = threadIdx.y;
    const float* src = qkv + (long)b * 1024 * 2304 + 1536 + h * 96;
    for (int i = ty; i < 32; i += 8)
        tb[i][tx] = src[(long)(t0 + i) * 2304 + d0 + tx];
    __syncthreads();
    float* dst = vt + ((long)z * 96 + d0) * 1024 + t0;
    for (int j = ty; j < 32; j += 8)
        dst[(long)j * 1024 + tx] = tb[tx][j];
}

// ---------------- misc ----------------
__global__ void zero_bytes_kernel(unsigned char* p, long n) {
    long i = (long)blockIdx.x * blockDim.x + threadIdx.x;
    long stride = (long)gridDim.x * blockDim.x;
    int* pi = (int*)p;
    long nw = n >> 2;
    for (; i < nw; i += stride) pi[i] = 0;
}

// ---------------- topk select ----------------
__global__ void topk_select_kernel(const float* __restrict__ sim, int* __restrict__ idx_out) {
    long r = blockIdx.x;
    const float* row = sim + r * SEQ;
    __shared__ float s[SEQ];
    __shared__ float bv[256];
    __shared__ int   bi[256];
    int tid = threadIdx.x;
    for (int i = tid; i < SEQ; i += 256) s[i] = row[i];
    __syncthreads();
    for (int sel = 0; sel < KNEIGH; sel++) {
        float v = -INFINITY; int mi = 0x7fffffff;
        for (int t = tid; t < SEQ; t += 256) {
            float sv = s[t];
            if (sv > v || (sv == v && t < mi)) { v = sv; mi = t; }
        }
        bv[tid] = v; bi[tid] = mi;
        __syncthreads();
        for (int o = 128; o > 0; o >>= 1) {
            if (tid < o) {
                if (bv[tid + o] > bv[tid] || (bv[tid + o] == bv[tid] && bi[tid + o] < bi[tid])) {
                    bv[tid] = bv[tid + o]; bi[tid] = bi[tid + o];
                }
            }
            __syncthreads();
        }
        if (tid == 0) { idx_out[r * KNEIGH + sel] = bi[0]; s[bi[0]] = -INFINITY; }
        __syncthreads();
    }
}

// ---------------- adjacency + degree ----------------
__global__ void scatter_adj_kernel(const int* __restrict__ idx, unsigned char* __restrict__ A) {
    int r = blockIdx.x * blockDim.x + threadIdx.x;
    if (r >= ROWS) return;
    int b = r >> 10, s = r & 1023;
    unsigned char* Ab = A + (long long)b * SEQ * SEQ;
    Ab[(long)s * SEQ + s] = 1;
    #pragma unroll
    for (int j = 0; j < KNEIGH; j++) {
        int t = idx[(long)r * KNEIGH + j];
        Ab[(long)s * SEQ + t] = 1;
        Ab[(long)t * SEQ + s] = 1;
    }
}
__global__ void degree_kernel(const unsigned char* __restrict__ A, float* __restrict__ dinv) {
    int r = blockIdx.x * blockDim.x + threadIdx.x;
    if (r >= ROWS) return;
    const uint32_t* row = (const uint32_t*)(A + (long long)r * SEQ);
    int d = 0;
    for (int i = 0; i < SEQ / 4; i++) {
        uint32_t w = row[i];
        d += (w & 0xff) + ((w >> 8) & 0xff) + ((w >> 16) & 0xff) + ((w >> 24) & 0xff);
    }
    dinv[r] = rsqrtf((float)d);
}

// ---------------- sparse GCN aggregate: cat fp32 + cat-blob (kch 0..23) ----------------
__global__ void gcn_agg_kernel(const unsigned char* __restrict__ A, const float* __restrict__ dinv,
                               const float* __restrict__ xw, const float* __restrict__ gcn_b,
                               float* __restrict__ cat, uint32_t* __restrict__ catblob) {
    int r = blockIdx.x;
    int b = r >> 10;
    const unsigned char* Arow = A + (long long)r * SEQ;
    __shared__ int   nbr[SEQ];
    __shared__ float wgt[SEQ];
    __shared__ float sbuf[DIM];
    __shared__ int cnt;
    int tid = threadIdx.x;
    if (tid == 0) cnt = 0;
    __syncthreads();
    for (int t = tid; t < SEQ; t += 256) {
        if (Arow[t]) {
            int p = atomicAdd(&cnt, 1);
            nbr[p] = t;
            wgt[p] = dinv[(b << 10) + t];
        }
    }
    __syncthreads();
    int n = cnt;
    float acc0 = 0.f, acc1 = 0.f, acc2 = 0.f;
    for (int i = 0; i < n; i++) {
        const float* row = xw + ((long)(b << 10) + nbr[i]) * DIM;
        float w = wgt[i];
        acc0 += w * row[tid];
        acc1 += w * row[tid + 256];
        acc2 += w * row[tid + 512];
    }
    float ws = dinv[r];
    long base = (long)r * (2 * DIM);
    float o0 = ws * acc0 + gcn_b[tid];
    float o1 = ws * acc1 + gcn_b[tid + 256];
    float o2 = ws * acc2 + gcn_b[tid + 512];
    cat[base + tid]       = o0;
    cat[base + tid + 256] = o1;
    cat[base + tid + 512] = o2;
    sbuf[tid] = o0; sbuf[tid + 256] = o1; sbuf[tid + 512] = o2;
    __syncthreads();
    // pack to cat blob (nchTot = 48, kchBase = 0)
    long mblk = r >> 7;
    int rloc = r & 127;
    int im = rloc >> 4, row8 = (rloc >> 3) & 1, g = rloc & 7;
    for (int w = tid; w < 384; w += 256) {
        int kch = w >> 4, ikf = (w >> 3) & 1, k8 = (w >> 2) & 1, t = w & 3;
        long word = ((mblk * 48 + kch) * 2048) + im * 256 + ikf * 128
                  + (g * 4 + t) * 4 + 2 * k8 + row8;
        catblob[word] = pack_h2(sbuf[2 * w], sbuf[2 * w + 1]);
    }
}

// ---------------- gate + residual + layernorm: h fp32 + h-blob ----------------
__global__ void fuse_ln_kernel(const float* __restrict__ gatelin, const float* __restrict__ cat,
                               const float* __restrict__ hin, float* __restrict__ hout,
                               uint32_t* __restrict__ hblob,
                               const float* __restrict__ ln_scale, const float* __restrict__ ln_bias) {
    long r = blockIdx.x;
    int tid = threadIdx.x;
    __shared__ float red[256];
    __shared__ float sbuf[DIM];
    float f[3];
    #pragma unroll
    for (int i = 0; i < 3; i++) {
        int j = tid + 256 * i;
        float g  = gatelin[r * DIM + j];
        float gc = cat[r * (2 * DIM) + j];
        float at = cat[r * (2 * DIM) + DIM + j];
        float sg = 1.f / (1.f + fexp(-g));
        f[i] = sg * gc + (1.f - sg) * at + hin[r * DIM + j];
    }
    float s1 = f[0] + f[1] + f[2];
    red[tid] = s1; __syncthreads();
    #pragma unroll
    for (int o = 128; o > 0; o >>= 1) { if (tid < o) red[tid] += red[tid + o]; __syncthreads(); }
    float mu = red[0] * (1.f / DIM);
    __syncthreads();
    float s2 = 0.f;
    #pragma unroll
    for (int i = 0; i < 3; i++) { float d = f[i] - mu; s2 += d * d; }
    red[tid] = s2; __syncthreads();
    #pragma unroll
    for (int o = 128; o > 0; o >>= 1) { if (tid < o) red[tid] += red[tid + o]; __syncthreads(); }
    float var = red[0] * (1.f / DIM);
    float inv = rsqrtf(var + LN_EPS);
    #pragma unroll
    for (int i = 0; i < 3; i++) {
        int j = tid + 256 * i;
        float v = (f[i] - mu) * inv * ln_scale[j] + ln_bias[j];
        hout[r * DIM + j] = v;
        sbuf[j] = v;
    }
    __syncthreads();
    long mblk = r >> 7;
    int rloc = (int)(r & 127);
    int im = rloc >> 4, row8 = (rloc >> 3) & 1, g = rloc & 7;
    for (int w = tid; w < 384; w += 256) {
        int kch = w >> 4, ikf = (w >> 3) & 1, k8 = (w >> 2) & 1, t = w & 3;
        long word = ((mblk * 24 + kch) * 2048) + im * 256 + ikf * 128
                  + (g * 4 + t) * 4 + 2 * k8 + row8;
        hblob[word] = pack_h2(sbuf[2 * w], sbuf[2 * w + 1]);
    }
}

// ---------------- host helper ----------------
static void launch_mma(const uint32_t* Ap, const uint32_t* Wp, float* C, long ldc,
                       const float* bias, int M, int N, int K,
                       uint32_t* packBlob = nullptr, int packNch = 0, int packKchBase = 0) {
    dim3 grid(N / 128, M / 128, 1);
    mma_gemm<<<grid, 256>>>(Ap, Wp, C, ldc, bias, N / 128, C, ldc, bias, K / 32,
                            packBlob, packNch, packKchBase);
}

extern "C" void kernel_launch(void* const* d_in, const int* in_sizes, int n_in,
                              void* d_out, int out_size) {
    const float* x          = (const float*)d_in[0];
    const float* gcn_w      = (const float*)d_in[1];
    const float* gcn_b      = (const float*)d_in[2];
    const float* attn_in_w  = (const float*)d_in[3];
    const float* attn_in_b  = (const float*)d_in[4];
    const float* attn_out_w = (const float*)d_in[5];
    const float* attn_out_b = (const float*)d_in[6];
    const float* gate_w     = (const float*)d_in[7];
    const float* gate_b     = (const float*)d_in[8];
    const float* ln_scale   = (const float*)d_in[9];
    const float* ln_bias    = (const float*)d_in[10];
    const float* proj_w     = (const float*)d_in[11];
    const float* proj_b     = (const float*)d_in[12];
    float* out = (float*)d_out;

    static cudaStream_t s_side = nullptr;
    static cudaEvent_t ev_fork = nullptr, ev_graph = nullptr;
    if (!s_side) {
        cudaStreamCreateWithFlags(&s_side, cudaStreamNonBlocking);
        cudaEventCreateWithFlags(&ev_fork, cudaEventDisableTiming);
        cudaEventCreateWithFlags(&ev_graph, cudaEventDisableTiming);
    }

    float *p_h, *p_xw, *p_qkv, *p_scores, *p_cat, *p_gate, *p_dinv, *p_vt;
    uint32_t *p_wp, *p_ap;
    unsigned char* p_adj;
    int* p_topk;
    cudaGetSymbolAddress((void**)&p_h, g_h);
    cudaGetSymbolAddress((void**)&p_xw, g_xw);
    cudaGetSymbolAddress((void**)&p_qkv, g_qkv);
    cudaGetSymbolAddress((void**)&p_scores, g_scores);
    cudaGetSymbolAddress((void**)&p_cat, g_cat);
    cudaGetSymbolAddress((void**)&p_gate, g_gate);
    cudaGetSymbolAddress((void**)&p_dinv, g_dinv);
    cudaGetSymbolAddress((void**)&p_adj, g_adj);
    cudaGetSymbolAddress((void**)&p_topk, g_topk);
    cudaGetSymbolAddress((void**)&p_wp, g_wp);
    cudaGetSymbolAddress((void**)&p_ap, g_ap);
    cudaGetSymbolAddress((void**)&p_vt, g_vt);

    const float attn_scale = (float)(1.0 / sqrt((double)HDIM));
    dim3 tb(32, 8);

    // ---- fork: graph-construction chain on side stream ----
    cudaEventRecord(ev_fork, 0);
    cudaStreamWaitEvent(s_side, ev_fork, 0);
    sim_gemm<<<dim3(8, 8, BATCH), 256, 0, s_side>>>(x, p_scores);
    topk_select_kernel<<<ROWS, 256, 0, s_side>>>(p_scores, p_topk);
    zero_bytes_kernel<<<1024, 256, 0, s_side>>>(p_adj, (long long)BATCH * SEQ * SEQ);
    scatter_adj_kernel<<<(ROWS + 255) / 256, 256, 0, s_side>>>(p_topk, p_adj);
    degree_kernel<<<(ROWS + 255) / 256, 256, 0, s_side>>>(p_adj, p_dinv);
    cudaEventRecord(ev_graph, s_side);

    // ---- main stream: weight packs + x blob ----
    for (int l = 0; l < NLAYERS; l++) {
        pack_weights_kernel<<<512, 256>>>(gcn_w + (long)l * DIM * DIM, p_wp + WP_FUSED(l), DIM, DIM);
        pack_weights_kernel<<<512, 256>>>(attn_in_w + (long)l * DIM * 3 * DIM,
                                          p_wp + WP_FUSED(l) + 294912, 3 * DIM, DIM);
        pack_weights_kernel<<<512, 256>>>(attn_out_w + (long)l * DIM * DIM, p_wp + WP_AOW(l), DIM, DIM);
        pack_weights_kernel<<<512, 256>>>(gate_w + (long)l * 2 * DIM * DIM, p_wp + WP_GW(l), DIM, 2 * DIM);
    }
    pack_weights_kernel<<<512, 256>>>(proj_w, p_wp + WP_PROJ, DIM, DIM);
    pack_act_kernel<<<dim3(24, 64), 256>>>(x, p_ap + AP_H, DIM);   // layer-0 A blob

    bool joined = false;
    for (int l = 0; l < NLAYERS; l++) {
        const float* gb  = gcn_b + (long)l * DIM;
        const float* aib = attn_in_b + (long)l * 3 * DIM;
        const float* aob = attn_out_b + (long)l * DIM;
        const float* gtb = gate_b + (long)l * DIM;
        const float* lns = ln_scale + (long)l * DIM;
        const float* lnb = ln_bias + (long)l * DIM;
        const float* hin = (l == 0) ? x : p_h;

        // fused: XW -> xw (n-blocks 0-5), QKV -> qkv (n-blocks 6-23); A = h blob
        {
            dim3 grid(24, ROWS / 128, 1);
            mma_gemm<<<grid, 256>>>(p_ap + AP_H, p_wp + WP_FUSED(l),
                                    p_xw, DIM, gb, 6,
                                    p_qkv, 3 * DIM, aib,
                                    24, nullptr, 0, 0);
        }
        // V transpose + flash attention -> packed O blob
        transpose_v_kernel<<<dim3(3, 32, 64), tb>>>(p_qkv, p_vt);
        flash_kernel<<<dim3(1, 8, 64), 256>>>(p_qkv, p_vt, p_ap + AP_O, attn_scale);
        // attn_out GEMM: cat fp32 [:,768:1536] + cat blob kch 24-47
        launch_mma(p_ap + AP_O, p_wp + WP_AOW(l), p_cat + DIM, 2 * DIM, aob,
                   ROWS, DIM, DIM, p_ap + AP_CAT, 48, 24);
        // join with graph chain before first gcn_agg
        if (!joined) { cudaStreamWaitEvent(0, ev_graph, 0); joined = true; }
        // gcn_out -> cat fp32 [:,0:768] + cat blob kch 0-23
        gcn_agg_kernel<<<ROWS, 256>>>(p_adj, p_dinv, p_xw, gb, p_cat, p_ap + AP_CAT);
        // gate_lin = cat @ gate_w[l] + b  (A = cat blob)
        launch_mma(p_ap + AP_CAT, p_wp + WP_GW(l), p_gate, DIM, gtb, ROWS, DIM, 2 * DIM);
        // h = LN(gate*gcn + (1-gate)*attn + hin) -> h fp32 + h blob
        fuse_ln_kernel<<<ROWS, 256>>>(p_gate, p_cat, hin, p_h, p_ap + AP_H, lns, lnb);
    }

    // out = h @ proj_w + proj_b  (A = h blob from last fuse_ln)
    launch_mma(p_ap + AP_H, p_wp + WP_PROJ, out, DIM, proj_b, ROWS, DIM, DIM);
}

// round 13
// speedup vs baseline: 7.6705x; 1.0282x over previous
#include <cuda_runtime.h>
#include <math.h>
#include <stdint.h>

// ---------------- problem constants ----------------
#define BATCH 8
#define SEQ   1024
#define DIM   768
#define HEADS 8
#define HDIM  96
#define KNEIGH 5
#define NLAYERS 3
#define ROWS (BATCH*SEQ)  // 8192
#define LN_EPS 1e-5f

// ---------------- device scratch (static, allocation-free) ----------------
__device__ float g_h[ROWS * DIM];
__device__ float g_xw[ROWS * DIM];
__device__ float g_qkv[ROWS * 3 * DIM];
__device__ float g_scores[(long long)BATCH * SEQ * SEQ]; // sim workspace (32 MB)
__device__ float g_cat[ROWS * 2 * DIM];   // [gcn | attn] stride 1536 (fp32 for fuse_ln)
__device__ float g_gate[ROWS * DIM];
__device__ unsigned char g_adj[(long long)BATCH * SEQ * SEQ];    // 8 MB
__device__ float g_dinv[ROWS];
__device__ int   g_topk[ROWS * KNEIGH];
__device__ uint32_t g_wp[6488064];         // fp16 fragment-packed weights (26 MB)
__device__ uint32_t g_ap[12582912];        // fp16 fragment-packed activations (50 MB)
__device__ float g_vt[ROWS * DIM];         // V transposed per (b,h): [64, 96, 1024]

// A-blob regions inside g_ap (words)
#define AP_H   0L          // h / x blob: 64 mblk x 24 kch
#define AP_O   3145728L    // attention-output blob: 64 x 24
#define AP_CAT 6291456L    // cat blob: 64 mblk x 48 kch

// packed weight word offsets
#define WP_FUSED(l) ((long)(l) * 1179648)
#define WP_AOW(l)   (3538944L + (long)(l) * 294912L)
#define WP_GW(l)    (4423680L + (long)(l) * 589824L)
#define WP_PROJ     (6193152L)

// pack two floats to half2 (lo = a, hi = b)
__device__ __forceinline__ uint32_t pack_h2(float a, float b) {
    uint32_t r;
    asm("cvt.rn.f16x2.f32 %0, %2, %1;" : "=r"(r) : "f"(a), "f"(b));
    return r;
}
__device__ __forceinline__ float h2f_lo(uint32_t h) {
    float f;
    asm("{.reg .b16 lo, hi;\n\t"
        "mov.b32 {lo, hi}, %1;\n\t"
        "cvt.f32.f16 %0, lo;}" : "=f"(f) : "r"(h));
    return f;
}
__device__ __forceinline__ float h2f_hi(uint32_t h) {
    float f;
    asm("{.reg .b16 lo, hi;\n\t"
        "mov.b32 {lo, hi}, %1;\n\t"
        "cvt.f32.f16 %0, hi;}" : "=f"(f) : "r"(h));
    return f;
}

// FMA-only exp (no MUFU)
__device__ __forceinline__ float fexp(float x) {
    x = fmaxf(x, -87.0f);
    float y = x * 1.4426950408889634f;
    int i = __float2int_rn(y);
    float r = (y - (float)i) * 0.6931471805599453f;
    float p = 1.9841270e-4f;
    p = fmaf(p, r, 1.3888889e-3f);
    p = fmaf(p, r, 8.3333333e-3f);
    p = fmaf(p, r, 4.1666667e-2f);
    p = fmaf(p, r, 1.6666667e-1f);
    p = fmaf(p, r, 0.5f);
    p = fmaf(p, r, 1.0f);
    p = fmaf(p, r, 1.0f);
    return p * __int_as_float((i + 127) << 23);
}

#define MMAF16(d, a, b) \
    asm volatile("mma.sync.aligned.m16n8k16.row.col.f32.f16.f16.f32 " \
        "{%0,%1,%2,%3}, {%4,%5,%6,%7}, {%8,%9}, {%0,%1,%2,%3};" \
        : "+f"((d)[0]), "+f"((d)[1]), "+f"((d)[2]), "+f"((d)[3]) \
        : "r"((a).x), "r"((a).y), "r"((a).z), "r"((a).w), \
          "r"((b).x), "r"((b).y))

// ---------------- weight packing: w [K,N] fp32 -> fragment-packed fp16 (B-layout) ----------------
__global__ void pack_weights_kernel(const float* __restrict__ w, uint32_t* __restrict__ wp,
                                    int N, int K) {
    int nch = K >> 5;
    long total = (long)N * (K >> 1);
    for (long tId = (long)blockIdx.x * blockDim.x + threadIdx.x; tId < total;
         tId += (long)gridDim.x * blockDim.x) {
        int n = (int)(tId % N);
        int kp = (int)(tId / N);
        int k = kp * 2;
        float v0 = w[(long)k * N + n];
        float v1 = w[(long)(k + 1) * N + n];
        long blk = (long)(n >> 7) * nch + (k >> 5);
        int nloc = n & 127, kloc = k & 31;
        int widx = ((((nloc >> 3) * 2 + ((kloc >> 4) & 1)) * 32
                     + (nloc & 7) * 4 + ((kloc >> 1) & 3)) * 2) + ((kloc >> 3) & 1);
        wp[blk * 2048 + widx] = pack_h2(v0, v1);
    }
}

// ---------------- activation packing (used only for x at layer 0) ----------------
__global__ void pack_act_kernel(const float* __restrict__ act, uint32_t* __restrict__ blob,
                                int K) {
    int kch = blockIdx.x, mblk = blockIdx.y;
    int nch = gridDim.x;
    const float* a0 = act + (long)mblk * 128 * K + kch * 32;
    uint32_t* out = blob + ((long)mblk * nch + kch) * 2048;
    int tid = threadIdx.x;
    #pragma unroll
    for (int i = 0; i < 8; i++) {
        int w = tid + 256 * i;
        int c = w & 3, lanep = (w >> 2) & 31, ikf = (w >> 7) & 1, im = w >> 8;
        int r = im * 16 + (c & 1) * 8 + (lanep >> 2);
        int k = ikf * 16 + ((c >> 1) & 1) * 8 + (lanep & 3) * 2;
        float2 v = *(const float2*)(a0 + (long)r * K + k);
        out[w] = pack_h2(v.x, v.y);
    }
}

// ---------------- sim = x x^T via fp16 hi/lo split (verified R9) ----------------
__global__ __launch_bounds__(256, 2)
void sim_gemm(const float* __restrict__ x, float* __restrict__ scores) {
    __shared__ uint32_t sAh[2048], sAl[2048], sBh[2048], sBl[2048];
    int b = blockIdx.z;
    int m0 = blockIdx.y * 128, n0 = blockIdx.x * 128;
    int tid = threadIdx.x, lane = tid & 31, wid = tid >> 5;
    int wm = wid & 1, wn = wid >> 1;
    const float* Xm = x + (long)b * SEQ * DIM + (long)m0 * DIM;
    const float* Xn = x + (long)b * SEQ * DIM + (long)n0 * DIM;

    int aR[4], aQ[4], aBase[4];
    #pragma unroll
    for (int i = 0; i < 4; i++) {
        int idx = tid + 256 * i;
        int r = idx >> 3, q = idx & 7;
        aR[i] = r; aQ[i] = q;
        int im = r >> 4, g = r & 7, row8 = (r >> 3) & 1;
        int ikf = q >> 2, k8 = (q >> 1) & 1;
        aBase[i] = ((im * 2 + ikf) * 32 + g * 4) * 4 + k8 * 2 + row8 + 8 * (q & 1);
    }
    int bR[4], bQ[4], bBase[4];
    #pragma unroll
    for (int i = 0; i < 4; i++) {
        int idx = tid + 256 * i;
        int r = idx >> 3, q = idx & 7;
        bR[i] = r; bQ[i] = q;
        int in = r >> 3, nn = r & 7;
        int ikf = q >> 2, k8 = (q >> 1) & 1;
        bBase[i] = ((in * 2 + ikf) * 32 + nn * 4) * 2 + k8 + 4 * (q & 1);
    }

    float acc[4][4][4];
    #pragma unroll
    for (int i = 0; i < 4; i++)
        #pragma unroll
        for (int j = 0; j < 4; j++)
            #pragma unroll
            for (int c = 0; c < 4; c++) acc[i][j][c] = 0.f;

    for (int it = 0; it < DIM / 32; it++) {
        long koff = (long)it * 32;
        float4 va[4], vb[4];
        #pragma unroll
        for (int i = 0; i < 4; i++)
            va[i] = *(const float4*)(Xm + (long)aR[i] * DIM + koff + aQ[i] * 4);
        #pragma unroll
        for (int i = 0; i < 4; i++)
            vb[i] = *(const float4*)(Xn + (long)bR[i] * DIM + koff + bQ[i] * 4);
        __syncthreads();
        #pragma unroll
        for (int i = 0; i < 4; i++) {
            uint32_t h0 = pack_h2(va[i].x, va[i].y);
            uint32_t h1 = pack_h2(va[i].z, va[i].w);
            uint32_t l0 = pack_h2(va[i].x - h2f_lo(h0), va[i].y - h2f_hi(h0));
            uint32_t l1 = pack_h2(va[i].z - h2f_lo(h1), va[i].w - h2f_hi(h1));
            sAh[aBase[i]] = h0; sAh[aBase[i] + 4] = h1;
            sAl[aBase[i]] = l0; sAl[aBase[i] + 4] = l1;
        }
        #pragma unroll
        for (int i = 0; i < 4; i++) {
            uint32_t h0 = pack_h2(vb[i].x, vb[i].y);
            uint32_t h1 = pack_h2(vb[i].z, vb[i].w);
            uint32_t l0 = pack_h2(vb[i].x - h2f_lo(h0), vb[i].y - h2f_hi(h0));
            uint32_t l1 = pack_h2(vb[i].z - h2f_lo(h1), vb[i].w - h2f_hi(h1));
            sBh[bBase[i]] = h0; sBh[bBase[i] + 2] = h1;
            sBl[bBase[i]] = l0; sBl[bBase[i] + 2] = l1;
        }
        __syncthreads();
        #pragma unroll
        for (int ikf = 0; ikf < 2; ikf++) {
            uint2 bh[4], bl[4];
            #pragma unroll
            for (int j2 = 0; j2 < 4; j2++) {
                int o = (((wn * 4 + j2) * 2 + ikf) * 32 + lane) * 2;
                bh[j2] = *(const uint2*)&sBh[o];
                bl[j2] = *(const uint2*)&sBl[o];
            }
            #pragma unroll
            for (int i2 = 0; i2 < 4; i2++) {
                int o = (((wm * 4 + i2) * 2 + ikf) * 32 + lane) * 4;
                uint4 ah = *(const uint4*)&sAh[o];
                uint4 al = *(const uint4*)&sAl[o];
                #pragma unroll
                for (int j2 = 0; j2 < 4; j2++) {
                    MMAF16(acc[i2][j2], ah, bh[j2]);
                    MMAF16(acc[i2][j2], ah, bl[j2]);
                    MMAF16(acc[i2][j2], al, bh[j2]);
                }
            }
        }
    }

    int g = lane >> 2, t = lane & 3;
    float* C = scores + (long)b * SEQ * SEQ;
    #pragma unroll
    for (int i2 = 0; i2 < 4; i2++) {
        int gm = m0 + (wm * 4 + i2) * 16 + g;
        #pragma unroll
        for (int j2 = 0; j2 < 4; j2++) {
            int gn = n0 + (wn * 4 + j2) * 8 + t * 2;
            *(float2*)&C[(long)gm * SEQ + gn] = make_float2(acc[i2][j2][0], acc[i2][j2][1]);
            *(float2*)&C[(long)(gm + 8) * SEQ + gn] = make_float2(acc[i2][j2][2], acc[i2][j2][3]);
        }
    }
}

// ---------------- flash attention: output written directly as packed A-blob ----------------
__global__ __launch_bounds__(256, 1)
void flash_kernel(const float* __restrict__ qkv, const float* __restrict__ vt,
                  uint32_t* __restrict__ oblob, float scale) {
    __shared__ uint32_t sK[6144];
    __shared__ uint32_t sV[6144];
    int z = blockIdx.z, b = z >> 3, h = z & 7;
    int m0 = blockIdx.y * 128;
    int tid = threadIdx.x, lane = tid & 31, wid = tid >> 5;
    int t = lane & 3, g = lane >> 2;

    const float* Qg = qkv + ((long)b * 1024 + m0) * 2304 + h * 96;
    const float* Kg = qkv + (long)b * 1024 * 2304 + 768 + h * 96;
    const float* Vg = vt + (long)z * 96 * 1024;

    #pragma unroll
    for (int i = 0; i < 12; i++) {
        int idx = tid + 256 * i;
        int r = idx / 24, q = idx % 24;
        int k0 = q * 4;
        int im = r >> 4, gg = r & 7, row8 = (r >> 3) & 1;
        int kg = k0 >> 4, k8 = (k0 >> 3) & 1, t0 = (k0 >> 1) & 3;
        int base = ((im * 6 + kg) * 32 + gg * 4 + t0) * 4 + row8 + 2 * k8;
        float4 v = *(const float4*)(Qg + (long)r * 2304 + k0);
        sK[base]     = pack_h2(v.x, v.y);
        sK[base + 4] = pack_h2(v.z, v.w);
    }
    __syncthreads();
    uint4 qf[6];
    #pragma unroll
    for (int kg = 0; kg < 6; kg++)
        qf[kg] = *(const uint4*)&sK[((wid * 6 + kg) * 32 + lane) * 4];
    __syncthreads();

    float mr0 = -1e30f, mr1 = -1e30f, l0 = 0.f, l1 = 0.f;
    float accO[12][4];
    #pragma unroll
    for (int j = 0; j < 12; j++)
        #pragma unroll
        for (int c = 0; c < 4; c++) accO[j][c] = 0.f;

    for (int kt = 0; kt < 8; kt++) {
        #pragma unroll
        for (int i = 0; i < 12; i++) {
            int idx = tid + 256 * i;
            int r = idx / 24, q = idx % 24;
            int k0 = q * 4;
            int jn = r >> 3, nn = r & 7;
            int kg = k0 >> 4, k8 = (k0 >> 3) & 1, t0 = (k0 >> 1) & 3;
            int base = ((jn * 6 + kg) * 32 + nn * 4 + t0) * 2 + k8;
            float4 v = *(const float4*)(Kg + (long)(kt * 128 + r) * 2304 + k0);
            sK[base]     = pack_h2(v.x, v.y);
            sK[base + 2] = pack_h2(v.z, v.w);
        }
        #pragma unroll
        for (int i = 0; i < 12; i++) {
            int idx = tid + 256 * i;
            int r = idx >> 5, q = idx & 31;
            int k0 = q * 4;
            int jn = r >> 3, nn = r & 7;
            int kg = k0 >> 4, k8 = (k0 >> 3) & 1, t0 = (k0 >> 1) & 3;
            int base = ((jn * 8 + kg) * 32 + nn * 4 + t0) * 2 + k8;
            float4 v = *(const float4*)(Vg + (long)r * 1024 + kt * 128 + k0);
            sV[base]     = pack_h2(v.x, v.y);
            sV[base + 2] = pack_h2(v.z, v.w);
        }
        __syncthreads();

        float accS[16][4];
        #pragma unroll
        for (int j = 0; j < 16; j++)
            #pragma unroll
            for (int c = 0; c < 4; c++) accS[j][c] = 0.f;
        #pragma unroll
        for (int kg = 0; kg < 6; kg++)
            #pragma unroll
            for (int jn = 0; jn < 16; jn++) {
                uint2 bf = *(const uint2*)&sK[((jn * 6 + kg) * 32 + lane) * 2];
                MMAF16(accS[jn], qf[kg], bf);
            }

        float mx0 = -1e30f, mx1 = -1e30f;
        #pragma unroll
        for (int jn = 0; jn < 16; jn++) {
            accS[jn][0] *= scale; accS[jn][1] *= scale;
            accS[jn][2] *= scale; accS[jn][3] *= scale;
            mx0 = fmaxf(mx0, fmaxf(accS[jn][0], accS[jn][1]));
            mx1 = fmaxf(mx1, fmaxf(accS[jn][2], accS[jn][3]));
        }
        mx0 = fmaxf(mx0, __shfl_xor_sync(0xffffffffu, mx0, 1));
        mx0 = fmaxf(mx0, __shfl_xor_sync(0xffffffffu, mx0, 2));
        mx1 = fmaxf(mx1, __shfl_xor_sync(0xffffffffu, mx1, 1));
        mx1 = fmaxf(mx1, __shfl_xor_sync(0xffffffffu, mx1, 2));

        float mn0 = fmaxf(mr0, mx0), mn1 = fmaxf(mr1, mx1);
        float cr0 = fexp(mr0 - mn0), cr1 = fexp(mr1 - mn1);

        float s0 = 0.f, s1 = 0.f;
        uint32_t plo[16], phi[16];
        #pragma unroll
        for (int jn = 0; jn < 16; jn++) {
            float e0 = fexp(accS[jn][0] - mn0);
            float e1 = fexp(accS[jn][1] - mn0);
            float e2 = fexp(accS[jn][2] - mn1);
            float e3 = fexp(accS[jn][3] - mn1);
            s0 += e0 + e1; s1 += e2 + e3;
            plo[jn] = pack_h2(e0, e1);
            phi[jn] = pack_h2(e2, e3);
        }
        s0 += __shfl_xor_sync(0xffffffffu, s0, 1);
        s0 += __shfl_xor_sync(0xffffffffu, s0, 2);
        s1 += __shfl_xor_sync(0xffffffffu, s1, 1);
        s1 += __shfl_xor_sync(0xffffffffu, s1, 2);

        l0 = l0 * cr0 + s0;
        l1 = l1 * cr1 + s1;
        mr0 = mn0; mr1 = mn1;
        #pragma unroll
        for (int j = 0; j < 12; j++) {
            accO[j][0] *= cr0; accO[j][1] *= cr0;
            accO[j][2] *= cr1; accO[j][3] *= cr1;
        }

        #pragma unroll
        for (int kg = 0; kg < 8; kg++) {
            uint4 af = make_uint4(plo[2 * kg], phi[2 * kg], plo[2 * kg + 1], phi[2 * kg + 1]);
            #pragma unroll
            for (int jn = 0; jn < 12; jn++) {
                uint2 bf = *(const uint2*)&sV[((jn * 8 + kg) * 32 + lane) * 2];
                MMAF16(accO[jn], af, bf);
            }
        }
        __syncthreads();
    }

    float inv0 = 1.f / l0, inv1 = 1.f / l1;
    long row0 = (long)(b * 1024 + m0 + wid * 16 + g);
    long mblk = row0 >> 7;
    #pragma unroll
    for (int jn = 0; jn < 12; jn++) {
        int kglob = h * 96 + jn * 8 + t * 2;
        int kch = kglob >> 5;
        int ikf = (jn >> 1) & 1, k8 = jn & 1;
        long word = ((mblk * 24 + kch) * 2048) + wid * 256 + ikf * 128 + lane * 4 + 2 * k8;
        uint2 pw;
        pw.x = pack_h2(accO[jn][0] * inv0, accO[jn][1] * inv0);
        pw.y = pack_h2(accO[jn][2] * inv1, accO[jn][3] * inv1);
        *(uint2*)&oblob[word] = pw;
    }
}

// ---------------- mma.sync fp16 GEMM + optional packed-A-blob emitter ----------------
__global__ __launch_bounds__(256, 2)
void mma_gemm(const uint32_t* __restrict__ Ap,
              const uint32_t* __restrict__ Wp,
              float* __restrict__ C0, long ldc0, const float* __restrict__ bias0, int nsplit,
              float* __restrict__ C1, long ldc1, const float* __restrict__ bias1,
              int nch,
              uint32_t* __restrict__ packBlob, int packNch, int packKchBase) {
    __shared__ uint32_t sA[2][2048];
    __shared__ uint32_t sB[2][2048];

    int tid = threadIdx.x, lane = tid & 31, wid = tid >> 5;
    int wm = wid & 1, wn = wid >> 1;

    const uint4* Ab = (const uint4*)(Ap + (long)blockIdx.y * nch * 2048);
    const uint4* Wb = (const uint4*)(Wp + (long)blockIdx.x * nch * 2048);

    float acc[4][4][4];
    #pragma unroll
    for (int i = 0; i < 4; i++)
        #pragma unroll
        for (int j = 0; j < 4; j++)
            #pragma unroll
            for (int c = 0; c < 4; c++) acc[i][j][c] = 0.f;

    uint4 va0 = Ab[tid], va1 = Ab[tid + 256];
    uint4 vb0 = Wb[tid], vb1 = Wb[tid + 256];
    ((uint4*)sA[0])[tid] = va0; ((uint4*)sA[0])[tid + 256] = va1;
    ((uint4*)sB[0])[tid] = vb0; ((uint4*)sB[0])[tid + 256] = vb1;
    __syncthreads();

    for (int it = 0; it < nch; it++) {
        int buf = it & 1;
        bool more = (it + 1 < nch);
        if (more) {
            const uint4* An = Ab + (long)(it + 1) * 512;
            const uint4* Wn = Wb + (long)(it + 1) * 512;
            va0 = An[tid]; va1 = An[tid + 256];
            vb0 = Wn[tid]; vb1 = Wn[tid + 256];
        }
        #pragma unroll
        for (int ikf = 0; ikf < 2; ikf++) {
            uint4 af[4];
            uint2 bf[4];
            #pragma unroll
            for (int i2 = 0; i2 < 4; i2++)
                af[i2] = *(const uint4*)&sA[buf][(((wm * 4 + i2) * 2 + ikf) * 32 + lane) * 4];
            #pragma unroll
            for (int j2 = 0; j2 < 4; j2++)
                bf[j2] = *(const uint2*)&sB[buf][(((wn * 4 + j2) * 2 + ikf) * 32 + lane) * 2];
            #pragma unroll
            for (int i2 = 0; i2 < 4; i2++)
                #pragma unroll
                for (int j2 = 0; j2 < 4; j2++)
                    MMAF16(acc[i2][j2], af[i2], bf[j2]);
        }
        __syncthreads();
        if (more) {
            int nb = buf ^ 1;
            ((uint4*)sA[nb])[tid] = va0; ((uint4*)sA[nb])[tid + 256] = va1;
            ((uint4*)sB[nb])[tid] = vb0; ((uint4*)sB[nb])[tid + 256] = vb1;
            __syncthreads();
        }
    }

    float* C; long ldc; const float* bias; int n0;
    if ((int)blockIdx.x < nsplit) {
        C = C0; ldc = ldc0; bias = bias0; n0 = blockIdx.x * 128;
    } else {
        C = C1; ldc = ldc1; bias = bias1; n0 = (blockIdx.x - nsplit) * 128;
    }
    int m0 = blockIdx.y * 128;
    int g = lane >> 2, t = lane & 3;
    #pragma unroll
    for (int i2 = 0; i2 < 4; i2++) {
        int im = wm * 4 + i2;
        int gm = m0 + im * 16 + g;
        #pragma unroll
        for (int j2 = 0; j2 < 4; j2++) {
            int gn = n0 + (wn * 4 + j2) * 8 + t * 2;
            float b0 = __ldg(bias + gn);
            float b1 = __ldg(bias + gn + 1);
            float2 v0, v1;
            v0.x = acc[i2][j2][0] + b0;
            v0.y = acc[i2][j2][1] + b1;
            v1.x = acc[i2][j2][2] + b0;
            v1.y = acc[i2][j2][3] + b1;
            *(float2*)&C[(long)gm * ldc + gn] = v0;
            *(float2*)&C[(long)(gm + 8) * ldc + gn] = v1;
            if (packBlob) {
                int kch = packKchBase + (n0 >> 5) + wn;
                long word = (((long)blockIdx.y * packNch + kch) * 2048)
                          + im * 256 + (j2 >> 1) * 128 + lane * 4 + 2 * (j2 & 1);
                uint2 pw;
                pw.x = pack_h2(v0.x, v0.y);
                pw.y = pack_h2(v1.x, v1.y);
                *(uint2*)&packBlob[word] = pw;
            }
        }
    }
}

// ---------------- V transpose for flash ----------------
__global__ void transpose_v_kernel(const float* __restrict__ qkv, float* __restrict__ vt) {
    int z = blockIdx.z; int b = z >> 3, h = z & 7;
    __shared__ float tb[32][33];
    int d0 = blockIdx.x * 32, t0 = blockIdx.y * 32;
    int tx = threadIdx.x, ty = threadIdx.y;
    const float* src = qkv + (long)b * 1024 * 2304 + 1536 + h * 96;
    for (int i = ty; i < 32; i += 8)
        tb[i][tx] = src[(long)(t0 + i) * 2304 + d0 + tx];
    __syncthreads();
    float* dst = vt + ((long)z * 96 + d0) * 1024 + t0;
    for (int j = ty; j < 32; j += 8)
        dst[(long)j * 1024 + tx] = tb[tx][j];
}

// ---------------- misc ----------------
__global__ void zero_bytes_kernel(unsigned char* p, long n) {
    long i = (long)blockIdx.x * blockDim.x + threadIdx.x;
    long stride = (long)gridDim.x * blockDim.x;
    int* pi = (int*)p;
    long nw = n >> 2;
    for (; i < nw; i += stride) pi[i] = 0;
}

// ---------------- topk: warp-per-row single pass, jax tie-break (lower index) ----------------
__global__ void topk_warp_kernel(const float* __restrict__ sim, int* __restrict__ idx_out) {
    long rowid = ((long)blockIdx.x * blockDim.x + threadIdx.x) >> 5;
    int lane = threadIdx.x & 31;
    if (rowid >= ROWS) return;
    const float* row = sim + rowid * SEQ;
    float v[5]; int id[5];
    #pragma unroll
    for (int i = 0; i < 5; i++) { v[i] = -INFINITY; id[i] = 0x7fffffff; }
    for (int t = lane; t < SEQ; t += 32) {
        float x = row[t];
        if (x > v[4] || (x == v[4] && t < id[4])) {
            v[4] = x; id[4] = t;
            #pragma unroll
            for (int j = 3; j >= 0; j--) {
                if (v[j + 1] > v[j] || (v[j + 1] == v[j] && id[j + 1] < id[j])) {
                    float tv = v[j]; v[j] = v[j + 1]; v[j + 1] = tv;
                    int ti = id[j]; id[j] = id[j + 1]; id[j + 1] = ti;
                }
            }
        }
    }
    #pragma unroll
    for (int sel = 0; sel < KNEIGH; sel++) {
        float bv = v[0]; int bi = id[0];
        #pragma unroll
        for (int o = 16; o > 0; o >>= 1) {
            float ov = __shfl_xor_sync(0xffffffffu, bv, o);
            int oi = __shfl_xor_sync(0xffffffffu, bi, o);
            if (ov > bv || (ov == bv && oi < bi)) { bv = ov; bi = oi; }
        }
        if (lane == 0) idx_out[rowid * KNEIGH + sel] = bi;
        if (bi == id[0]) {
            #pragma unroll
            for (int j = 0; j < 4; j++) { v[j] = v[j + 1]; id[j] = id[j + 1]; }
            v[4] = -INFINITY; id[4] = 0x7fffffff;
        }
    }
}

// ---------------- adjacency + degree ----------------
__global__ void scatter_adj_kernel(const int* __restrict__ idx, unsigned char* __restrict__ A) {
    int r = blockIdx.x * blockDim.x + threadIdx.x;
    if (r >= ROWS) return;
    int b = r >> 10, s = r & 1023;
    unsigned char* Ab = A + (long long)b * SEQ * SEQ;
    Ab[(long)s * SEQ + s] = 1;
    #pragma unroll
    for (int j = 0; j < KNEIGH; j++) {
        int t = idx[(long)r * KNEIGH + j];
        Ab[(long)s * SEQ + t] = 1;
        Ab[(long)t * SEQ + s] = 1;
    }
}
__global__ void degree_kernel(const unsigned char* __restrict__ A, float* __restrict__ dinv) {
    int r = blockIdx.x * blockDim.x + threadIdx.x;
    if (r >= ROWS) return;
    const uint32_t* row = (const uint32_t*)(A + (long long)r * SEQ);
    int d = 0;
    for (int i = 0; i < SEQ / 4; i++) {
        uint32_t w = row[i];
        d += (w & 0xff) + ((w >> 8) & 0xff) + ((w >> 16) & 0xff) + ((w >> 24) & 0xff);
    }
    dinv[r] = rsqrtf((float)d);
}

// ---------------- sparse GCN aggregate: cat fp32 + cat-blob (kch 0..23) ----------------
__global__ void gcn_agg_kernel(const unsigned char* __restrict__ A, const float* __restrict__ dinv,
                               const float* __restrict__ xw, const float* __restrict__ gcn_b,
                               float* __restrict__ cat, uint32_t* __restrict__ catblob) {
    int r = blockIdx.x;
    int b = r >> 10;
    const unsigned char* Arow = A + (long long)r * SEQ;
    __shared__ int   nbr[SEQ];
    __shared__ float wgt[SEQ];
    __shared__ float sbuf[DIM];
    __shared__ int cnt;
    int tid = threadIdx.x;
    if (tid == 0) cnt = 0;
    __syncthreads();
    for (int t = tid; t < SEQ; t += 256) {
        if (Arow[t]) {
            int p = atomicAdd(&cnt, 1);
            nbr[p] = t;
            wgt[p] = dinv[(b << 10) + t];
        }
    }
    __syncthreads();
    int n = cnt;
    float acc0 = 0.f, acc1 = 0.f, acc2 = 0.f;
    for (int i = 0; i < n; i++) {
        const float* row = xw + ((long)(b << 10) + nbr[i]) * DIM;
        float w = wgt[i];
        acc0 += w * row[tid];
        acc1 += w * row[tid + 256];
        acc2 += w * row[tid + 512];
    }
    float ws = dinv[r];
    long base = (long)r * (2 * DIM);
    float o0 = ws * acc0 + gcn_b[tid];
    float o1 = ws * acc1 + gcn_b[tid + 256];
    float o2 = ws * acc2 + gcn_b[tid + 512];
    cat[base + tid]       = o0;
    cat[base + tid + 256] = o1;
    cat[base + tid + 512] = o2;
    sbuf[tid] = o0; sbuf[tid + 256] = o1; sbuf[tid + 512] = o2;
    __syncthreads();
    long mblk = r >> 7;
    int rloc = r & 127;
    int im = rloc >> 4, row8 = (rloc >> 3) & 1, g = rloc & 7;
    for (int w = tid; w < 384; w += 256) {
        int kch = w >> 4, ikf = (w >> 3) & 1, k8 = (w >> 2) & 1, t = w & 3;
        long word = ((mblk * 48 + kch) * 2048) + im * 256 + ikf * 128
                  + (g * 4 + t) * 4 + 2 * k8 + row8;
        catblob[word] = pack_h2(sbuf[2 * w], sbuf[2 * w + 1]);
    }
}

// ---------------- gate + residual + layernorm: h fp32 + h-blob ----------------
__global__ void fuse_ln_kernel(const float* __restrict__ gatelin, const float* __restrict__ cat,
                               const float* __restrict__ hin, float* __restrict__ hout,
                               uint32_t* __restrict__ hblob,
                               const float* __restrict__ ln_scale, const float* __restrict__ ln_bias) {
    long r = blockIdx.x;
    int tid = threadIdx.x;
    __shared__ float red[256];
    __shared__ float sbuf[DIM];
    float f[3];
    #pragma unroll
    for (int i = 0; i < 3; i++) {
        int j = tid + 256 * i;
        float g  = gatelin[r * DIM + j];
        float gc = cat[r * (2 * DIM) + j];
        float at = cat[r * (2 * DIM) + DIM + j];
        float sg = 1.f / (1.f + fexp(-g));
        f[i] = sg * gc + (1.f - sg) * at + hin[r * DIM + j];
    }
    float s1 = f[0] + f[1] + f[2];
    red[tid] = s1; __syncthreads();
    #pragma unroll
    for (int o = 128; o > 0; o >>= 1) { if (tid < o) red[tid] += red[tid + o]; __syncthreads(); }
    float mu = red[0] * (1.f / DIM);
    __syncthreads();
    float s2 = 0.f;
    #pragma unroll
    for (int i = 0; i < 3; i++) { float d = f[i] - mu; s2 += d * d; }
    red[tid] = s2; __syncthreads();
    #pragma unroll
    for (int o = 128; o > 0; o >>= 1) { if (tid < o) red[tid] += red[tid + o]; __syncthreads(); }
    float var = red[0] * (1.f / DIM);
    float inv = rsqrtf(var + LN_EPS);
    #pragma unroll
    for (int i = 0; i < 3; i++) {
        int j = tid + 256 * i;
        float v = (f[i] - mu) * inv * ln_scale[j] + ln_bias[j];
        hout[r * DIM + j] = v;
        sbuf[j] = v;
    }
    __syncthreads();
    long mblk = r >> 7;
    int rloc = (int)(r & 127);
    int im = rloc >> 4, row8 = (rloc >> 3) & 1, g = rloc & 7;
    for (int w = tid; w < 384; w += 256) {
        int kch = w >> 4, ikf = (w >> 3) & 1, k8 = (w >> 2) & 1, t = w & 3;
        long word = ((mblk * 24 + kch) * 2048) + im * 256 + ikf * 128
                  + (g * 4 + t) * 4 + 2 * k8 + row8;
        hblob[word] = pack_h2(sbuf[2 * w], sbuf[2 * w + 1]);
    }
}

// ---------------- host helper ----------------
static void launch_mma(const uint32_t* Ap, const uint32_t* Wp, float* C, long ldc,
                       const float* bias, int M, int N, int K,
                       uint32_t* packBlob = nullptr, int packNch = 0, int packKchBase = 0) {
    dim3 grid(N / 128, M / 128, 1);
    mma_gemm<<<grid, 256>>>(Ap, Wp, C, ldc, bias, N / 128, C, ldc, bias, K / 32,
                            packBlob, packNch, packKchBase);
}

extern "C" void kernel_launch(void* const* d_in, const int* in_sizes, int n_in,
                              void* d_out, int out_size) {
    const float* x          = (const float*)d_in[0];
    const float* gcn_w      = (const float*)d_in[1];
    const float* gcn_b      = (const float*)d_in[2];
    const float* attn_in_w  = (const float*)d_in[3];
    const float* attn_in_b  = (const float*)d_in[4];
    const float* attn_out_w = (const float*)d_in[5];
    const float* attn_out_b = (const float*)d_in[6];
    const float* gate_w     = (const float*)d_in[7];
    const float* gate_b     = (const float*)d_in[8];
    const float* ln_scale   = (const float*)d_in[9];
    const float* ln_bias    = (const float*)d_in[10];
    const float* proj_w     = (const float*)d_in[11];
    const float* proj_b     = (const float*)d_in[12];
    float* out = (float*)d_out;

    static cudaStream_t s_side = nullptr;
    static cudaEvent_t ev_fork = nullptr;
    static cudaEvent_t ev_xw[NLAYERS], ev_agg[NLAYERS];
    if (!s_side) {
        cudaStreamCreateWithFlags(&s_side, cudaStreamNonBlocking);
        cudaEventCreateWithFlags(&ev_fork, cudaEventDisableTiming);
        for (int l = 0; l < NLAYERS; l++) {
            cudaEventCreateWithFlags(&ev_xw[l], cudaEventDisableTiming);
            cudaEventCreateWithFlags(&ev_agg[l], cudaEventDisableTiming);
        }
    }

    float *p_h, *p_xw, *p_qkv, *p_scores, *p_cat, *p_gate, *p_dinv, *p_vt;
    uint32_t *p_wp, *p_ap;
    unsigned char* p_adj;
    int* p_topk;
    cudaGetSymbolAddress((void**)&p_h, g_h);
    cudaGetSymbolAddress((void**)&p_xw, g_xw);
    cudaGetSymbolAddress((void**)&p_qkv, g_qkv);
    cudaGetSymbolAddress((void**)&p_scores, g_scores);
    cudaGetSymbolAddress((void**)&p_cat, g_cat);
    cudaGetSymbolAddress((void**)&p_gate, g_gate);
    cudaGetSymbolAddress((void**)&p_dinv, g_dinv);
    cudaGetSymbolAddress((void**)&p_adj, g_adj);
    cudaGetSymbolAddress((void**)&p_topk, g_topk);
    cudaGetSymbolAddress((void**)&p_wp, g_wp);
    cudaGetSymbolAddress((void**)&p_ap, g_ap);
    cudaGetSymbolAddress((void**)&p_vt, g_vt);

    const float attn_scale = (float)(1.0 / sqrt((double)HDIM));
    dim3 tb(32, 8);

    // ---- fork: graph-construction chain on side stream ----
    cudaEventRecord(ev_fork, 0);
    cudaStreamWaitEvent(s_side, ev_fork, 0);
    sim_gemm<<<dim3(8, 8, BATCH), 256, 0, s_side>>>(x, p_scores);
    topk_warp_kernel<<<ROWS / 8, 256, 0, s_side>>>(p_scores, p_topk);
    zero_bytes_kernel<<<1024, 256, 0, s_side>>>(p_adj, (long long)BATCH * SEQ * SEQ);
    scatter_adj_kernel<<<(ROWS + 255) / 256, 256, 0, s_side>>>(p_topk, p_adj);
    degree_kernel<<<(ROWS + 255) / 256, 256, 0, s_side>>>(p_adj, p_dinv);

    // ---- main stream: weight packs + x blob ----
    for (int l = 0; l < NLAYERS; l++) {
        pack_weights_kernel<<<512, 256>>>(gcn_w + (long)l * DIM * DIM, p_wp + WP_FUSED(l), DIM, DIM);
        pack_weights_kernel<<<512, 256>>>(attn_in_w + (long)l * DIM * 3 * DIM,
                                          p_wp + WP_FUSED(l) + 294912, 3 * DIM, DIM);
        pack_weights_kernel<<<512, 256>>>(attn_out_w + (long)l * DIM * DIM, p_wp + WP_AOW(l), DIM, DIM);
        pack_weights_kernel<<<512, 256>>>(gate_w + (long)l * 2 * DIM * DIM, p_wp + WP_GW(l), DIM, 2 * DIM);
    }
    pack_weights_kernel<<<512, 256>>>(proj_w, p_wp + WP_PROJ, DIM, DIM);
    pack_act_kernel<<<dim3(24, 64), 256>>>(x, p_ap + AP_H, DIM);   // layer-0 A blob

    for (int l = 0; l < NLAYERS; l++) {
        const float* gb  = gcn_b + (long)l * DIM;
        const float* aib = attn_in_b + (long)l * 3 * DIM;
        const float* aob = attn_out_b + (long)l * DIM;
        const float* gtb = gate_b + (long)l * DIM;
        const float* lns = ln_scale + (long)l * DIM;
        const float* lnb = ln_bias + (long)l * DIM;
        const float* hin = (l == 0) ? x : p_h;

        // fused: XW -> xw (n-blocks 0-5), QKV -> qkv (n-blocks 6-23); A = h blob
        {
            dim3 grid(24, ROWS / 128, 1);
            mma_gemm<<<grid, 256>>>(p_ap + AP_H, p_wp + WP_FUSED(l),
                                    p_xw, DIM, gb, 6,
                                    p_qkv, 3 * DIM, aib,
                                    24, nullptr, 0, 0);
        }
        cudaEventRecord(ev_xw[l], 0);

        // side stream: gcn_agg overlapped with attention path
        // (graph chain already queued on s_side before layer 0)
        cudaStreamWaitEvent(s_side, ev_xw[l], 0);
        gcn_agg_kernel<<<ROWS, 256, 0, s_side>>>(p_adj, p_dinv, p_xw, gb, p_cat, p_ap + AP_CAT);
        cudaEventRecord(ev_agg[l], s_side);

        // main stream: attention path
        transpose_v_kernel<<<dim3(3, 32, 64), tb>>>(p_qkv, p_vt);
        flash_kernel<<<dim3(1, 8, 64), 256>>>(p_qkv, p_vt, p_ap + AP_O, attn_scale);
        // attn_out GEMM: cat fp32 [:,768:1536] + cat blob kch 24-47
        launch_mma(p_ap + AP_O, p_wp + WP_AOW(l), p_cat + DIM, 2 * DIM, aob,
                   ROWS, DIM, DIM, p_ap + AP_CAT, 48, 24);

        // join: gate GEMM needs both cat halves
        cudaStreamWaitEvent(0, ev_agg[l], 0);
        launch_mma(p_ap + AP_CAT, p_wp + WP_GW(l), p_gate, DIM, gtb, ROWS, DIM, 2 * DIM);
        // h = LN(gate*gcn + (1-gate)*attn + hin) -> h fp32 + h blob
        fuse_ln_kernel<<<ROWS, 256>>>(p_gate, p_cat, hin, p_h, p_ap + AP_H, lns, lnb);
    }

    // out = h @ proj_w + proj_b  (A = h blob from last fuse_ln)
    launch_mma(p_ap + AP_H, p_wp + WP_PROJ, out, DIM, proj_b, ROWS, DIM, DIM);
}